// round 7
// baseline (speedup 1.0000x reference)
#include <cuda_runtime.h>

#define EPSV 1e-5f

// scratch (no cudaMalloc allowed)
__device__ float g_x1p[16 * 16 * 256 * 256];   // stage1 output, pooled  [N,16,256,256]
__device__ float g_mask2[16 * 256 * 256];      // pooled mask            [N,256,256]
__device__ float g_x2p[16 * 8 * 128 * 128];    // stage2 output, pooled  [N,8,128,128]
__device__ float g_fcpart[16 * 32 * 10];       // FC partial sums
__device__ int   g_cnt1;                       // active tile count (stage1)
__device__ int   g_list1[16384];               // active tile list  (stage1)

// prepped weights / BN (global; read warp-uniform via L1)
__device__ __align__(16) float g_w2p[9216];    // stage1 d2 paired [c1*9+t][pair16][2]
__device__ __align__(16) float g_q2p[2304];    // stage2 d2 paired [c1*9+t][pair8][2]
__device__ float g_sc[144], g_sh[144];
// offsets: s1bn0=0(16) s1bn1=16(32) s1bn2=48(32) s1bn3=80(16)
//          s2bn0=96(8) s2bn1=104(16) s2bn2=120(16) s2bn3=136(8)

typedef unsigned long long ull;

__device__ __forceinline__ void fma2(ull& d, ull a, ull b) {
    asm("fma.rn.f32x2 %0, %1, %2, %0;" : "+l"(d) : "l"(a), "l"(b));
}
__device__ __forceinline__ ull pack2(float lo, float hi) {
    ull r; asm("mov.b64 %0, {%1, %2};" : "=l"(r) : "f"(lo), "f"(hi)); return r;
}
__device__ __forceinline__ ull dup2(float v) { return pack2(v, v); }
__device__ __forceinline__ float2 unpack2(ull u) {
    float2 f; asm("mov.b64 {%0, %1}, %2;" : "=f"(f.x), "=f"(f.y) : "l"(u)); return f;
}

// padded row stride (floats) for activation tiles
#define RS 20
#define CS 320   // 16 rows * RS

// ---------------------------------------------------------------------------
// prep: reorder d2 weights, BN affine precompute, reset compaction counter
// ---------------------------------------------------------------------------
__global__ void prep_kernel(
    const float* __restrict__ s1d2w, const float* __restrict__ s2d2w,
    const float* __restrict__ b10, const float* __restrict__ b11,
    const float* __restrict__ b12, const float* __restrict__ b13,
    const float* __restrict__ b20, const float* __restrict__ b21,
    const float* __restrict__ b22, const float* __restrict__ b23)
{
    const int tid = threadIdx.x;
    if (tid == 0) g_cnt1 = 0;
    for (int i = tid; i < 9216; i += 256) {
        int c2 = i / 288, rem = i - c2 * 288;
        int c1 = rem / 9, t = rem - c1 * 9;
        g_w2p[((c1 * 9 + t) * 16 + (c2 >> 1)) * 2 + (c2 & 1)] = s1d2w[i];
    }
    for (int i = tid; i < 2304; i += 256) {
        int c2 = i / 144, rem = i - c2 * 144;
        int c1 = rem / 9, t = rem - c1 * 9;
        g_q2p[((c1 * 9 + t) * 8 + (c2 >> 1)) * 2 + (c2 & 1)] = s2d2w[i];
    }
    if (tid < 144) {
        const float* bp; int c, C;
        if      (tid < 16)  { bp = b10; c = tid;       C = 16; }
        else if (tid < 48)  { bp = b11; c = tid - 16;  C = 32; }
        else if (tid < 80)  { bp = b12; c = tid - 48;  C = 32; }
        else if (tid < 96)  { bp = b13; c = tid - 80;  C = 16; }
        else if (tid < 104) { bp = b20; c = tid - 96;  C = 8;  }
        else if (tid < 120) { bp = b21; c = tid - 104; C = 16; }
        else if (tid < 136) { bp = b22; c = tid - 120; C = 16; }
        else                { bp = b23; c = tid - 136; C = 8;  }
        float g = bp[c], b = bp[C + c], m = bp[2 * C + c], v = bp[3 * C + c];
        float s = g * rsqrtf(v + EPSV);
        g_sc[tid] = s; g_sh[tid] = b - s * m;
    }
}

// ---------------------------------------------------------------------------
// Stage 1a (all tiles): mask pool, activity vote -> compact list,
// channel conv + pool for INACTIVE tiles only.
// ---------------------------------------------------------------------------
__global__ void __launch_bounds__(256) stage1_all_kernel(
    const float* __restrict__ x, const float* __restrict__ mask,
    const float* __restrict__ cw, const float* __restrict__ cb)
{
    __shared__ float s_red[256];
    __shared__ float s_wsum[8];
    __shared__ float s_xc[16 * CS];
    __shared__ int s_active;

    const int bid = blockIdx.x;
    const int n   = bid >> 10;
    const int by  = (bid >> 5) & 31;
    const int bx  = bid & 31;
    const int tid = threadIdx.x;
    const int py  = tid >> 4, px_ = tid & 15;
    const int gy  = by * 16 + py, gx = bx * 16 + px_;

    float mval = mask[(n * 512 + gy) * 512 + gx];
    s_red[tid] = mval;
    float msum = mval;
#pragma unroll
    for (int o = 16; o; o >>= 1) msum += __shfl_xor_sync(0xffffffffu, msum, o);
    if ((tid & 31) == 0) s_wsum[tid >> 5] = msum;
    __syncthreads();

    if (tid < 64) {
        int qy = tid >> 3, qx = tid & 7;
        int p0 = (qy * 2) * 16 + qx * 2;
        float m0 = fmaxf(fmaxf(s_red[p0], s_red[p0 + 1]),
                         fmaxf(s_red[p0 + 16], s_red[p0 + 17]));
        g_mask2[(n * 256 + by * 8 + qy) * 256 + (bx * 8 + qx)] = m0;
    }
    if (tid == 0) {
        float t = 0.f;
#pragma unroll
        for (int i = 0; i < 8; i++) t += s_wsum[i];
        int act = (t > 128.0f) ? 1 : 0;
        s_active = act;
        if (act) {
            int pos = atomicAdd(&g_cnt1, 1);
            g_list1[pos] = bid;
        }
    }
    __syncthreads();
    if (s_active) return;   // active tiles handled by stage1_active_kernel

    // inactive: channel conv -> pool
    {
        const int ibase = ((n * 3) * 512 + gy) * 512 + gx;
        float xv0 = x[ibase];
        float xv1 = x[ibase + 512 * 512];
        float xv2 = x[ibase + 2 * 512 * 512];
        const int po = py * RS + px_;
#pragma unroll
        for (int c = 0; c < 16; c++) {
            float t = __ldg(&cw[c * 3 + 0]) * xv0 + __ldg(&cw[c * 3 + 1]) * xv1 +
                      __ldg(&cw[c * 3 + 2]) * xv2 + __ldg(&cb[c]);
            t = fmaxf(t, 0.0f);
            s_xc[c * CS + po] = fmaf(__ldg(&g_sc[c]), t, __ldg(&g_sh[c]));
        }
    }
    __syncthreads();

#pragma unroll
    for (int k = 0; k < 4; k++) {
        int o = tid + k * 256;
        int c = o >> 6;
        int q = o & 63;
        int qy = q >> 3, qx = q & 7;
        const float* sp = &s_xc[c * CS + (qy * 2) * RS + qx * 2];
        float mo = fmaxf(fmaxf(sp[0], sp[1]), fmaxf(sp[RS], sp[RS + 1]));
        g_x1p[((n * 16 + c) * 256 + by * 8 + qy) * 256 + (bx * 8 + qx)] = mo;
    }
}

// ---------------------------------------------------------------------------
// Stage 1b (active tiles only, compacted): channel conv + d1/d2/d3 + pool
// Lane map (conflict-free LDS): prow = lane&15, pcol = (lane>>4)*8.
// SMEM (floats): s_a [0..10240) padded 32xCS (d3-out flat 16x256 aliases);
//                s_b [10240..18432) compact 32x256 (s_xc padded 16xCS aliases)
// ---------------------------------------------------------------------------
__global__ void __launch_bounds__(256, 2) stage1_active_kernel(
    const float* __restrict__ x,
    const float* __restrict__ cw, const float* __restrict__ cb,
    const float* __restrict__ d1w, const float* __restrict__ d1b,
    const float* __restrict__ d2b,
    const float* __restrict__ d3w, const float* __restrict__ d3b)
{
    if ((int)blockIdx.x >= g_cnt1) return;
    const int bid = g_list1[blockIdx.x];

    extern __shared__ float sm[];
    float*  s_a   = sm;                  // padded [32][CS]
    float*  s_f   = sm;                  // d3 out flat [16][256]
    float*  s_b   = sm + 10240;          // compact [32][256]
    float*  s_xc  = s_b;                 // padded [16][CS] alias

    const int n   = bid >> 10;
    const int by  = (bid >> 5) & 31;
    const int bx  = bid & 31;
    const int tid = threadIdx.x;
    const int py  = tid >> 4, px_ = tid & 15;
    const int gy  = by * 16 + py, gx = bx * 16 + px_;

    // channel path: 1x1 conv 3->16 + bias, relu, bn  -> s_xc (padded)
    {
        const int ibase = ((n * 3) * 512 + gy) * 512 + gx;
        float xv0 = x[ibase];
        float xv1 = x[ibase + 512 * 512];
        float xv2 = x[ibase + 2 * 512 * 512];
        const int po = py * RS + px_;
#pragma unroll
        for (int c = 0; c < 16; c++) {
            float t = __ldg(&cw[c * 3 + 0]) * xv0 + __ldg(&cw[c * 3 + 1]) * xv1 +
                      __ldg(&cw[c * 3 + 2]) * xv2 + __ldg(&cb[c]);
            t = fmaxf(t, 0.0f);
            s_xc[c * CS + po] = fmaf(__ldg(&g_sc[c]), t, __ldg(&g_sh[c]));
        }
    }
    __syncthreads();

    // conflict-free lane map: 8 distinct rows per LDS phase
    const int lane  = tid & 31;
    const int prow  = lane & 15;          // 0..15
    const int pcol  = (lane >> 4) * 8;    // 0 or 8
    const int wg    = tid >> 5;           // warp id 0..7

    // ---- d1: 1x1, 16 -> 32 ----  (8px x 4c2 per thread; pixel-pair accs)
    {
        const int c2base = wg * 4;
        ull acc[4][4];
#pragma unroll
        for (int c2 = 0; c2 < 4; c2++) {
            ull bv = dup2(__ldg(&d1b[c2base + c2]));
            acc[c2][0] = bv; acc[c2][1] = bv; acc[c2][2] = bv; acc[c2][3] = bv;
        }
        const int po = prow * RS + pcol;
#pragma unroll
        for (int c1 = 0; c1 < 16; c1++) {
            const float* p = s_xc + c1 * CS + po;
            float4 a = *(const float4*)p;
            float4 b = *(const float4*)(p + 4);
            ull va0 = pack2(a.x, a.y), va1 = pack2(a.z, a.w);
            ull vb0 = pack2(b.x, b.y), vb1 = pack2(b.z, b.w);
#pragma unroll
            for (int c2 = 0; c2 < 4; c2++) {
                ull w = dup2(__ldg(&d1w[(c2base + c2) * 16 + c1]));
                fma2(acc[c2][0], w, va0);
                fma2(acc[c2][1], w, va1);
                fma2(acc[c2][2], w, vb0);
                fma2(acc[c2][3], w, vb1);
            }
        }
#pragma unroll
        for (int c2 = 0; c2 < 4; c2++) {
            int c = c2base + c2;
            float sc = __ldg(&g_sc[16 + c]), sh = __ldg(&g_sh[16 + c]);
            float4 o0, o1;
            float2 f0 = unpack2(acc[c2][0]), f1 = unpack2(acc[c2][1]);
            float2 f2 = unpack2(acc[c2][2]), f3 = unpack2(acc[c2][3]);
            o0.x = fmaf(sc, fmaxf(f0.x, 0.f), sh); o0.y = fmaf(sc, fmaxf(f0.y, 0.f), sh);
            o0.z = fmaf(sc, fmaxf(f1.x, 0.f), sh); o0.w = fmaf(sc, fmaxf(f1.y, 0.f), sh);
            o1.x = fmaf(sc, fmaxf(f2.x, 0.f), sh); o1.y = fmaf(sc, fmaxf(f2.y, 0.f), sh);
            o1.z = fmaf(sc, fmaxf(f3.x, 0.f), sh); o1.w = fmaf(sc, fmaxf(f3.y, 0.f), sh);
            *(float4*)(s_a + c * CS + po)     = o0;
            *(float4*)(s_a + c * CS + po + 4) = o1;
        }
    }
    __syncthreads();

    // ---- d2: 3x3 (block-padded), 32 -> 32 ----  (8px x 4c2; channel-pair accs)
    {
        const int pairb = wg * 2;
        ull acc[2][8];
#pragma unroll
        for (int p = 0; p < 2; p++) {
            int c2 = 2 * (pairb + p);
            ull bv = pack2(__ldg(&d2b[c2]), __ldg(&d2b[c2 + 1]));
#pragma unroll
            for (int k = 0; k < 8; k++) acc[p][k] = bv;
        }
        const float* sap = s_a + pcol;
        const ulonglong2* __restrict__ wbase =
            (const ulonglong2*)g_w2p + pairb / 2;
#pragma unroll 4
        for (int c1 = 0; c1 < 32; c1++) {
            const float* cbase = sap + c1 * CS;
#pragma unroll
            for (int r = 0; r < 3; r++) {
                int yy = prow - 1 + r;
                float u0, u9; float4 m1, m2;
                if ((unsigned)yy < 16u) {
                    const float* rp = cbase + yy * RS;
                    m1 = *(const float4*)rp;
                    m2 = *(const float4*)(rp + 4);
                    u0 = pcol ? rp[-1] : 0.f;
                    u9 = pcol ? 0.f : rp[8];
                } else {
                    m1 = make_float4(0.f, 0.f, 0.f, 0.f);
                    m2 = m1; u0 = 0.f; u9 = 0.f;
                }
                ull vd[10] = {dup2(u0), dup2(m1.x), dup2(m1.y), dup2(m1.z), dup2(m1.w),
                              dup2(m2.x), dup2(m2.y), dup2(m2.z), dup2(m2.w), dup2(u9)};
                const ulonglong2* wrow = wbase + (c1 * 9 + r * 3) * 8;
#pragma unroll
                for (int dx = 0; dx < 3; dx++) {
                    ulonglong2 w = __ldg(wrow + dx * 8);
#pragma unroll
                    for (int k = 0; k < 8; k++) {
                        fma2(acc[0][k], w.x, vd[dx + k]);
                        fma2(acc[1][k], w.y, vd[dx + k]);
                    }
                }
            }
        }
        const int poc = prow * 16 + pcol;
#pragma unroll
        for (int p = 0; p < 2; p++) {
            int c2 = 2 * (pairb + p);
            float sa = __ldg(&g_sc[48 + c2]), ha = __ldg(&g_sh[48 + c2]);
            float sb2 = __ldg(&g_sc[48 + c2 + 1]), hb = __ldg(&g_sh[48 + c2 + 1]);
            float4 oa0, oa1, ob0, ob1;
            float2 f;
            f = unpack2(acc[p][0]); oa0.x = fmaf(sa, fmaxf(f.x,0.f), ha); ob0.x = fmaf(sb2, fmaxf(f.y,0.f), hb);
            f = unpack2(acc[p][1]); oa0.y = fmaf(sa, fmaxf(f.x,0.f), ha); ob0.y = fmaf(sb2, fmaxf(f.y,0.f), hb);
            f = unpack2(acc[p][2]); oa0.z = fmaf(sa, fmaxf(f.x,0.f), ha); ob0.z = fmaf(sb2, fmaxf(f.y,0.f), hb);
            f = unpack2(acc[p][3]); oa0.w = fmaf(sa, fmaxf(f.x,0.f), ha); ob0.w = fmaf(sb2, fmaxf(f.y,0.f), hb);
            f = unpack2(acc[p][4]); oa1.x = fmaf(sa, fmaxf(f.x,0.f), ha); ob1.x = fmaf(sb2, fmaxf(f.y,0.f), hb);
            f = unpack2(acc[p][5]); oa1.y = fmaf(sa, fmaxf(f.x,0.f), ha); ob1.y = fmaf(sb2, fmaxf(f.y,0.f), hb);
            f = unpack2(acc[p][6]); oa1.z = fmaf(sa, fmaxf(f.x,0.f), ha); ob1.z = fmaf(sb2, fmaxf(f.y,0.f), hb);
            f = unpack2(acc[p][7]); oa1.w = fmaf(sa, fmaxf(f.x,0.f), ha); ob1.w = fmaf(sb2, fmaxf(f.y,0.f), hb);
            *(float4*)(s_b + c2 * 256 + poc)           = oa0;
            *(float4*)(s_b + c2 * 256 + poc + 4)       = oa1;
            *(float4*)(s_b + (c2 + 1) * 256 + poc)     = ob0;
            *(float4*)(s_b + (c2 + 1) * 256 + poc + 4) = ob1;
        }
    }
    __syncthreads();

    // ---- d3: 1x1, 32 -> 16 ----  (coalesced quad map; pixel-pair accs)
    {
        const int q      = tid & 63;
        const int c2base = (tid >> 6) * 4;
        ull acc[4][2];
#pragma unroll
        for (int c2 = 0; c2 < 4; c2++) {
            ull bv = dup2(__ldg(&d3b[c2base + c2]));
            acc[c2][0] = bv; acc[c2][1] = bv;
        }
#pragma unroll 4
        for (int c1 = 0; c1 < 32; c1++) {
            float4 v = *(const float4*)(s_b + c1 * 256 + q * 4);
            ull v0 = pack2(v.x, v.y), v1 = pack2(v.z, v.w);
#pragma unroll
            for (int c2 = 0; c2 < 4; c2++) {
                ull w = dup2(__ldg(&d3w[(c2base + c2) * 32 + c1]));
                fma2(acc[c2][0], w, v0);
                fma2(acc[c2][1], w, v1);
            }
        }
#pragma unroll
        for (int c2 = 0; c2 < 4; c2++) {
            int c = c2base + c2;
            float sc = __ldg(&g_sc[80 + c]), sh = __ldg(&g_sh[80 + c]);
            float2 f0 = unpack2(acc[c2][0]), f1 = unpack2(acc[c2][1]);
            float4 o;
            o.x = fmaf(sc, fmaxf(f0.x, 0.f), sh);
            o.y = fmaf(sc, fmaxf(f0.y, 0.f), sh);
            o.z = fmaf(sc, fmaxf(f1.x, 0.f), sh);
            o.w = fmaf(sc, fmaxf(f1.y, 0.f), sh);
            *(float4*)(s_f + c * 256 + q * 4) = o;
        }
    }
    __syncthreads();

    // fused 2x2 maxpool -> g_x1p
#pragma unroll
    for (int k = 0; k < 4; k++) {
        int o = tid + k * 256;
        int c = o >> 6;
        int q = o & 63;
        int qy = q >> 3, qx = q & 7;
        const float* sp = &s_f[c * 256 + (qy * 2) * 16 + qx * 2];
        float mo = fmaxf(fmaxf(sp[0], sp[1]), fmaxf(sp[16], sp[17]));
        g_x1p[((n * 16 + c) * 256 + by * 8 + qy) * 256 + (bx * 8 + qx)] = mo;
    }
}

// ---------------------------------------------------------------------------
// Stage 2: g_x1p[16,16,256,256] -> g_x2p[16,8,128,128]
// d2 remapped to 8px x 2c2 (one c2-pair per warp), conflict-free lane map,
// occupancy target 3 CTAs/SM.
// ---------------------------------------------------------------------------
__global__ void __launch_bounds__(256, 3) stage2_kernel(
    const float* __restrict__ cw, const float* __restrict__ cb,
    const float* __restrict__ d1w, const float* __restrict__ d1b,
    const float* __restrict__ d2b,
    const float* __restrict__ d3w, const float* __restrict__ d3b)
{
    extern __shared__ float sm2[];
    float*  s_a   = sm2;
    float*  s_f   = sm2;
    float*  s_b   = sm2 + 5120;
    float*  s_xc  = s_b;

    __shared__ float s_wsum[8];
    __shared__ int s_active;

    const int bid = blockIdx.x;
    const int n   = bid >> 8;
    const int by  = (bid >> 4) & 15;
    const int bx  = bid & 15;
    const int tid = threadIdx.x;
    const int py  = tid >> 4, px_ = tid & 15;
    const int gy  = by * 16 + py, gx = bx * 16 + px_;

    {
        float mv = g_mask2[(n * 256 + gy) * 256 + gx];
#pragma unroll
        for (int o = 16; o; o >>= 1) mv += __shfl_xor_sync(0xffffffffu, mv, o);
        if ((tid & 31) == 0) s_wsum[tid >> 5] = mv;
    }
    __syncthreads();
    if (tid == 0) {
        float t = 0.f;
#pragma unroll
        for (int i = 0; i < 8; i++) t += s_wsum[i];
        s_active = (t > 128.0f) ? 1 : 0;
    }

    // channel path: 1x1 conv 16->8 -> s_xc (padded)
    {
        const int ibase = ((n * 16) * 256 + gy) * 256 + gx;
        float xin[16];
#pragma unroll
        for (int c = 0; c < 16; c++) xin[c] = g_x1p[ibase + c * 65536];
        const int po = py * RS + px_;
#pragma unroll
        for (int c2 = 0; c2 < 8; c2++) {
            float t = __ldg(&cb[c2]);
#pragma unroll
            for (int c1 = 0; c1 < 16; c1++)
                t = fmaf(xin[c1], __ldg(&cw[c2 * 16 + c1]), t);
            t = fmaxf(t, 0.0f);
            s_xc[c2 * CS + po] = fmaf(__ldg(&g_sc[96 + c2]), t, __ldg(&g_sh[96 + c2]));
        }
    }
    __syncthreads();

    const int act  = s_active;
    const int lane = tid & 31;
    const int wg   = tid >> 5;
    const int prow = lane & 15;           // conflict-free lane map
    const int pcol = (lane >> 4) * 8;

    if (act) {
        // ---- d1: 1x1, 8 -> 16 ----  (8px x 2c2; pixel-pair accs)
        {
            const int c2base = wg * 2;
            const int po = prow * RS + pcol;
            ull acc[2][4];
#pragma unroll
            for (int c2 = 0; c2 < 2; c2++) {
                ull bv = dup2(__ldg(&d1b[c2base + c2]));
                acc[c2][0] = bv; acc[c2][1] = bv; acc[c2][2] = bv; acc[c2][3] = bv;
            }
#pragma unroll
            for (int c1 = 0; c1 < 8; c1++) {
                const float* p = s_xc + c1 * CS + po;
                float4 a = *(const float4*)p;
                float4 b = *(const float4*)(p + 4);
                ull va0 = pack2(a.x, a.y), va1 = pack2(a.z, a.w);
                ull vb0 = pack2(b.x, b.y), vb1 = pack2(b.z, b.w);
#pragma unroll
                for (int c2 = 0; c2 < 2; c2++) {
                    ull w = dup2(__ldg(&d1w[(c2base + c2) * 8 + c1]));
                    fma2(acc[c2][0], w, va0);
                    fma2(acc[c2][1], w, va1);
                    fma2(acc[c2][2], w, vb0);
                    fma2(acc[c2][3], w, vb1);
                }
            }
#pragma unroll
            for (int c2 = 0; c2 < 2; c2++) {
                int c = c2base + c2;
                float sc = __ldg(&g_sc[104 + c]), sh = __ldg(&g_sh[104 + c]);
                float2 f0 = unpack2(acc[c2][0]), f1 = unpack2(acc[c2][1]);
                float2 f2 = unpack2(acc[c2][2]), f3 = unpack2(acc[c2][3]);
                float4 o0, o1;
                o0.x = fmaf(sc, fmaxf(f0.x, 0.f), sh); o0.y = fmaf(sc, fmaxf(f0.y, 0.f), sh);
                o0.z = fmaf(sc, fmaxf(f1.x, 0.f), sh); o0.w = fmaf(sc, fmaxf(f1.y, 0.f), sh);
                o1.x = fmaf(sc, fmaxf(f2.x, 0.f), sh); o1.y = fmaf(sc, fmaxf(f2.y, 0.f), sh);
                o1.z = fmaf(sc, fmaxf(f3.x, 0.f), sh); o1.w = fmaf(sc, fmaxf(f3.y, 0.f), sh);
                *(float4*)(s_a + c * CS + po)     = o0;
                *(float4*)(s_a + c * CS + po + 4) = o1;
            }
        }
        __syncthreads();

        // ---- d2: 3x3, 16 -> 16 ----  (8px x 2c2; one c2-pair per warp)
        {
            const int pairb = wg;           // pair 0..7 -> c2 = 2*wg, 2*wg+1
            ull acc[8];
            {
                int c2 = 2 * pairb;
                ull bv = pack2(__ldg(&d2b[c2]), __ldg(&d2b[c2 + 1]));
#pragma unroll
                for (int k = 0; k < 8; k++) acc[k] = bv;
            }
            const float* sap = s_a + pcol;
            const ull* __restrict__ wbase = (const ull*)g_q2p + pairb;
#pragma unroll 4
            for (int c1 = 0; c1 < 16; c1++) {
                const float* cbase = sap + c1 * CS;
#pragma unroll
                for (int r = 0; r < 3; r++) {
                    int yy = prow - 1 + r;
                    float u0, u9; float4 m1, m2;
                    if ((unsigned)yy < 16u) {
                        const float* rp = cbase + yy * RS;
                        m1 = *(const float4*)rp;
                        m2 = *(const float4*)(rp + 4);
                        u0 = pcol ? rp[-1] : 0.f;
                        u9 = pcol ? 0.f : rp[8];
                    } else {
                        m1 = make_float4(0.f, 0.f, 0.f, 0.f);
                        m2 = m1; u0 = 0.f; u9 = 0.f;
                    }
                    ull vd[10] = {dup2(u0), dup2(m1.x), dup2(m1.y), dup2(m1.z), dup2(m1.w),
                                  dup2(m2.x), dup2(m2.y), dup2(m2.z), dup2(m2.w), dup2(u9)};
                    const ull* wrow = wbase + (c1 * 9 + r * 3) * 8;
#pragma unroll
                    for (int dx = 0; dx < 3; dx++) {
                        ull w = __ldg(wrow + dx * 8);
#pragma unroll
                        for (int k = 0; k < 8; k++) fma2(acc[k], w, vd[dx + k]);
                    }
                }
            }
            const int poc = prow * 16 + pcol;
            {
                int c2 = 2 * pairb;
                float sa = __ldg(&g_sc[120 + c2]), ha = __ldg(&g_sh[120 + c2]);
                float sb2 = __ldg(&g_sc[120 + c2 + 1]), hb = __ldg(&g_sh[120 + c2 + 1]);
                float4 oa0, oa1, ob0, ob1;
                float2 f;
                f = unpack2(acc[0]); oa0.x = fmaf(sa, fmaxf(f.x,0.f), ha); ob0.x = fmaf(sb2, fmaxf(f.y,0.f), hb);
                f = unpack2(acc[1]); oa0.y = fmaf(sa, fmaxf(f.x,0.f), ha); ob0.y = fmaf(sb2, fmaxf(f.y,0.f), hb);
                f = unpack2(acc[2]); oa0.z = fmaf(sa, fmaxf(f.x,0.f), ha); ob0.z = fmaf(sb2, fmaxf(f.y,0.f), hb);
                f = unpack2(acc[3]); oa0.w = fmaf(sa, fmaxf(f.x,0.f), ha); ob0.w = fmaf(sb2, fmaxf(f.y,0.f), hb);
                f = unpack2(acc[4]); oa1.x = fmaf(sa, fmaxf(f.x,0.f), ha); ob1.x = fmaf(sb2, fmaxf(f.y,0.f), hb);
                f = unpack2(acc[5]); oa1.y = fmaf(sa, fmaxf(f.x,0.f), ha); ob1.y = fmaf(sb2, fmaxf(f.y,0.f), hb);
                f = unpack2(acc[6]); oa1.z = fmaf(sa, fmaxf(f.x,0.f), ha); ob1.z = fmaf(sb2, fmaxf(f.y,0.f), hb);
                f = unpack2(acc[7]); oa1.w = fmaf(sa, fmaxf(f.x,0.f), ha); ob1.w = fmaf(sb2, fmaxf(f.y,0.f), hb);
                *(float4*)(s_b + c2 * 256 + poc)           = oa0;
                *(float4*)(s_b + c2 * 256 + poc + 4)       = oa1;
                *(float4*)(s_b + (c2 + 1) * 256 + poc)     = ob0;
                *(float4*)(s_b + (c2 + 1) * 256 + poc + 4) = ob1;
            }
        }
        __syncthreads();

        // ---- d3: 1x1, 16 -> 8 ----  (coalesced quad map; pixel-pair accs)
        {
            const int q      = tid & 63;
            const int c2base = (tid >> 6) * 2;
            ull acc[2][2];
#pragma unroll
            for (int c2 = 0; c2 < 2; c2++) {
                ull bv = dup2(__ldg(&d3b[c2base + c2]));
                acc[c2][0] = bv; acc[c2][1] = bv;
            }
#pragma unroll
            for (int c1 = 0; c1 < 16; c1++) {
                float4 v = *(const float4*)(s_b + c1 * 256 + q * 4);
                ull v0 = pack2(v.x, v.y), v1 = pack2(v.z, v.w);
#pragma unroll
                for (int c2 = 0; c2 < 2; c2++) {
                    ull w = dup2(__ldg(&d3w[(c2base + c2) * 16 + c1]));
                    fma2(acc[c2][0], w, v0);
                    fma2(acc[c2][1], w, v1);
                }
            }
#pragma unroll
            for (int c2 = 0; c2 < 2; c2++) {
                int c = c2base + c2;
                float sc = __ldg(&g_sc[136 + c]), sh = __ldg(&g_sh[136 + c]);
                float2 f0 = unpack2(acc[c2][0]), f1 = unpack2(acc[c2][1]);
                float4 o;
                o.x = fmaf(sc, fmaxf(f0.x, 0.f), sh);
                o.y = fmaf(sc, fmaxf(f0.y, 0.f), sh);
                o.z = fmaf(sc, fmaxf(f1.x, 0.f), sh);
                o.w = fmaf(sc, fmaxf(f1.y, 0.f), sh);
                *(float4*)(s_f + c * 256 + q * 4) = o;
            }
        }
        __syncthreads();
    }

    // fused maxpool -> g_x2p
    const float* srcp = act ? s_f : s_xc;
    const int chs = act ? 256 : CS;
    const int rs  = act ? 16 : RS;
#pragma unroll
    for (int k = 0; k < 2; k++) {
        int o = tid + k * 256;
        int c = o >> 6;
        int q = o & 63;
        int qy = q >> 3, qx = q & 7;
        const float* sp = &srcp[c * chs + (qy * 2) * rs + qx * 2];
        float mo = fmaxf(fmaxf(sp[0], sp[1]), fmaxf(sp[rs], sp[rs + 1]));
        g_x2p[((n * 8 + c) * 128 + by * 8 + qy) * 128 + (bx * 8 + qx)] = mo;
    }
}

// ---------------------------------------------------------------------------
// FC (split-K x32, vectorized) + softmax
// ---------------------------------------------------------------------------
__global__ void __launch_bounds__(256) fc_partial_kernel(const float* __restrict__ fc_w)
{
    const int b = blockIdx.x;       // 0..511
    const int n = b >> 5, s = b & 31;
    const int tid = threadIdx.x;
    const float4* f = (const float4*)(g_x2p + n * 131072 + s * 4096);
    const float4* w = (const float4*)(fc_w) + s * 1024;

    float part[10];
#pragma unroll
    for (int k = 0; k < 10; k++) part[k] = 0.0f;

#pragma unroll
    for (int j = tid; j < 1024; j += 256) {
        float4 fv = f[j];
#pragma unroll
        for (int k = 0; k < 10; k++) {
            float4 wv = __ldg(&w[k * 32768 + j]);
            part[k] += fv.x * wv.x + fv.y * wv.y + fv.z * wv.z + fv.w * wv.w;
        }
    }

    __shared__ float sred[10][256];
#pragma unroll
    for (int k = 0; k < 10; k++) sred[k][tid] = part[k];
    __syncthreads();
    for (int st = 128; st > 0; st >>= 1) {
        if (tid < st) {
#pragma unroll
            for (int k = 0; k < 10; k++) sred[k][tid] += sred[k][tid + st];
        }
        __syncthreads();
    }
    if (tid < 10) g_fcpart[(n * 32 + s) * 10 + tid] = sred[tid][0];
}

__global__ void fc_final_kernel(const float* __restrict__ fc_b, float* __restrict__ out)
{
    const int t = threadIdx.x;
    __shared__ float s_l[16][10];
    if (t < 160) {
        int n = t / 10, k = t - n * 10;
        float a = fc_b[k];
#pragma unroll
        for (int s = 0; s < 32; s++) a += g_fcpart[(n * 32 + s) * 10 + k];
        s_l[n][k] = a;
    }
    __syncthreads();
    if (t < 16) {
        float mx = -1e30f;
#pragma unroll
        for (int k = 0; k < 10; k++) mx = fmaxf(mx, s_l[t][k]);
        float e[10], se = 0.f;
#pragma unroll
        for (int k = 0; k < 10; k++) { e[k] = expf(s_l[t][k] - mx); se += e[k]; }
        float inv = 1.0f / se;
#pragma unroll
        for (int k = 0; k < 10; k++) out[t * 10 + k] = e[k] * inv;
    }
}

// ---------------------------------------------------------------------------
extern "C" void kernel_launch(void* const* d_in, const int* in_sizes, int n_in,
                              void* d_out, int out_size)
{
    const float* x      = (const float*)d_in[0];
    const float* mask   = (const float*)d_in[1];
    const float* s1_cw  = (const float*)d_in[2];
    const float* s1_cb  = (const float*)d_in[3];
    const float* s1_bn0 = (const float*)d_in[4];
    const float* s1_d1w = (const float*)d_in[5];
    const float* s1_d1b = (const float*)d_in[6];
    const float* s1_bn1 = (const float*)d_in[7];
    const float* s1_d2w = (const float*)d_in[8];
    const float* s1_d2b = (const float*)d_in[9];
    const float* s1_bn2 = (const float*)d_in[10];
    const float* s1_d3w = (const float*)d_in[11];
    const float* s1_d3b = (const float*)d_in[12];
    const float* s1_bn3 = (const float*)d_in[13];
    const float* s2_cw  = (const float*)d_in[14];
    const float* s2_cb  = (const float*)d_in[15];
    const float* s2_bn0 = (const float*)d_in[16];
    const float* s2_d1w = (const float*)d_in[17];
    const float* s2_d1b = (const float*)d_in[18];
    const float* s2_bn1 = (const float*)d_in[19];
    const float* s2_d2w = (const float*)d_in[20];
    const float* s2_d2b = (const float*)d_in[21];
    const float* s2_bn2 = (const float*)d_in[22];
    const float* s2_d3w = (const float*)d_in[23];
    const float* s2_d3b = (const float*)d_in[24];
    const float* s2_bn3 = (const float*)d_in[25];
    const float* fc_w   = (const float*)d_in[26];
    const float* fc_b   = (const float*)d_in[27];

    prep_kernel<<<1, 256>>>(s1_d2w, s2_d2w,
                            s1_bn0, s1_bn1, s1_bn2, s1_bn3,
                            s2_bn0, s2_bn1, s2_bn2, s2_bn3);

    stage1_all_kernel<<<16 * 32 * 32, 256>>>(x, mask, s1_cw, s1_cb);

    const int smem1 = 18432 * sizeof(float);   // 72 KB dynamic
    cudaFuncSetAttribute(stage1_active_kernel, cudaFuncAttributeMaxDynamicSharedMemorySize, smem1);
    stage1_active_kernel<<<16 * 32 * 32, 256, smem1>>>(
        x, s1_cw, s1_cb, s1_d1w, s1_d1b, s1_d2b, s1_d3w, s1_d3b);

    const int smem2 = 9216 * sizeof(float);    // 36 KB dynamic
    cudaFuncSetAttribute(stage2_kernel, cudaFuncAttributeMaxDynamicSharedMemorySize, smem2);
    stage2_kernel<<<16 * 16 * 16, 256, smem2>>>(
        s2_cw, s2_cb, s2_d1w, s2_d1b, s2_d2b, s2_d3w, s2_d3b);

    fc_partial_kernel<<<512, 256>>>(fc_w);
    fc_final_kernel<<<1, 256>>>(fc_b, (float*)d_out);
}

// round 8
// speedup vs baseline: 1.1617x; 1.1617x over previous
#include <cuda_runtime.h>

#define EPSV 1e-5f
typedef unsigned long long ull;
typedef unsigned int uint;

__device__ float g_x1p[16 * 16 * 256 * 256];
__device__ float g_mask2[16 * 256 * 256];
__device__ float g_x2p[16 * 8 * 128 * 128];
__device__ float g_fcpart[16 * 32 * 10];
__device__ int   g_cnt1;
__device__ int   g_list1[16384];

__device__ __align__(16) float g_bhi[9216];    // stage1 d2 tf32-hi fragments [kstep][lane][8]
__device__ __align__(16) float g_blo[9216];    // stage1 d2 tf32-lo fragments
__device__ __align__(16) float g_q2p[2304];    // stage2 d2 paired
__device__ float g_sc[144], g_sh[144];

__device__ __forceinline__ void fma2(ull& d, ull a, ull b) {
    asm("fma.rn.f32x2 %0, %1, %2, %0;" : "+l"(d) : "l"(a), "l"(b));
}
__device__ __forceinline__ ull pack2(float lo, float hi) {
    ull r; asm("mov.b64 %0, {%1, %2};" : "=l"(r) : "f"(lo), "f"(hi)); return r;
}
__device__ __forceinline__ ull dup2(float v) { return pack2(v, v); }
__device__ __forceinline__ float2 unpack2(ull u) {
    float2 f; asm("mov.b64 {%0, %1}, %2;" : "=f"(f.x), "=f"(f.y) : "l"(u)); return f;
}
__device__ __forceinline__ uint tf32_rna(float v) {
    uint r; asm("cvt.rna.tf32.f32 %0, %1;" : "=r"(r) : "f"(v)); return r;
}
__device__ __forceinline__ void mma8(float* a, const uint* A, uint b0, uint b1) {
    asm volatile("mma.sync.aligned.m16n8k8.row.col.f32.tf32.tf32.f32 "
        "{%0,%1,%2,%3},{%4,%5,%6,%7},{%8,%9},{%0,%1,%2,%3};"
        : "+f"(a[0]), "+f"(a[1]), "+f"(a[2]), "+f"(a[3])
        : "r"(A[0]), "r"(A[1]), "r"(A[2]), "r"(A[3]), "r"(b0), "r"(b1));
}

#define RS 20
#define CS 320

// ---------------------------------------------------------------------------
__global__ void prep_kernel(
    const float* __restrict__ s1d2w, const float* __restrict__ s2d2w,
    const float* __restrict__ b10, const float* __restrict__ b11,
    const float* __restrict__ b12, const float* __restrict__ b13,
    const float* __restrict__ b20, const float* __restrict__ b21,
    const float* __restrict__ b22, const float* __restrict__ b23)
{
    const int tid = threadIdx.x;
    if (tid == 0) g_cnt1 = 0;
    // stage1 d2 -> tf32 hi/lo mma fragments. K-order: k = tap*32 + c1.
    for (int i = tid; i < 9216; i += 256) {
        int kstep = i >> 8, r = i & 255;
        int ln = r >> 3, jj = r & 7;
        int kk = kstep * 8 + (ln & 3) + (jj & 1) * 4;
        int c2 = (jj >> 1) * 8 + (ln >> 2);
        int tap = kk >> 5, c1 = kk & 31;
        float wv = s1d2w[(c2 * 32 + c1) * 9 + tap];
        uint hu = tf32_rna(wv);
        g_bhi[i] = __uint_as_float(hu);
        g_blo[i] = __uint_as_float(tf32_rna(wv - __uint_as_float(hu)));
    }
    for (int i = tid; i < 2304; i += 256) {
        int c2 = i / 144, rem = i - c2 * 144;
        int c1 = rem / 9, t = rem - c1 * 9;
        g_q2p[((c1 * 9 + t) * 8 + (c2 >> 1)) * 2 + (c2 & 1)] = s2d2w[i];
    }
    if (tid < 144) {
        const float* bp; int c, C;
        if      (tid < 16)  { bp = b10; c = tid;       C = 16; }
        else if (tid < 48)  { bp = b11; c = tid - 16;  C = 32; }
        else if (tid < 80)  { bp = b12; c = tid - 48;  C = 32; }
        else if (tid < 96)  { bp = b13; c = tid - 80;  C = 16; }
        else if (tid < 104) { bp = b20; c = tid - 96;  C = 8;  }
        else if (tid < 120) { bp = b21; c = tid - 104; C = 16; }
        else if (tid < 136) { bp = b22; c = tid - 120; C = 16; }
        else                { bp = b23; c = tid - 136; C = 8;  }
        float g = bp[c], b = bp[C + c], m = bp[2 * C + c], v = bp[3 * C + c];
        float s = g * rsqrtf(v + EPSV);
        g_sc[tid] = s; g_sh[tid] = b - s * m;
    }
}

// ---------------------------------------------------------------------------
__global__ void __launch_bounds__(256) stage1_all_kernel(
    const float* __restrict__ x, const float* __restrict__ mask,
    const float* __restrict__ cw, const float* __restrict__ cb)
{
    __shared__ float s_red[256];
    __shared__ float s_wsum[8];
    __shared__ float s_xc[16 * CS];
    __shared__ int s_active;

    const int bid = blockIdx.x;
    const int n = bid >> 10, by = (bid >> 5) & 31, bx = bid & 31;
    const int tid = threadIdx.x;
    const int py = tid >> 4, px_ = tid & 15;
    const int gy = by * 16 + py, gx = bx * 16 + px_;

    float mval = mask[(n * 512 + gy) * 512 + gx];
    s_red[tid] = mval;
    float msum = mval;
#pragma unroll
    for (int o = 16; o; o >>= 1) msum += __shfl_xor_sync(0xffffffffu, msum, o);
    if ((tid & 31) == 0) s_wsum[tid >> 5] = msum;
    __syncthreads();

    if (tid < 64) {
        int qy = tid >> 3, qx = tid & 7;
        int p0 = (qy * 2) * 16 + qx * 2;
        float m0 = fmaxf(fmaxf(s_red[p0], s_red[p0 + 1]),
                         fmaxf(s_red[p0 + 16], s_red[p0 + 17]));
        g_mask2[(n * 256 + by * 8 + qy) * 256 + (bx * 8 + qx)] = m0;
    }
    if (tid == 0) {
        float t = 0.f;
#pragma unroll
        for (int i = 0; i < 8; i++) t += s_wsum[i];
        int act = (t > 128.0f) ? 1 : 0;
        s_active = act;
        if (act) { int pos = atomicAdd(&g_cnt1, 1); g_list1[pos] = bid; }
    }
    __syncthreads();
    if (s_active) return;

    {
        const int ibase = ((n * 3) * 512 + gy) * 512 + gx;
        float xv0 = x[ibase];
        float xv1 = x[ibase + 512 * 512];
        float xv2 = x[ibase + 2 * 512 * 512];
        const int po = py * RS + px_;
#pragma unroll
        for (int c = 0; c < 16; c++) {
            float t = __ldg(&cw[c * 3 + 0]) * xv0 + __ldg(&cw[c * 3 + 1]) * xv1 +
                      __ldg(&cw[c * 3 + 2]) * xv2 + __ldg(&cb[c]);
            t = fmaxf(t, 0.0f);
            s_xc[c * CS + po] = fmaf(__ldg(&g_sc[c]), t, __ldg(&g_sh[c]));
        }
    }
    __syncthreads();

#pragma unroll
    for (int k = 0; k < 4; k++) {
        int o = tid + k * 256;
        int c = o >> 6, q = o & 63;
        int qy = q >> 3, qx = q & 7;
        const float* sp = &s_xc[c * CS + (qy * 2) * RS + qx * 2];
        float mo = fmaxf(fmaxf(sp[0], sp[1]), fmaxf(sp[RS], sp[RS + 1]));
        g_x1p[((n * 16 + c) * 256 + by * 8 + qy) * 256 + (bx * 8 + qx)] = mo;
    }
}

// ---------------------------------------------------------------------------
// Stage 1b (active): channel conv -> d1 (into zero-border halo) -> d2 via
// tf32 mma 3-term -> d3 -> pool.
// SMEM words: [0..4) guard/pad, s_halo=sm+4 [32][360] (rows 0,17 + cols>=16
// zero), s_b=sm+11528 [32][260] (s_xc [16][CS] aliases), s_f=sm (d3 out).
// ---------------------------------------------------------------------------
__global__ void __launch_bounds__(256, 2) stage1_active_kernel(
    const float* __restrict__ x,
    const float* __restrict__ cw, const float* __restrict__ cb,
    const float* __restrict__ d1w, const float* __restrict__ d1b,
    const float* __restrict__ d2b,
    const float* __restrict__ d3w, const float* __restrict__ d3b)
{
    if ((int)blockIdx.x >= g_cnt1) return;
    const int bid = g_list1[blockIdx.x];

    extern __shared__ float sm[];
    float* s_halo = sm + 4;
    float* s_f    = sm;
    float* s_b    = sm + 11528;   // stride 260
    float* s_xc   = s_b;          // [16][CS]

    const int n = bid >> 10, by = (bid >> 5) & 31, bx = bid & 31;
    const int tid = threadIdx.x;
    const int py = tid >> 4, px_ = tid & 15;
    const int gy = by * 16 + py, gx = bx * 16 + px_;

    // zero guard + halo (words 0..11528)
    {
        float4 z4 = make_float4(0.f, 0.f, 0.f, 0.f);
        for (int i = tid; i < 2882; i += 256) ((float4*)sm)[i] = z4;
    }
    // channel conv -> s_xc (disjoint from halo)
    {
        const int ibase = ((n * 3) * 512 + gy) * 512 + gx;
        float xv0 = x[ibase];
        float xv1 = x[ibase + 512 * 512];
        float xv2 = x[ibase + 2 * 512 * 512];
        const int po = py * RS + px_;
#pragma unroll
        for (int c = 0; c < 16; c++) {
            float t = __ldg(&cw[c * 3 + 0]) * xv0 + __ldg(&cw[c * 3 + 1]) * xv1 +
                      __ldg(&cw[c * 3 + 2]) * xv2 + __ldg(&cb[c]);
            t = fmaxf(t, 0.0f);
            s_xc[c * CS + po] = fmaf(__ldg(&g_sc[c]), t, __ldg(&g_sh[c]));
        }
    }
    __syncthreads();

    const int lane = tid & 31, wg = tid >> 5;
    const int prow = lane & 15, pcol = (lane >> 4) * 8;

    // ---- d1: 1x1, 16 -> 32 (writes halo interior rows 1..16, cols 0..15) ----
    {
        const int c2base = wg * 4;
        ull acc[4][4];
#pragma unroll
        for (int c2 = 0; c2 < 4; c2++) {
            ull bv = dup2(__ldg(&d1b[c2base + c2]));
            acc[c2][0] = bv; acc[c2][1] = bv; acc[c2][2] = bv; acc[c2][3] = bv;
        }
        const int po = prow * RS + pcol;
#pragma unroll
        for (int c1 = 0; c1 < 16; c1++) {
            const float* p = s_xc + c1 * CS + po;
            float4 a = *(const float4*)p;
            float4 b = *(const float4*)(p + 4);
            ull va0 = pack2(a.x, a.y), va1 = pack2(a.z, a.w);
            ull vb0 = pack2(b.x, b.y), vb1 = pack2(b.z, b.w);
#pragma unroll
            for (int c2 = 0; c2 < 4; c2++) {
                ull w = dup2(__ldg(&d1w[(c2base + c2) * 16 + c1]));
                fma2(acc[c2][0], w, va0);
                fma2(acc[c2][1], w, va1);
                fma2(acc[c2][2], w, vb0);
                fma2(acc[c2][3], w, vb1);
            }
        }
        const int ho = (prow + 1) * 20 + pcol;
#pragma unroll
        for (int c2 = 0; c2 < 4; c2++) {
            int c = c2base + c2;
            float sc = __ldg(&g_sc[16 + c]), sh = __ldg(&g_sh[16 + c]);
            float4 o0, o1;
            float2 f0 = unpack2(acc[c2][0]), f1 = unpack2(acc[c2][1]);
            float2 f2 = unpack2(acc[c2][2]), f3 = unpack2(acc[c2][3]);
            o0.x = fmaf(sc, fmaxf(f0.x, 0.f), sh); o0.y = fmaf(sc, fmaxf(f0.y, 0.f), sh);
            o0.z = fmaf(sc, fmaxf(f1.x, 0.f), sh); o0.w = fmaf(sc, fmaxf(f1.y, 0.f), sh);
            o1.x = fmaf(sc, fmaxf(f2.x, 0.f), sh); o1.y = fmaf(sc, fmaxf(f2.y, 0.f), sh);
            o1.z = fmaf(sc, fmaxf(f3.x, 0.f), sh); o1.w = fmaf(sc, fmaxf(f3.y, 0.f), sh);
            *(float4*)(s_halo + c * 360 + ho)     = o0;
            *(float4*)(s_halo + c * 360 + ho + 4) = o1;
        }
    }
    __syncthreads();

    // ---- d2: 3x3, 32 -> 32 via tf32 mma (3-term) ----
    // warp wg: image rows wg and wg+8 (2 M-tiles of 16 px), all 32 c2.
    {
        const int tg = lane & 3, q = lane >> 2;
        float acc[8][4];
#pragma unroll
        for (int i = 0; i < 8; i++) {
            int c2 = (i & 3) * 8 + tg * 2;
            float b0 = __ldg(&d2b[c2]), b1 = __ldg(&d2b[c2 + 1]);
            acc[i][0] = b0; acc[i][1] = b1; acc[i][2] = b0; acc[i][3] = b1;
        }
        const float* hp0 = s_halo + tg * 360 + wg * 20 + q - 1;
        const uint4* bh = (const uint4*)g_bhi + lane * 2;
        const uint4* bl = (const uint4*)g_blo + lane * 2;
#pragma unroll 1
        for (int tap = 0; tap < 9; tap++) {
            int dyq = (tap * 11) >> 5;                 // dy
            const float* hp = hp0 + tap + 17 * dyq;    // + dy*20 + dx - 1
#pragma unroll
            for (int kl = 0; kl < 4; kl++) {
                float av[8];
                av[0] = hp[0];    av[1] = hp[8];    av[2] = hp[1440]; av[3] = hp[1448];
                av[4] = hp[160];  av[5] = hp[168];  av[6] = hp[1600]; av[7] = hp[1608];
                hp += 2880;
                uint Ah[8], Al[8];
#pragma unroll
                for (int i = 0; i < 8; i++) {
                    Ah[i] = tf32_rna(av[i]);
                    Al[i] = tf32_rna(av[i] - __uint_as_float(Ah[i]));
                }
                uint4 H0 = __ldg(bh), H1 = __ldg(bh + 1);
                uint4 L0 = __ldg(bl), L1 = __ldg(bl + 1);
                bh += 64; bl += 64;
                uint BH[8] = {H0.x, H0.y, H0.z, H0.w, H1.x, H1.y, H1.z, H1.w};
                uint BL[8] = {L0.x, L0.y, L0.z, L0.w, L1.x, L1.y, L1.z, L1.w};
#pragma unroll
                for (int nt = 0; nt < 4; nt++) {
                    mma8(acc[nt],     Ah,     BH[2*nt], BH[2*nt+1]);
                    mma8(acc[nt],     Ah,     BL[2*nt], BL[2*nt+1]);
                    mma8(acc[nt],     Al,     BH[2*nt], BH[2*nt+1]);
                    mma8(acc[nt + 4], Ah + 4, BH[2*nt], BH[2*nt+1]);
                    mma8(acc[nt + 4], Ah + 4, BL[2*nt], BL[2*nt+1]);
                    mma8(acc[nt + 4], Al + 4, BH[2*nt], BH[2*nt+1]);
                }
            }
        }
        // epilogue: bias already in acc; relu + bn -> s_b (stride 260)
#pragma unroll
        for (int i = 0; i < 8; i++) {
            int mt = i >> 2, nt = i & 3;
            int c2 = nt * 8 + tg * 2;
            float s0 = __ldg(&g_sc[48 + c2]), h0 = __ldg(&g_sh[48 + c2]);
            float s1 = __ldg(&g_sc[49 + c2]), h1 = __ldg(&g_sh[49 + c2]);
            float* o = s_b + c2 * 260 + (wg + mt * 8) * 16 + q;
            o[0]   = fmaf(s0, fmaxf(acc[i][0], 0.f), h0);
            o[260] = fmaf(s1, fmaxf(acc[i][1], 0.f), h1);
            o[8]   = fmaf(s0, fmaxf(acc[i][2], 0.f), h0);
            o[268] = fmaf(s1, fmaxf(acc[i][3], 0.f), h1);
        }
    }
    __syncthreads();

    // ---- d3: 1x1, 32 -> 16 ----
    {
        const int q = tid & 63;
        const int c2base = (tid >> 6) * 4;
        ull acc[4][2];
#pragma unroll
        for (int c2 = 0; c2 < 4; c2++) {
            ull bv = dup2(__ldg(&d3b[c2base + c2]));
            acc[c2][0] = bv; acc[c2][1] = bv;
        }
#pragma unroll 4
        for (int c1 = 0; c1 < 32; c1++) {
            float4 v = *(const float4*)(s_b + c1 * 260 + q * 4);
            ull v0 = pack2(v.x, v.y), v1 = pack2(v.z, v.w);
#pragma unroll
            for (int c2 = 0; c2 < 4; c2++) {
                ull w = dup2(__ldg(&d3w[(c2base + c2) * 32 + c1]));
                fma2(acc[c2][0], w, v0);
                fma2(acc[c2][1], w, v1);
            }
        }
#pragma unroll
        for (int c2 = 0; c2 < 4; c2++) {
            int c = c2base + c2;
            float sc = __ldg(&g_sc[80 + c]), sh = __ldg(&g_sh[80 + c]);
            float2 f0 = unpack2(acc[c2][0]), f1 = unpack2(acc[c2][1]);
            float4 o;
            o.x = fmaf(sc, fmaxf(f0.x, 0.f), sh);
            o.y = fmaf(sc, fmaxf(f0.y, 0.f), sh);
            o.z = fmaf(sc, fmaxf(f1.x, 0.f), sh);
            o.w = fmaf(sc, fmaxf(f1.y, 0.f), sh);
            *(float4*)(s_f + c * 256 + q * 4) = o;
        }
    }
    __syncthreads();

#pragma unroll
    for (int k = 0; k < 4; k++) {
        int o = tid + k * 256;
        int c = o >> 6, q = o & 63;
        int qy = q >> 3, qx = q & 7;
        const float* sp = &s_f[c * 256 + (qy * 2) * 16 + qx * 2];
        float mo = fmaxf(fmaxf(sp[0], sp[1]), fmaxf(sp[16], sp[17]));
        g_x1p[((n * 16 + c) * 256 + by * 8 + qy) * 256 + (bx * 8 + qx)] = mo;
    }
}

// ---------------------------------------------------------------------------
// Stage 2 (unchanged from round 6)
// ---------------------------------------------------------------------------
__global__ void __launch_bounds__(256, 3) stage2_kernel(
    const float* __restrict__ cw, const float* __restrict__ cb,
    const float* __restrict__ d1w, const float* __restrict__ d1b,
    const float* __restrict__ d2b,
    const float* __restrict__ d3w, const float* __restrict__ d3b)
{
    extern __shared__ float sm2[];
    float* s_a = sm2;
    float* s_f = sm2;
    float* s_b = sm2 + 5120;
    float* s_xc = s_b;

    __shared__ float s_wsum[8];
    __shared__ int s_active;

    const int bid = blockIdx.x;
    const int n = bid >> 8, by = (bid >> 4) & 15, bx = bid & 15;
    const int tid = threadIdx.x;
    const int py = tid >> 4, px_ = tid & 15;
    const int gy = by * 16 + py, gx = bx * 16 + px_;

    {
        float mv = g_mask2[(n * 256 + gy) * 256 + gx];
#pragma unroll
        for (int o = 16; o; o >>= 1) mv += __shfl_xor_sync(0xffffffffu, mv, o);
        if ((tid & 31) == 0) s_wsum[tid >> 5] = mv;
    }
    __syncthreads();
    if (tid == 0) {
        float t = 0.f;
#pragma unroll
        for (int i = 0; i < 8; i++) t += s_wsum[i];
        s_active = (t > 128.0f) ? 1 : 0;
    }

    {
        const int ibase = ((n * 16) * 256 + gy) * 256 + gx;
        float xin[16];
#pragma unroll
        for (int c = 0; c < 16; c++) xin[c] = g_x1p[ibase + c * 65536];
        const int po = py * RS + px_;
#pragma unroll
        for (int c2 = 0; c2 < 8; c2++) {
            float t = __ldg(&cb[c2]);
#pragma unroll
            for (int c1 = 0; c1 < 16; c1++)
                t = fmaf(xin[c1], __ldg(&cw[c2 * 16 + c1]), t);
            t = fmaxf(t, 0.0f);
            s_xc[c2 * CS + po] = fmaf(__ldg(&g_sc[96 + c2]), t, __ldg(&g_sh[96 + c2]));
        }
    }
    __syncthreads();

    const int act = s_active;
    const int lane = tid & 31, wg = tid >> 5;
    const int prow = lane & 15, pcol = (lane >> 4) * 8;

    if (act) {
        {
            const int c2base = wg * 2;
            const int po = prow * RS + pcol;
            ull acc[2][4];
#pragma unroll
            for (int c2 = 0; c2 < 2; c2++) {
                ull bv = dup2(__ldg(&d1b[c2base + c2]));
                acc[c2][0] = bv; acc[c2][1] = bv; acc[c2][2] = bv; acc[c2][3] = bv;
            }
#pragma unroll
            for (int c1 = 0; c1 < 8; c1++) {
                const float* p = s_xc + c1 * CS + po;
                float4 a = *(const float4*)p;
                float4 b = *(const float4*)(p + 4);
                ull va0 = pack2(a.x, a.y), va1 = pack2(a.z, a.w);
                ull vb0 = pack2(b.x, b.y), vb1 = pack2(b.z, b.w);
#pragma unroll
                for (int c2 = 0; c2 < 2; c2++) {
                    ull w = dup2(__ldg(&d1w[(c2base + c2) * 8 + c1]));
                    fma2(acc[c2][0], w, va0);
                    fma2(acc[c2][1], w, va1);
                    fma2(acc[c2][2], w, vb0);
                    fma2(acc[c2][3], w, vb1);
                }
            }
#pragma unroll
            for (int c2 = 0; c2 < 2; c2++) {
                int c = c2base + c2;
                float sc = __ldg(&g_sc[104 + c]), sh = __ldg(&g_sh[104 + c]);
                float2 f0 = unpack2(acc[c2][0]), f1 = unpack2(acc[c2][1]);
                float2 f2 = unpack2(acc[c2][2]), f3 = unpack2(acc[c2][3]);
                float4 o0, o1;
                o0.x = fmaf(sc, fmaxf(f0.x, 0.f), sh); o0.y = fmaf(sc, fmaxf(f0.y, 0.f), sh);
                o0.z = fmaf(sc, fmaxf(f1.x, 0.f), sh); o0.w = fmaf(sc, fmaxf(f1.y, 0.f), sh);
                o1.x = fmaf(sc, fmaxf(f2.x, 0.f), sh); o1.y = fmaf(sc, fmaxf(f2.y, 0.f), sh);
                o1.z = fmaf(sc, fmaxf(f3.x, 0.f), sh); o1.w = fmaf(sc, fmaxf(f3.y, 0.f), sh);
                *(float4*)(s_a + c * CS + po)     = o0;
                *(float4*)(s_a + c * CS + po + 4) = o1;
            }
        }
        __syncthreads();

        {
            const int pairb = wg;
            ull acc[8];
            {
                int c2 = 2 * pairb;
                ull bv = pack2(__ldg(&d2b[c2]), __ldg(&d2b[c2 + 1]));
#pragma unroll
                for (int k = 0; k < 8; k++) acc[k] = bv;
            }
            const float* sap = s_a + pcol;
            const ull* __restrict__ wbase = (const ull*)g_q2p + pairb;
#pragma unroll 4
            for (int c1 = 0; c1 < 16; c1++) {
                const float* cbase = sap + c1 * CS;
#pragma unroll
                for (int r = 0; r < 3; r++) {
                    int yy = prow - 1 + r;
                    float u0, u9; float4 m1, m2;
                    if ((unsigned)yy < 16u) {
                        const float* rp = cbase + yy * RS;
                        m1 = *(const float4*)rp;
                        m2 = *(const float4*)(rp + 4);
                        u0 = pcol ? rp[-1] : 0.f;
                        u9 = pcol ? 0.f : rp[8];
                    } else {
                        m1 = make_float4(0.f, 0.f, 0.f, 0.f);
                        m2 = m1; u0 = 0.f; u9 = 0.f;
                    }
                    ull vd[10] = {dup2(u0), dup2(m1.x), dup2(m1.y), dup2(m1.z), dup2(m1.w),
                                  dup2(m2.x), dup2(m2.y), dup2(m2.z), dup2(m2.w), dup2(u9)};
                    const ull* wrow = wbase + (c1 * 9 + r * 3) * 8;
#pragma unroll
                    for (int dx = 0; dx < 3; dx++) {
                        ull w = __ldg(wrow + dx * 8);
#pragma unroll
                        for (int k = 0; k < 8; k++) fma2(acc[k], w, vd[dx + k]);
                    }
                }
            }
            const int poc = prow * 16 + pcol;
            {
                int c2 = 2 * pairb;
                float sa = __ldg(&g_sc[120 + c2]), ha = __ldg(&g_sh[120 + c2]);
                float sb2 = __ldg(&g_sc[120 + c2 + 1]), hb = __ldg(&g_sh[120 + c2 + 1]);
                float4 oa0, oa1, ob0, ob1;
                float2 f;
                f = unpack2(acc[0]); oa0.x = fmaf(sa, fmaxf(f.x,0.f), ha); ob0.x = fmaf(sb2, fmaxf(f.y,0.f), hb);
                f = unpack2(acc[1]); oa0.y = fmaf(sa, fmaxf(f.x,0.f), ha); ob0.y = fmaf(sb2, fmaxf(f.y,0.f), hb);
                f = unpack2(acc[2]); oa0.z = fmaf(sa, fmaxf(f.x,0.f), ha); ob0.z = fmaf(sb2, fmaxf(f.y,0.f), hb);
                f = unpack2(acc[3]); oa0.w = fmaf(sa, fmaxf(f.x,0.f), ha); ob0.w = fmaf(sb2, fmaxf(f.y,0.f), hb);
                f = unpack2(acc[4]); oa1.x = fmaf(sa, fmaxf(f.x,0.f), ha); ob1.x = fmaf(sb2, fmaxf(f.y,0.f), hb);
                f = unpack2(acc[5]); oa1.y = fmaf(sa, fmaxf(f.x,0.f), ha); ob1.y = fmaf(sb2, fmaxf(f.y,0.f), hb);
                f = unpack2(acc[6]); oa1.z = fmaf(sa, fmaxf(f.x,0.f), ha); ob1.z = fmaf(sb2, fmaxf(f.y,0.f), hb);
                f = unpack2(acc[7]); oa1.w = fmaf(sa, fmaxf(f.x,0.f), ha); ob1.w = fmaf(sb2, fmaxf(f.y,0.f), hb);
                *(float4*)(s_b + c2 * 256 + poc)           = oa0;
                *(float4*)(s_b + c2 * 256 + poc + 4)       = oa1;
                *(float4*)(s_b + (c2 + 1) * 256 + poc)     = ob0;
                *(float4*)(s_b + (c2 + 1) * 256 + poc + 4) = ob1;
            }
        }
        __syncthreads();

        {
            const int q = tid & 63;
            const int c2base = (tid >> 6) * 2;
            ull acc[2][2];
#pragma unroll
            for (int c2 = 0; c2 < 2; c2++) {
                ull bv = dup2(__ldg(&d3b[c2base + c2]));
                acc[c2][0] = bv; acc[c2][1] = bv;
            }
#pragma unroll
            for (int c1 = 0; c1 < 16; c1++) {
                float4 v = *(const float4*)(s_b + c1 * 256 + q * 4);
                ull v0 = pack2(v.x, v.y), v1 = pack2(v.z, v.w);
#pragma unroll
                for (int c2 = 0; c2 < 2; c2++) {
                    ull w = dup2(__ldg(&d3w[(c2base + c2) * 16 + c1]));
                    fma2(acc[c2][0], w, v0);
                    fma2(acc[c2][1], w, v1);
                }
            }
#pragma unroll
            for (int c2 = 0; c2 < 2; c2++) {
                int c = c2base + c2;
                float sc = __ldg(&g_sc[136 + c]), sh = __ldg(&g_sh[136 + c]);
                float2 f0 = unpack2(acc[c2][0]), f1 = unpack2(acc[c2][1]);
                float4 o;
                o.x = fmaf(sc, fmaxf(f0.x, 0.f), sh);
                o.y = fmaf(sc, fmaxf(f0.y, 0.f), sh);
                o.z = fmaf(sc, fmaxf(f1.x, 0.f), sh);
                o.w = fmaf(sc, fmaxf(f1.y, 0.f), sh);
                *(float4*)(s_f + c * 256 + q * 4) = o;
            }
        }
        __syncthreads();
    }

    const float* srcp = act ? s_f : s_xc;
    const int chs = act ? 256 : CS;
    const int rs = act ? 16 : RS;
#pragma unroll
    for (int k = 0; k < 2; k++) {
        int o = tid + k * 256;
        int c = o >> 6, q = o & 63;
        int qy = q >> 3, qx = q & 7;
        const float* sp = &srcp[c * chs + (qy * 2) * rs + qx * 2];
        float mo = fmaxf(fmaxf(sp[0], sp[1]), fmaxf(sp[rs], sp[rs + 1]));
        g_x2p[((n * 8 + c) * 128 + by * 8 + qy) * 128 + (bx * 8 + qx)] = mo;
    }
}

// ---------------------------------------------------------------------------
__global__ void __launch_bounds__(256) fc_partial_kernel(const float* __restrict__ fc_w)
{
    const int b = blockIdx.x;
    const int n = b >> 5, s = b & 31;
    const int tid = threadIdx.x;
    const float4* f = (const float4*)(g_x2p + n * 131072 + s * 4096);
    const float4* w = (const float4*)(fc_w) + s * 1024;

    float part[10];
#pragma unroll
    for (int k = 0; k < 10; k++) part[k] = 0.0f;

#pragma unroll
    for (int j = tid; j < 1024; j += 256) {
        float4 fv = f[j];
#pragma unroll
        for (int k = 0; k < 10; k++) {
            float4 wv = __ldg(&w[k * 32768 + j]);
            part[k] += fv.x * wv.x + fv.y * wv.y + fv.z * wv.z + fv.w * wv.w;
        }
    }

    __shared__ float sred[10][256];
#pragma unroll
    for (int k = 0; k < 10; k++) sred[k][tid] = part[k];
    __syncthreads();
    for (int st = 128; st > 0; st >>= 1) {
        if (tid < st) {
#pragma unroll
            for (int k = 0; k < 10; k++) sred[k][tid] += sred[k][tid + st];
        }
        __syncthreads();
    }
    if (tid < 10) g_fcpart[(n * 32 + s) * 10 + tid] = sred[tid][0];
}

__global__ void fc_final_kernel(const float* __restrict__ fc_b, float* __restrict__ out)
{
    const int t = threadIdx.x;
    __shared__ float s_l[16][10];
    if (t < 160) {
        int n = t / 10, k = t - n * 10;
        float a = fc_b[k];
#pragma unroll
        for (int s = 0; s < 32; s++) a += g_fcpart[(n * 32 + s) * 10 + k];
        s_l[n][k] = a;
    }
    __syncthreads();
    if (t < 16) {
        float mx = -1e30f;
#pragma unroll
        for (int k = 0; k < 10; k++) mx = fmaxf(mx, s_l[t][k]);
        float e[10], se = 0.f;
#pragma unroll
        for (int k = 0; k < 10; k++) { e[k] = expf(s_l[t][k] - mx); se += e[k]; }
        float inv = 1.0f / se;
#pragma unroll
        for (int k = 0; k < 10; k++) out[t * 10 + k] = e[k] * inv;
    }
}

// ---------------------------------------------------------------------------
extern "C" void kernel_launch(void* const* d_in, const int* in_sizes, int n_in,
                              void* d_out, int out_size)
{
    const float* x      = (const float*)d_in[0];
    const float* mask   = (const float*)d_in[1];
    const float* s1_cw  = (const float*)d_in[2];
    const float* s1_cb  = (const float*)d_in[3];
    const float* s1_bn0 = (const float*)d_in[4];
    const float* s1_d1w = (const float*)d_in[5];
    const float* s1_d1b = (const float*)d_in[6];
    const float* s1_bn1 = (const float*)d_in[7];
    const float* s1_d2w = (const float*)d_in[8];
    const float* s1_d2b = (const float*)d_in[9];
    const float* s1_bn2 = (const float*)d_in[10];
    const float* s1_d3w = (const float*)d_in[11];
    const float* s1_d3b = (const float*)d_in[12];
    const float* s1_bn3 = (const float*)d_in[13];
    const float* s2_cw  = (const float*)d_in[14];
    const float* s2_cb  = (const float*)d_in[15];
    const float* s2_bn0 = (const float*)d_in[16];
    const float* s2_d1w = (const float*)d_in[17];
    const float* s2_d1b = (const float*)d_in[18];
    const float* s2_bn1 = (const float*)d_in[19];
    const float* s2_d2w = (const float*)d_in[20];
    const float* s2_d2b = (const float*)d_in[21];
    const float* s2_bn2 = (const float*)d_in[22];
    const float* s2_d3w = (const float*)d_in[23];
    const float* s2_d3b = (const float*)d_in[24];
    const float* s2_bn3 = (const float*)d_in[25];
    const float* fc_w   = (const float*)d_in[26];
    const float* fc_b   = (const float*)d_in[27];

    prep_kernel<<<1, 256>>>(s1_d2w, s2_d2w,
                            s1_bn0, s1_bn1, s1_bn2, s1_bn3,
                            s2_bn0, s2_bn1, s2_bn2, s2_bn3);

    stage1_all_kernel<<<16 * 32 * 32, 256>>>(x, mask, s1_cw, s1_cb);

    const int smem1 = 19848 * sizeof(float);   // ~77.5 KB dynamic
    cudaFuncSetAttribute(stage1_active_kernel, cudaFuncAttributeMaxDynamicSharedMemorySize, smem1);
    stage1_active_kernel<<<16 * 32 * 32, 256, smem1>>>(
        x, s1_cw, s1_cb, s1_d1w, s1_d1b, s1_d2b, s1_d3w, s1_d3b);

    const int smem2 = 9216 * sizeof(float);
    cudaFuncSetAttribute(stage2_kernel, cudaFuncAttributeMaxDynamicSharedMemorySize, smem2);
    stage2_kernel<<<16 * 16 * 16, 256, smem2>>>(
        s2_cw, s2_cb, s2_d1w, s2_d1b, s2_d2b, s2_d3w, s2_d3b);

    fc_partial_kernel<<<512, 256>>>(fc_w);
    fc_final_kernel<<<1, 256>>>(fc_b, (float*)d_out);
}

// round 9
// speedup vs baseline: 1.2080x; 1.0398x over previous
#include <cuda_runtime.h>

#define EPSV 1e-5f
typedef unsigned long long ull;
typedef unsigned int uint;

__device__ float g_x1p[16 * 16 * 256 * 256];
__device__ float g_mask2[16 * 256 * 256];
__device__ float g_x2p[16 * 8 * 128 * 128];
__device__ float g_fcpart[16 * 32 * 10];
__device__ int   g_cnt1;
__device__ int   g_list1[16384];

__device__ __align__(16) float g_bhi[9216];    // stage1 d2 tf32-hi fragments
__device__ __align__(16) float g_blo[9216];    // stage1 d2 tf32-lo fragments
__device__ __align__(16) float g_qhi[2304];    // stage2 d2 tf32-hi fragments
__device__ __align__(16) float g_qlo[2304];    // stage2 d2 tf32-lo fragments
__device__ float g_sc[144], g_sh[144];

__device__ __forceinline__ void fma2(ull& d, ull a, ull b) {
    asm("fma.rn.f32x2 %0, %1, %2, %0;" : "+l"(d) : "l"(a), "l"(b));
}
__device__ __forceinline__ ull pack2(float lo, float hi) {
    ull r; asm("mov.b64 %0, {%1, %2};" : "=l"(r) : "f"(lo), "f"(hi)); return r;
}
__device__ __forceinline__ ull dup2(float v) { return pack2(v, v); }
__device__ __forceinline__ float2 unpack2(ull u) {
    float2 f; asm("mov.b64 {%0, %1}, %2;" : "=f"(f.x), "=f"(f.y) : "l"(u)); return f;
}
__device__ __forceinline__ uint tf32_rna(float v) {
    uint r; asm("cvt.rna.tf32.f32 %0, %1;" : "=r"(r) : "f"(v)); return r;
}
__device__ __forceinline__ void mma8(float* a, const uint* A, uint b0, uint b1) {
    asm volatile("mma.sync.aligned.m16n8k8.row.col.f32.tf32.tf32.f32 "
        "{%0,%1,%2,%3},{%4,%5,%6,%7},{%8,%9},{%0,%1,%2,%3};"
        : "+f"(a[0]), "+f"(a[1]), "+f"(a[2]), "+f"(a[3])
        : "r"(A[0]), "r"(A[1]), "r"(A[2]), "r"(A[3]), "r"(b0), "r"(b1));
}

#define RS 20
#define CS 320

// ---------------------------------------------------------------------------
__global__ void prep_kernel(
    const float* __restrict__ s1d2w, const float* __restrict__ s2d2w,
    const float* __restrict__ b10, const float* __restrict__ b11,
    const float* __restrict__ b12, const float* __restrict__ b13,
    const float* __restrict__ b20, const float* __restrict__ b21,
    const float* __restrict__ b22, const float* __restrict__ b23)
{
    const int tid = threadIdx.x;
    if (tid == 0) g_cnt1 = 0;
    // stage1 d2 fragments (K = tap*32 + c1)
    for (int i = tid; i < 9216; i += 256) {
        int kstep = i >> 8, r = i & 255;
        int ln = r >> 3, jj = r & 7;
        int kk = kstep * 8 + (ln & 3) + (jj & 1) * 4;
        int c2 = (jj >> 1) * 8 + (ln >> 2);
        int tap = kk >> 5, c1 = kk & 31;
        float wv = s1d2w[(c2 * 32 + c1) * 9 + tap];
        uint hu = tf32_rna(wv);
        g_bhi[i] = __uint_as_float(hu);
        g_blo[i] = __uint_as_float(tf32_rna(wv - __uint_as_float(hu)));
    }
    // stage2 d2 fragments (K = tap*16 + c1)
    for (int i = tid; i < 2304; i += 256) {
        int kstep = i >> 7, r = i & 127;
        int ln = r >> 2, jj = r & 3;
        int kk = kstep * 8 + (ln & 3) + (jj & 1) * 4;
        int c2 = (jj >> 1) * 8 + (ln >> 2);
        int tap = kk >> 4, c1 = kk & 15;
        float wv = s2d2w[(c2 * 16 + c1) * 9 + tap];
        uint hu = tf32_rna(wv);
        g_qhi[i] = __uint_as_float(hu);
        g_qlo[i] = __uint_as_float(tf32_rna(wv - __uint_as_float(hu)));
    }
    if (tid < 144) {
        const float* bp; int c, C;
        if      (tid < 16)  { bp = b10; c = tid;       C = 16; }
        else if (tid < 48)  { bp = b11; c = tid - 16;  C = 32; }
        else if (tid < 80)  { bp = b12; c = tid - 48;  C = 32; }
        else if (tid < 96)  { bp = b13; c = tid - 80;  C = 16; }
        else if (tid < 104) { bp = b20; c = tid - 96;  C = 8;  }
        else if (tid < 120) { bp = b21; c = tid - 104; C = 16; }
        else if (tid < 136) { bp = b22; c = tid - 120; C = 16; }
        else                { bp = b23; c = tid - 136; C = 8;  }
        float g = bp[c], b = bp[C + c], m = bp[2 * C + c], v = bp[3 * C + c];
        float s = g * rsqrtf(v + EPSV);
        g_sc[tid] = s; g_sh[tid] = b - s * m;
    }
}

// ---------------------------------------------------------------------------
__global__ void __launch_bounds__(256) stage1_all_kernel(
    const float* __restrict__ x, const float* __restrict__ mask,
    const float* __restrict__ cw, const float* __restrict__ cb)
{
    __shared__ float s_red[256];
    __shared__ float s_wsum[8];
    __shared__ float s_xc[16 * CS];
    __shared__ int s_active;

    const int bid = blockIdx.x;
    const int n = bid >> 10, by = (bid >> 5) & 31, bx = bid & 31;
    const int tid = threadIdx.x;
    const int py = tid >> 4, px_ = tid & 15;
    const int gy = by * 16 + py, gx = bx * 16 + px_;

    float mval = mask[(n * 512 + gy) * 512 + gx];
    s_red[tid] = mval;
    float msum = mval;
#pragma unroll
    for (int o = 16; o; o >>= 1) msum += __shfl_xor_sync(0xffffffffu, msum, o);
    if ((tid & 31) == 0) s_wsum[tid >> 5] = msum;
    __syncthreads();

    if (tid < 64) {
        int qy = tid >> 3, qx = tid & 7;
        int p0 = (qy * 2) * 16 + qx * 2;
        float m0 = fmaxf(fmaxf(s_red[p0], s_red[p0 + 1]),
                         fmaxf(s_red[p0 + 16], s_red[p0 + 17]));
        g_mask2[(n * 256 + by * 8 + qy) * 256 + (bx * 8 + qx)] = m0;
    }
    if (tid == 0) {
        float t = 0.f;
#pragma unroll
        for (int i = 0; i < 8; i++) t += s_wsum[i];
        int act = (t > 128.0f) ? 1 : 0;
        s_active = act;
        if (act) { int pos = atomicAdd(&g_cnt1, 1); g_list1[pos] = bid; }
    }
    __syncthreads();
    if (s_active) return;

    {
        const int ibase = ((n * 3) * 512 + gy) * 512 + gx;
        float xv0 = x[ibase];
        float xv1 = x[ibase + 512 * 512];
        float xv2 = x[ibase + 2 * 512 * 512];
        const int po = py * RS + px_;
#pragma unroll
        for (int c = 0; c < 16; c++) {
            float t = __ldg(&cw[c * 3 + 0]) * xv0 + __ldg(&cw[c * 3 + 1]) * xv1 +
                      __ldg(&cw[c * 3 + 2]) * xv2 + __ldg(&cb[c]);
            t = fmaxf(t, 0.0f);
            s_xc[c * CS + po] = fmaf(__ldg(&g_sc[c]), t, __ldg(&g_sh[c]));
        }
    }
    __syncthreads();

#pragma unroll
    for (int k = 0; k < 4; k++) {
        int o = tid + k * 256;
        int c = o >> 6, q = o & 63;
        int qy = q >> 3, qx = q & 7;
        const float* sp = &s_xc[c * CS + (qy * 2) * RS + qx * 2];
        float mo = fmaxf(fmaxf(sp[0], sp[1]), fmaxf(sp[RS], sp[RS + 1]));
        g_x1p[((n * 16 + c) * 256 + by * 8 + qy) * 256 + (bx * 8 + qx)] = mo;
    }
}

// ---------------------------------------------------------------------------
// Stage 1b (active): identical to round 8 (tf32 mma d2)
// ---------------------------------------------------------------------------
__global__ void __launch_bounds__(256, 2) stage1_active_kernel(
    const float* __restrict__ x,
    const float* __restrict__ cw, const float* __restrict__ cb,
    const float* __restrict__ d1w, const float* __restrict__ d1b,
    const float* __restrict__ d2b,
    const float* __restrict__ d3w, const float* __restrict__ d3b)
{
    if ((int)blockIdx.x >= g_cnt1) return;
    const int bid = g_list1[blockIdx.x];

    extern __shared__ float sm[];
    float* s_halo = sm + 4;
    float* s_f    = sm;
    float* s_b    = sm + 11528;   // stride 260
    float* s_xc   = s_b;          // [16][CS]

    const int n = bid >> 10, by = (bid >> 5) & 31, bx = bid & 31;
    const int tid = threadIdx.x;
    const int py = tid >> 4, px_ = tid & 15;
    const int gy = by * 16 + py, gx = bx * 16 + px_;

    {
        float4 z4 = make_float4(0.f, 0.f, 0.f, 0.f);
        for (int i = tid; i < 2882; i += 256) ((float4*)sm)[i] = z4;
    }
    {
        const int ibase = ((n * 3) * 512 + gy) * 512 + gx;
        float xv0 = x[ibase];
        float xv1 = x[ibase + 512 * 512];
        float xv2 = x[ibase + 2 * 512 * 512];
        const int po = py * RS + px_;
#pragma unroll
        for (int c = 0; c < 16; c++) {
            float t = __ldg(&cw[c * 3 + 0]) * xv0 + __ldg(&cw[c * 3 + 1]) * xv1 +
                      __ldg(&cw[c * 3 + 2]) * xv2 + __ldg(&cb[c]);
            t = fmaxf(t, 0.0f);
            s_xc[c * CS + po] = fmaf(__ldg(&g_sc[c]), t, __ldg(&g_sh[c]));
        }
    }
    __syncthreads();

    const int lane = tid & 31, wg = tid >> 5;
    const int prow = lane & 15, pcol = (lane >> 4) * 8;

    // d1: 16 -> 32 into halo
    {
        const int c2base = wg * 4;
        ull acc[4][4];
#pragma unroll
        for (int c2 = 0; c2 < 4; c2++) {
            ull bv = dup2(__ldg(&d1b[c2base + c2]));
            acc[c2][0] = bv; acc[c2][1] = bv; acc[c2][2] = bv; acc[c2][3] = bv;
        }
        const int po = prow * RS + pcol;
#pragma unroll
        for (int c1 = 0; c1 < 16; c1++) {
            const float* p = s_xc + c1 * CS + po;
            float4 a = *(const float4*)p;
            float4 b = *(const float4*)(p + 4);
            ull va0 = pack2(a.x, a.y), va1 = pack2(a.z, a.w);
            ull vb0 = pack2(b.x, b.y), vb1 = pack2(b.z, b.w);
#pragma unroll
            for (int c2 = 0; c2 < 4; c2++) {
                ull w = dup2(__ldg(&d1w[(c2base + c2) * 16 + c1]));
                fma2(acc[c2][0], w, va0);
                fma2(acc[c2][1], w, va1);
                fma2(acc[c2][2], w, vb0);
                fma2(acc[c2][3], w, vb1);
            }
        }
        const int ho = (prow + 1) * 20 + pcol;
#pragma unroll
        for (int c2 = 0; c2 < 4; c2++) {
            int c = c2base + c2;
            float sc = __ldg(&g_sc[16 + c]), sh = __ldg(&g_sh[16 + c]);
            float4 o0, o1;
            float2 f0 = unpack2(acc[c2][0]), f1 = unpack2(acc[c2][1]);
            float2 f2 = unpack2(acc[c2][2]), f3 = unpack2(acc[c2][3]);
            o0.x = fmaf(sc, fmaxf(f0.x, 0.f), sh); o0.y = fmaf(sc, fmaxf(f0.y, 0.f), sh);
            o0.z = fmaf(sc, fmaxf(f1.x, 0.f), sh); o0.w = fmaf(sc, fmaxf(f1.y, 0.f), sh);
            o1.x = fmaf(sc, fmaxf(f2.x, 0.f), sh); o1.y = fmaf(sc, fmaxf(f2.y, 0.f), sh);
            o1.z = fmaf(sc, fmaxf(f3.x, 0.f), sh); o1.w = fmaf(sc, fmaxf(f3.y, 0.f), sh);
            *(float4*)(s_halo + c * 360 + ho)     = o0;
            *(float4*)(s_halo + c * 360 + ho + 4) = o1;
        }
    }
    __syncthreads();

    // d2: tf32 mma 3-term
    {
        const int tg = lane & 3, q = lane >> 2;
        float acc[8][4];
#pragma unroll
        for (int i = 0; i < 8; i++) {
            int c2 = (i & 3) * 8 + tg * 2;
            float b0 = __ldg(&d2b[c2]), b1 = __ldg(&d2b[c2 + 1]);
            acc[i][0] = b0; acc[i][1] = b1; acc[i][2] = b0; acc[i][3] = b1;
        }
        const float* hp0 = s_halo + tg * 360 + wg * 20 + q - 1;
        const uint4* bh = (const uint4*)g_bhi + lane * 2;
        const uint4* bl = (const uint4*)g_blo + lane * 2;
#pragma unroll 1
        for (int tap = 0; tap < 9; tap++) {
            int dyq = (tap * 11) >> 5;
            const float* hp = hp0 + tap + 17 * dyq;
#pragma unroll
            for (int kl = 0; kl < 4; kl++) {
                float av[8];
                av[0] = hp[0];    av[1] = hp[8];    av[2] = hp[1440]; av[3] = hp[1448];
                av[4] = hp[160];  av[5] = hp[168];  av[6] = hp[1600]; av[7] = hp[1608];
                hp += 2880;
                uint Ah[8], Al[8];
#pragma unroll
                for (int i = 0; i < 8; i++) {
                    Ah[i] = tf32_rna(av[i]);
                    Al[i] = tf32_rna(av[i] - __uint_as_float(Ah[i]));
                }
                uint4 H0 = __ldg(bh), H1 = __ldg(bh + 1);
                uint4 L0 = __ldg(bl), L1 = __ldg(bl + 1);
                bh += 64; bl += 64;
                uint BH[8] = {H0.x, H0.y, H0.z, H0.w, H1.x, H1.y, H1.z, H1.w};
                uint BL[8] = {L0.x, L0.y, L0.z, L0.w, L1.x, L1.y, L1.z, L1.w};
#pragma unroll
                for (int nt = 0; nt < 4; nt++) {
                    mma8(acc[nt],     Ah,     BH[2*nt], BH[2*nt+1]);
                    mma8(acc[nt],     Ah,     BL[2*nt], BL[2*nt+1]);
                    mma8(acc[nt],     Al,     BH[2*nt], BH[2*nt+1]);
                    mma8(acc[nt + 4], Ah + 4, BH[2*nt], BH[2*nt+1]);
                    mma8(acc[nt + 4], Ah + 4, BL[2*nt], BL[2*nt+1]);
                    mma8(acc[nt + 4], Al + 4, BH[2*nt], BH[2*nt+1]);
                }
            }
        }
#pragma unroll
        for (int i = 0; i < 8; i++) {
            int mt = i >> 2, nt = i & 3;
            int c2 = nt * 8 + tg * 2;
            float s0 = __ldg(&g_sc[48 + c2]), h0 = __ldg(&g_sh[48 + c2]);
            float s1 = __ldg(&g_sc[49 + c2]), h1 = __ldg(&g_sh[49 + c2]);
            float* o = s_b + c2 * 260 + (wg + mt * 8) * 16 + q;
            o[0]   = fmaf(s0, fmaxf(acc[i][0], 0.f), h0);
            o[260] = fmaf(s1, fmaxf(acc[i][1], 0.f), h1);
            o[8]   = fmaf(s0, fmaxf(acc[i][2], 0.f), h0);
            o[268] = fmaf(s1, fmaxf(acc[i][3], 0.f), h1);
        }
    }
    __syncthreads();

    // d3: 32 -> 16
    {
        const int q = tid & 63;
        const int c2base = (tid >> 6) * 4;
        ull acc[4][2];
#pragma unroll
        for (int c2 = 0; c2 < 4; c2++) {
            ull bv = dup2(__ldg(&d3b[c2base + c2]));
            acc[c2][0] = bv; acc[c2][1] = bv;
        }
#pragma unroll 4
        for (int c1 = 0; c1 < 32; c1++) {
            float4 v = *(const float4*)(s_b + c1 * 260 + q * 4);
            ull v0 = pack2(v.x, v.y), v1 = pack2(v.z, v.w);
#pragma unroll
            for (int c2 = 0; c2 < 4; c2++) {
                ull w = dup2(__ldg(&d3w[(c2base + c2) * 32 + c1]));
                fma2(acc[c2][0], w, v0);
                fma2(acc[c2][1], w, v1);
            }
        }
#pragma unroll
        for (int c2 = 0; c2 < 4; c2++) {
            int c = c2base + c2;
            float sc = __ldg(&g_sc[80 + c]), sh = __ldg(&g_sh[80 + c]);
            float2 f0 = unpack2(acc[c2][0]), f1 = unpack2(acc[c2][1]);
            float4 o;
            o.x = fmaf(sc, fmaxf(f0.x, 0.f), sh);
            o.y = fmaf(sc, fmaxf(f0.y, 0.f), sh);
            o.z = fmaf(sc, fmaxf(f1.x, 0.f), sh);
            o.w = fmaf(sc, fmaxf(f1.y, 0.f), sh);
            *(float4*)(s_f + c * 256 + q * 4) = o;
        }
    }
    __syncthreads();

#pragma unroll
    for (int k = 0; k < 4; k++) {
        int o = tid + k * 256;
        int c = o >> 6, q = o & 63;
        int qy = q >> 3, qx = q & 7;
        const float* sp = &s_f[c * 256 + (qy * 2) * 16 + qx * 2];
        float mo = fmaxf(fmaxf(sp[0], sp[1]), fmaxf(sp[16], sp[17]));
        g_x1p[((n * 16 + c) * 256 + by * 8 + qy) * 256 + (bx * 8 + qx)] = mo;
    }
}

// ---------------------------------------------------------------------------
// Stage 2: now also tf32 mma d2.
// SMEM: [0..4) guard, s_halo=sm2+4 [16][360], s_b=sm2+5764 [16][260]
// (s_xc [8][CS] aliases s_b; s_f [8][256] aliases halo)
// ---------------------------------------------------------------------------
__global__ void __launch_bounds__(256, 3) stage2_kernel(
    const float* __restrict__ cw, const float* __restrict__ cb,
    const float* __restrict__ d1w, const float* __restrict__ d1b,
    const float* __restrict__ d2b,
    const float* __restrict__ d3w, const float* __restrict__ d3b)
{
    extern __shared__ float sm2[];
    float* s_halo = sm2 + 4;
    float* s_f    = sm2;
    float* s_b    = sm2 + 5764;   // stride 260
    float* s_xc   = s_b;          // [8][CS]

    __shared__ float s_wsum[8];
    __shared__ int s_active;

    const int bid = blockIdx.x;
    const int n = bid >> 8, by = (bid >> 4) & 15, bx = bid & 15;
    const int tid = threadIdx.x;
    const int py = tid >> 4, px_ = tid & 15;
    const int gy = by * 16 + py, gx = bx * 16 + px_;

    {
        float mv = g_mask2[(n * 256 + gy) * 256 + gx];
#pragma unroll
        for (int o = 16; o; o >>= 1) mv += __shfl_xor_sync(0xffffffffu, mv, o);
        if ((tid & 31) == 0) s_wsum[tid >> 5] = mv;
    }
    // zero guard + halo
    {
        float4 z4 = make_float4(0.f, 0.f, 0.f, 0.f);
        for (int i = tid; i < 1441; i += 256) ((float4*)sm2)[i] = z4;
    }
    __syncthreads();
    if (tid == 0) {
        float t = 0.f;
#pragma unroll
        for (int i = 0; i < 8; i++) t += s_wsum[i];
        s_active = (t > 128.0f) ? 1 : 0;
    }

    // channel path -> s_xc (padded, disjoint from halo)
    {
        const int ibase = ((n * 16) * 256 + gy) * 256 + gx;
        float xin[16];
#pragma unroll
        for (int c = 0; c < 16; c++) xin[c] = g_x1p[ibase + c * 65536];
        const int po = py * RS + px_;
#pragma unroll
        for (int c2 = 0; c2 < 8; c2++) {
            float t = __ldg(&cb[c2]);
#pragma unroll
            for (int c1 = 0; c1 < 16; c1++)
                t = fmaf(xin[c1], __ldg(&cw[c2 * 16 + c1]), t);
            t = fmaxf(t, 0.0f);
            s_xc[c2 * CS + po] = fmaf(__ldg(&g_sc[96 + c2]), t, __ldg(&g_sh[96 + c2]));
        }
    }
    __syncthreads();

    const int act = s_active;
    const int lane = tid & 31, wg = tid >> 5;
    const int prow = lane & 15, pcol = (lane >> 4) * 8;

    if (act) {
        // d1: 8 -> 16 into halo
        {
            const int c2base = wg * 2;
            const int po = prow * RS + pcol;
            ull acc[2][4];
#pragma unroll
            for (int c2 = 0; c2 < 2; c2++) {
                ull bv = dup2(__ldg(&d1b[c2base + c2]));
                acc[c2][0] = bv; acc[c2][1] = bv; acc[c2][2] = bv; acc[c2][3] = bv;
            }
#pragma unroll
            for (int c1 = 0; c1 < 8; c1++) {
                const float* p = s_xc + c1 * CS + po;
                float4 a = *(const float4*)p;
                float4 b = *(const float4*)(p + 4);
                ull va0 = pack2(a.x, a.y), va1 = pack2(a.z, a.w);
                ull vb0 = pack2(b.x, b.y), vb1 = pack2(b.z, b.w);
#pragma unroll
                for (int c2 = 0; c2 < 2; c2++) {
                    ull w = dup2(__ldg(&d1w[(c2base + c2) * 8 + c1]));
                    fma2(acc[c2][0], w, va0);
                    fma2(acc[c2][1], w, va1);
                    fma2(acc[c2][2], w, vb0);
                    fma2(acc[c2][3], w, vb1);
                }
            }
            const int ho = (prow + 1) * 20 + pcol;
#pragma unroll
            for (int c2 = 0; c2 < 2; c2++) {
                int c = c2base + c2;
                float sc = __ldg(&g_sc[104 + c]), sh = __ldg(&g_sh[104 + c]);
                float2 f0 = unpack2(acc[c2][0]), f1 = unpack2(acc[c2][1]);
                float2 f2 = unpack2(acc[c2][2]), f3 = unpack2(acc[c2][3]);
                float4 o0, o1;
                o0.x = fmaf(sc, fmaxf(f0.x, 0.f), sh); o0.y = fmaf(sc, fmaxf(f0.y, 0.f), sh);
                o0.z = fmaf(sc, fmaxf(f1.x, 0.f), sh); o0.w = fmaf(sc, fmaxf(f1.y, 0.f), sh);
                o1.x = fmaf(sc, fmaxf(f2.x, 0.f), sh); o1.y = fmaf(sc, fmaxf(f2.y, 0.f), sh);
                o1.z = fmaf(sc, fmaxf(f3.x, 0.f), sh); o1.w = fmaf(sc, fmaxf(f3.y, 0.f), sh);
                *(float4*)(s_halo + c * 360 + ho)     = o0;
                *(float4*)(s_halo + c * 360 + ho + 4) = o1;
            }
        }
        __syncthreads();

        // d2: 3x3, 16 -> 16 via tf32 mma (3-term)
        {
            const int tg = lane & 3, q = lane >> 2;
            float acc[4][4];
#pragma unroll
            for (int i = 0; i < 4; i++) {
                int c2 = (i & 1) * 8 + tg * 2;
                float b0 = __ldg(&d2b[c2]), b1 = __ldg(&d2b[c2 + 1]);
                acc[i][0] = b0; acc[i][1] = b1; acc[i][2] = b0; acc[i][3] = b1;
            }
            const float* hp0 = s_halo + tg * 360 + wg * 20 + q - 1;
            const uint4* bh = (const uint4*)g_qhi + lane;
            const uint4* bl = (const uint4*)g_qlo + lane;
#pragma unroll 1
            for (int tap = 0; tap < 9; tap++) {
                int dyq = (tap * 11) >> 5;
                const float* hp = hp0 + tap + 17 * dyq;
#pragma unroll
                for (int kl = 0; kl < 2; kl++) {
                    float av[8];
                    av[0] = hp[0];    av[1] = hp[8];    av[2] = hp[1440]; av[3] = hp[1448];
                    av[4] = hp[160];  av[5] = hp[168];  av[6] = hp[1600]; av[7] = hp[1608];
                    hp += 2880;
                    uint Ah[8], Al[8];
#pragma unroll
                    for (int i = 0; i < 8; i++) {
                        Ah[i] = tf32_rna(av[i]);
                        Al[i] = tf32_rna(av[i] - __uint_as_float(Ah[i]));
                    }
                    uint4 H = __ldg(bh), L = __ldg(bl);
                    bh += 32; bl += 32;
                    mma8(acc[0], Ah,     H.x, H.y);
                    mma8(acc[0], Ah,     L.x, L.y);
                    mma8(acc[0], Al,     H.x, H.y);
                    mma8(acc[1], Ah,     H.z, H.w);
                    mma8(acc[1], Ah,     L.z, L.w);
                    mma8(acc[1], Al,     H.z, H.w);
                    mma8(acc[2], Ah + 4, H.x, H.y);
                    mma8(acc[2], Ah + 4, L.x, L.y);
                    mma8(acc[2], Al + 4, H.x, H.y);
                    mma8(acc[3], Ah + 4, H.z, H.w);
                    mma8(acc[3], Ah + 4, L.z, L.w);
                    mma8(acc[3], Al + 4, H.z, H.w);
                }
            }
#pragma unroll
            for (int i = 0; i < 4; i++) {
                int mt = i >> 1, nt = i & 1;
                int c2 = nt * 8 + tg * 2;
                float s0 = __ldg(&g_sc[120 + c2]), h0 = __ldg(&g_sh[120 + c2]);
                float s1 = __ldg(&g_sc[121 + c2]), h1 = __ldg(&g_sh[121 + c2]);
                float* o = s_b + c2 * 260 + (wg + mt * 8) * 16 + q;
                o[0]   = fmaf(s0, fmaxf(acc[i][0], 0.f), h0);
                o[260] = fmaf(s1, fmaxf(acc[i][1], 0.f), h1);
                o[8]   = fmaf(s0, fmaxf(acc[i][2], 0.f), h0);
                o[268] = fmaf(s1, fmaxf(acc[i][3], 0.f), h1);
            }
        }
        __syncthreads();

        // d3: 16 -> 8
        {
            const int q = tid & 63;
            const int c2base = (tid >> 6) * 2;
            ull acc[2][2];
#pragma unroll
            for (int c2 = 0; c2 < 2; c2++) {
                ull bv = dup2(__ldg(&d3b[c2base + c2]));
                acc[c2][0] = bv; acc[c2][1] = bv;
            }
#pragma unroll
            for (int c1 = 0; c1 < 16; c1++) {
                float4 v = *(const float4*)(s_b + c1 * 260 + q * 4);
                ull v0 = pack2(v.x, v.y), v1 = pack2(v.z, v.w);
#pragma unroll
                for (int c2 = 0; c2 < 2; c2++) {
                    ull w = dup2(__ldg(&d3w[(c2base + c2) * 16 + c1]));
                    fma2(acc[c2][0], w, v0);
                    fma2(acc[c2][1], w, v1);
                }
            }
#pragma unroll
            for (int c2 = 0; c2 < 2; c2++) {
                int c = c2base + c2;
                float sc = __ldg(&g_sc[136 + c]), sh = __ldg(&g_sh[136 + c]);
                float2 f0 = unpack2(acc[c2][0]), f1 = unpack2(acc[c2][1]);
                float4 o;
                o.x = fmaf(sc, fmaxf(f0.x, 0.f), sh);
                o.y = fmaf(sc, fmaxf(f0.y, 0.f), sh);
                o.z = fmaf(sc, fmaxf(f1.x, 0.f), sh);
                o.w = fmaf(sc, fmaxf(f1.y, 0.f), sh);
                *(float4*)(s_f + c * 256 + q * 4) = o;
            }
        }
        __syncthreads();
    }

    const float* srcp = act ? s_f : s_xc;
    const int chs = act ? 256 : CS;
    const int rs = act ? 16 : RS;
#pragma unroll
    for (int k = 0; k < 2; k++) {
        int o = tid + k * 256;
        int c = o >> 6, q = o & 63;
        int qy = q >> 3, qx = q & 7;
        const float* sp = &srcp[c * chs + (qy * 2) * rs + qx * 2];
        float mo = fmaxf(fmaxf(sp[0], sp[1]), fmaxf(sp[rs], sp[rs + 1]));
        g_x2p[((n * 8 + c) * 128 + by * 8 + qy) * 128 + (bx * 8 + qx)] = mo;
    }
}

// ---------------------------------------------------------------------------
__global__ void __launch_bounds__(256) fc_partial_kernel(const float* __restrict__ fc_w)
{
    const int b = blockIdx.x;
    const int n = b >> 5, s = b & 31;
    const int tid = threadIdx.x;
    const float4* f = (const float4*)(g_x2p + n * 131072 + s * 4096);
    const float4* w = (const float4*)(fc_w) + s * 1024;

    float part[10];
#pragma unroll
    for (int k = 0; k < 10; k++) part[k] = 0.0f;

#pragma unroll
    for (int j = tid; j < 1024; j += 256) {
        float4 fv = f[j];
#pragma unroll
        for (int k = 0; k < 10; k++) {
            float4 wv = __ldg(&w[k * 32768 + j]);
            part[k] += fv.x * wv.x + fv.y * wv.y + fv.z * wv.z + fv.w * wv.w;
        }
    }

    __shared__ float sred[10][256];
#pragma unroll
    for (int k = 0; k < 10; k++) sred[k][tid] = part[k];
    __syncthreads();
    for (int st = 128; st > 0; st >>= 1) {
        if (tid < st) {
#pragma unroll
            for (int k = 0; k < 10; k++) sred[k][tid] += sred[k][tid + st];
        }
        __syncthreads();
    }
    if (tid < 10) g_fcpart[(n * 32 + s) * 10 + tid] = sred[tid][0];
}

__global__ void fc_final_kernel(const float* __restrict__ fc_b, float* __restrict__ out)
{
    const int t = threadIdx.x;
    __shared__ float s_l[16][10];
    if (t < 160) {
        int n = t / 10, k = t - n * 10;
        float a = fc_b[k];
#pragma unroll
        for (int s = 0; s < 32; s++) a += g_fcpart[(n * 32 + s) * 10 + k];
        s_l[n][k] = a;
    }
    __syncthreads();
    if (t < 16) {
        float mx = -1e30f;
#pragma unroll
        for (int k = 0; k < 10; k++) mx = fmaxf(mx, s_l[t][k]);
        float e[10], se = 0.f;
#pragma unroll
        for (int k = 0; k < 10; k++) { e[k] = expf(s_l[t][k] - mx); se += e[k]; }
        float inv = 1.0f / se;
#pragma unroll
        for (int k = 0; k < 10; k++) out[t * 10 + k] = e[k] * inv;
    }
}

// ---------------------------------------------------------------------------
extern "C" void kernel_launch(void* const* d_in, const int* in_sizes, int n_in,
                              void* d_out, int out_size)
{
    const float* x      = (const float*)d_in[0];
    const float* mask   = (const float*)d_in[1];
    const float* s1_cw  = (const float*)d_in[2];
    const float* s1_cb  = (const float*)d_in[3];
    const float* s1_bn0 = (const float*)d_in[4];
    const float* s1_d1w = (const float*)d_in[5];
    const float* s1_d1b = (const float*)d_in[6];
    const float* s1_bn1 = (const float*)d_in[7];
    const float* s1_d2w = (const float*)d_in[8];
    const float* s1_d2b = (const float*)d_in[9];
    const float* s1_bn2 = (const float*)d_in[10];
    const float* s1_d3w = (const float*)d_in[11];
    const float* s1_d3b = (const float*)d_in[12];
    const float* s1_bn3 = (const float*)d_in[13];
    const float* s2_cw  = (const float*)d_in[14];
    const float* s2_cb  = (const float*)d_in[15];
    const float* s2_bn0 = (const float*)d_in[16];
    const float* s2_d1w = (const float*)d_in[17];
    const float* s2_d1b = (const float*)d_in[18];
    const float* s2_bn1 = (const float*)d_in[19];
    const float* s2_d2w = (const float*)d_in[20];
    const float* s2_d2b = (const float*)d_in[21];
    const float* s2_bn2 = (const float*)d_in[22];
    const float* s2_d3w = (const float*)d_in[23];
    const float* s2_d3b = (const float*)d_in[24];
    const float* s2_bn3 = (const float*)d_in[25];
    const float* fc_w   = (const float*)d_in[26];
    const float* fc_b   = (const float*)d_in[27];

    prep_kernel<<<1, 256>>>(s1_d2w, s2_d2w,
                            s1_bn0, s1_bn1, s1_bn2, s1_bn3,
                            s2_bn0, s2_bn1, s2_bn2, s2_bn3);

    stage1_all_kernel<<<16 * 32 * 32, 256>>>(x, mask, s1_cw, s1_cb);

    const int smem1 = 19848 * sizeof(float);
    cudaFuncSetAttribute(stage1_active_kernel, cudaFuncAttributeMaxDynamicSharedMemorySize, smem1);
    stage1_active_kernel<<<16 * 32 * 32, 256, smem1>>>(
        x, s1_cw, s1_cb, s1_d1w, s1_d1b, s1_d2b, s1_d3w, s1_d3b);

    const int smem2 = 9924 * sizeof(float);
    cudaFuncSetAttribute(stage2_kernel, cudaFuncAttributeMaxDynamicSharedMemorySize, smem2);
    stage2_kernel<<<16 * 16 * 16, 256, smem2>>>(
        s2_cw, s2_cb, s2_d1w, s2_d1b, s2_d2b, s2_d3w, s2_d3b);

    fc_partial_kernel<<<512, 256>>>(fc_w);
    fc_final_kernel<<<1, 256>>>(fc_b, (float*)d_out);
}

// round 10
// speedup vs baseline: 1.2263x; 1.0152x over previous
#include <cuda_runtime.h>

#define EPSV 1e-5f
typedef unsigned long long ull;
typedef unsigned int uint;

__device__ float g_x1p[16 * 16 * 256 * 256];
__device__ float g_mask2[16 * 256 * 256];
__device__ float g_x2p[16 * 8 * 128 * 128];
__device__ float g_fcpart[16 * 32 * 10];
__device__ int   g_cnt1;
__device__ int   g_list1[16384];

__device__ __align__(16) float g_bhi[9216];    // stage1 d2 tf32-hi fragments
__device__ __align__(16) float g_blo[9216];    // stage1 d2 tf32-lo fragments
__device__ __align__(16) float g_qhi[2304];    // stage2 d2 tf32-hi fragments
__device__ __align__(16) float g_qlo[2304];    // stage2 d2 tf32-lo fragments
__device__ float g_sc[144], g_sh[144];

__device__ __forceinline__ void fma2(ull& d, ull a, ull b) {
    asm("fma.rn.f32x2 %0, %1, %2, %0;" : "+l"(d) : "l"(a), "l"(b));
}
__device__ __forceinline__ ull pack2(float lo, float hi) {
    ull r; asm("mov.b64 %0, {%1, %2};" : "=l"(r) : "f"(lo), "f"(hi)); return r;
}
__device__ __forceinline__ ull dup2(float v) { return pack2(v, v); }
__device__ __forceinline__ float2 unpack2(ull u) {
    float2 f; asm("mov.b64 {%0, %1}, %2;" : "=f"(f.x), "=f"(f.y) : "l"(u)); return f;
}
__device__ __forceinline__ uint tf32_rna(float v) {
    uint r; asm("cvt.rna.tf32.f32 %0, %1;" : "=r"(r) : "f"(v)); return r;
}
__device__ __forceinline__ void mma8(float* a, const uint* A, uint b0, uint b1) {
    asm volatile("mma.sync.aligned.m16n8k8.row.col.f32.tf32.tf32.f32 "
        "{%0,%1,%2,%3},{%4,%5,%6,%7},{%8,%9},{%0,%1,%2,%3};"
        : "+f"(a[0]), "+f"(a[1]), "+f"(a[2]), "+f"(a[3])
        : "r"(A[0]), "r"(A[1]), "r"(A[2]), "r"(A[3]), "r"(b0), "r"(b1));
}

#define RS 20
#define CS 320

// ---------------------------------------------------------------------------
__global__ void prep_kernel(
    const float* __restrict__ s1d2w, const float* __restrict__ s2d2w,
    const float* __restrict__ b10, const float* __restrict__ b11,
    const float* __restrict__ b12, const float* __restrict__ b13,
    const float* __restrict__ b20, const float* __restrict__ b21,
    const float* __restrict__ b22, const float* __restrict__ b23)
{
    const int tid = threadIdx.x;
    if (tid == 0) g_cnt1 = 0;
    for (int i = tid; i < 9216; i += 256) {
        int kstep = i >> 8, r = i & 255;
        int ln = r >> 3, jj = r & 7;
        int kk = kstep * 8 + (ln & 3) + (jj & 1) * 4;
        int c2 = (jj >> 1) * 8 + (ln >> 2);
        int tap = kk >> 5, c1 = kk & 31;
        float wv = s1d2w[(c2 * 32 + c1) * 9 + tap];
        uint hu = tf32_rna(wv);
        g_bhi[i] = __uint_as_float(hu);
        g_blo[i] = __uint_as_float(tf32_rna(wv - __uint_as_float(hu)));
    }
    for (int i = tid; i < 2304; i += 256) {
        int kstep = i >> 7, r = i & 127;
        int ln = r >> 2, jj = r & 3;
        int kk = kstep * 8 + (ln & 3) + (jj & 1) * 4;
        int c2 = (jj >> 1) * 8 + (ln >> 2);
        int tap = kk >> 4, c1 = kk & 15;
        float wv = s2d2w[(c2 * 16 + c1) * 9 + tap];
        uint hu = tf32_rna(wv);
        g_qhi[i] = __uint_as_float(hu);
        g_qlo[i] = __uint_as_float(tf32_rna(wv - __uint_as_float(hu)));
    }
    if (tid < 144) {
        const float* bp; int c, C;
        if      (tid < 16)  { bp = b10; c = tid;       C = 16; }
        else if (tid < 48)  { bp = b11; c = tid - 16;  C = 32; }
        else if (tid < 80)  { bp = b12; c = tid - 48;  C = 32; }
        else if (tid < 96)  { bp = b13; c = tid - 80;  C = 16; }
        else if (tid < 104) { bp = b20; c = tid - 96;  C = 8;  }
        else if (tid < 120) { bp = b21; c = tid - 104; C = 16; }
        else if (tid < 136) { bp = b22; c = tid - 120; C = 16; }
        else                { bp = b23; c = tid - 136; C = 8;  }
        float g = bp[c], b = bp[C + c], m = bp[2 * C + c], v = bp[3 * C + c];
        float s = g * rsqrtf(v + EPSV);
        g_sc[tid] = s; g_sh[tid] = b - s * m;
    }
}

// ---------------------------------------------------------------------------
__global__ void __launch_bounds__(256) stage1_all_kernel(
    const float* __restrict__ x, const float* __restrict__ mask,
    const float* __restrict__ cw, const float* __restrict__ cb)
{
    __shared__ float s_red[256];
    __shared__ float s_wsum[8];
    __shared__ float s_xc[16 * CS];
    __shared__ int s_active;

    const int bid = blockIdx.x;
    const int n = bid >> 10, by = (bid >> 5) & 31, bx = bid & 31;
    const int tid = threadIdx.x;
    const int py = tid >> 4, px_ = tid & 15;
    const int gy = by * 16 + py, gx = bx * 16 + px_;

    float mval = mask[(n * 512 + gy) * 512 + gx];
    s_red[tid] = mval;
    float msum = mval;
#pragma unroll
    for (int o = 16; o; o >>= 1) msum += __shfl_xor_sync(0xffffffffu, msum, o);
    if ((tid & 31) == 0) s_wsum[tid >> 5] = msum;
    __syncthreads();

    if (tid < 64) {
        int qy = tid >> 3, qx = tid & 7;
        int p0 = (qy * 2) * 16 + qx * 2;
        float m0 = fmaxf(fmaxf(s_red[p0], s_red[p0 + 1]),
                         fmaxf(s_red[p0 + 16], s_red[p0 + 17]));
        g_mask2[(n * 256 + by * 8 + qy) * 256 + (bx * 8 + qx)] = m0;
    }
    if (tid == 0) {
        float t = 0.f;
#pragma unroll
        for (int i = 0; i < 8; i++) t += s_wsum[i];
        int act = (t > 128.0f) ? 1 : 0;
        s_active = act;
        if (act) { int pos = atomicAdd(&g_cnt1, 1); g_list1[pos] = bid; }
    }
    __syncthreads();
    if (s_active) return;

    {
        const int ibase = ((n * 3) * 512 + gy) * 512 + gx;
        float xv0 = x[ibase];
        float xv1 = x[ibase + 512 * 512];
        float xv2 = x[ibase + 2 * 512 * 512];
        const int po = py * RS + px_;
#pragma unroll
        for (int c = 0; c < 16; c++) {
            float t = __ldg(&cw[c * 3 + 0]) * xv0 + __ldg(&cw[c * 3 + 1]) * xv1 +
                      __ldg(&cw[c * 3 + 2]) * xv2 + __ldg(&cb[c]);
            t = fmaxf(t, 0.0f);
            s_xc[c * CS + po] = fmaf(__ldg(&g_sc[c]), t, __ldg(&g_sh[c]));
        }
    }
    __syncthreads();

#pragma unroll
    for (int k = 0; k < 4; k++) {
        int o = tid + k * 256;
        int c = o >> 6, q = o & 63;
        int qy = q >> 3, qx = q & 7;
        const float* sp = &s_xc[c * CS + (qy * 2) * RS + qx * 2];
        float mo = fmaxf(fmaxf(sp[0], sp[1]), fmaxf(sp[RS], sp[RS + 1]));
        g_x1p[((n * 16 + c) * 256 + by * 8 + qy) * 256 + (bx * 8 + qx)] = mo;
    }
}

// ---------------------------------------------------------------------------
__global__ void __launch_bounds__(256, 2) stage1_active_kernel(
    const float* __restrict__ x,
    const float* __restrict__ cw, const float* __restrict__ cb,
    const float* __restrict__ d1w, const float* __restrict__ d1b,
    const float* __restrict__ d2b,
    const float* __restrict__ d3w, const float* __restrict__ d3b)
{
    if ((int)blockIdx.x >= g_cnt1) return;
    const int bid = g_list1[blockIdx.x];

    extern __shared__ float sm[];
    float* s_halo = sm + 4;
    float* s_f    = sm;
    float* s_b    = sm + 11528;   // stride 260
    float* s_xc   = s_b;          // [16][CS]

    const int n = bid >> 10, by = (bid >> 5) & 31, bx = bid & 31;
    const int tid = threadIdx.x;
    const int py = tid >> 4, px_ = tid & 15;
    const int gy = by * 16 + py, gx = bx * 16 + px_;

    {
        float4 z4 = make_float4(0.f, 0.f, 0.f, 0.f);
        for (int i = tid; i < 2882; i += 256) ((float4*)sm)[i] = z4;
    }
    {
        const int ibase = ((n * 3) * 512 + gy) * 512 + gx;
        float xv0 = x[ibase];
        float xv1 = x[ibase + 512 * 512];
        float xv2 = x[ibase + 2 * 512 * 512];
        const int po = py * RS + px_;
#pragma unroll
        for (int c = 0; c < 16; c++) {
            float t = __ldg(&cw[c * 3 + 0]) * xv0 + __ldg(&cw[c * 3 + 1]) * xv1 +
                      __ldg(&cw[c * 3 + 2]) * xv2 + __ldg(&cb[c]);
            t = fmaxf(t, 0.0f);
            s_xc[c * CS + po] = fmaf(__ldg(&g_sc[c]), t, __ldg(&g_sh[c]));
        }
    }
    __syncthreads();

    const int lane = tid & 31, wg = tid >> 5;
    const int prow = lane & 15, pcol = (lane >> 4) * 8;

    // d1: 16 -> 32 into halo
    {
        const int c2base = wg * 4;
        ull acc[4][4];
#pragma unroll
        for (int c2 = 0; c2 < 4; c2++) {
            ull bv = dup2(__ldg(&d1b[c2base + c2]));
            acc[c2][0] = bv; acc[c2][1] = bv; acc[c2][2] = bv; acc[c2][3] = bv;
        }
        const int po = prow * RS + pcol;
#pragma unroll
        for (int c1 = 0; c1 < 16; c1++) {
            const float* p = s_xc + c1 * CS + po;
            float4 a = *(const float4*)p;
            float4 b = *(const float4*)(p + 4);
            ull va0 = pack2(a.x, a.y), va1 = pack2(a.z, a.w);
            ull vb0 = pack2(b.x, b.y), vb1 = pack2(b.z, b.w);
#pragma unroll
            for (int c2 = 0; c2 < 4; c2++) {
                ull w = dup2(__ldg(&d1w[(c2base + c2) * 16 + c1]));
                fma2(acc[c2][0], w, va0);
                fma2(acc[c2][1], w, va1);
                fma2(acc[c2][2], w, vb0);
                fma2(acc[c2][3], w, vb1);
            }
        }
        const int ho = (prow + 1) * 20 + pcol;
#pragma unroll
        for (int c2 = 0; c2 < 4; c2++) {
            int c = c2base + c2;
            float sc = __ldg(&g_sc[16 + c]), sh = __ldg(&g_sh[16 + c]);
            float4 o0, o1;
            float2 f0 = unpack2(acc[c2][0]), f1 = unpack2(acc[c2][1]);
            float2 f2 = unpack2(acc[c2][2]), f3 = unpack2(acc[c2][3]);
            o0.x = fmaf(sc, fmaxf(f0.x, 0.f), sh); o0.y = fmaf(sc, fmaxf(f0.y, 0.f), sh);
            o0.z = fmaf(sc, fmaxf(f1.x, 0.f), sh); o0.w = fmaf(sc, fmaxf(f1.y, 0.f), sh);
            o1.x = fmaf(sc, fmaxf(f2.x, 0.f), sh); o1.y = fmaf(sc, fmaxf(f2.y, 0.f), sh);
            o1.z = fmaf(sc, fmaxf(f3.x, 0.f), sh); o1.w = fmaf(sc, fmaxf(f3.y, 0.f), sh);
            *(float4*)(s_halo + c * 360 + ho)     = o0;
            *(float4*)(s_halo + c * 360 + ho + 4) = o1;
        }
    }
    __syncthreads();

    // d2: tf32 mma 3-term (hi via cvt.rna; residual passed as raw fp32 bits)
    {
        const int tg = lane & 3, q = lane >> 2;
        float acc[8][4];
#pragma unroll
        for (int i = 0; i < 8; i++) {
            int c2 = (i & 3) * 8 + tg * 2;
            float b0 = __ldg(&d2b[c2]), b1 = __ldg(&d2b[c2 + 1]);
            acc[i][0] = b0; acc[i][1] = b1; acc[i][2] = b0; acc[i][3] = b1;
        }
        const float* hp0 = s_halo + tg * 360 + wg * 20 + q - 1;
        const uint4* bh = (const uint4*)g_bhi + lane * 2;
        const uint4* bl = (const uint4*)g_blo + lane * 2;
#pragma unroll 1
        for (int tap = 0; tap < 9; tap++) {
            int dyq = (tap * 11) >> 5;
            const float* hp = hp0 + tap + 17 * dyq;
#pragma unroll
            for (int kl = 0; kl < 4; kl++) {
                float av[8];
                av[0] = hp[0];    av[1] = hp[8];    av[2] = hp[1440]; av[3] = hp[1448];
                av[4] = hp[160];  av[5] = hp[168];  av[6] = hp[1600]; av[7] = hp[1608];
                hp += 2880;
                uint Ah[8], Al[8];
#pragma unroll
                for (int i = 0; i < 8; i++) {
                    Ah[i] = tf32_rna(av[i]);
                    Al[i] = __float_as_uint(av[i] - __uint_as_float(Ah[i]));
                }
                uint4 H0 = __ldg(bh), H1 = __ldg(bh + 1);
                uint4 L0 = __ldg(bl), L1 = __ldg(bl + 1);
                bh += 64; bl += 64;
                uint BH[8] = {H0.x, H0.y, H0.z, H0.w, H1.x, H1.y, H1.z, H1.w};
                uint BL[8] = {L0.x, L0.y, L0.z, L0.w, L1.x, L1.y, L1.z, L1.w};
#pragma unroll
                for (int nt = 0; nt < 4; nt++) {
                    mma8(acc[nt],     Ah,     BH[2*nt], BH[2*nt+1]);
                    mma8(acc[nt],     Ah,     BL[2*nt], BL[2*nt+1]);
                    mma8(acc[nt],     Al,     BH[2*nt], BH[2*nt+1]);
                    mma8(acc[nt + 4], Ah + 4, BH[2*nt], BH[2*nt+1]);
                    mma8(acc[nt + 4], Ah + 4, BL[2*nt], BL[2*nt+1]);
                    mma8(acc[nt + 4], Al + 4, BH[2*nt], BH[2*nt+1]);
                }
            }
        }
#pragma unroll
        for (int i = 0; i < 8; i++) {
            int mt = i >> 2, nt = i & 3;
            int c2 = nt * 8 + tg * 2;
            float s0 = __ldg(&g_sc[48 + c2]), h0 = __ldg(&g_sh[48 + c2]);
            float s1 = __ldg(&g_sc[49 + c2]), h1 = __ldg(&g_sh[49 + c2]);
            float* o = s_b + c2 * 260 + (wg + mt * 8) * 16 + q;
            o[0]   = fmaf(s0, fmaxf(acc[i][0], 0.f), h0);
            o[260] = fmaf(s1, fmaxf(acc[i][1], 0.f), h1);
            o[8]   = fmaf(s0, fmaxf(acc[i][2], 0.f), h0);
            o[268] = fmaf(s1, fmaxf(acc[i][3], 0.f), h1);
        }
    }
    __syncthreads();

    // d3: 32 -> 16
    {
        const int q = tid & 63;
        const int c2base = (tid >> 6) * 4;
        ull acc[4][2];
#pragma unroll
        for (int c2 = 0; c2 < 4; c2++) {
            ull bv = dup2(__ldg(&d3b[c2base + c2]));
            acc[c2][0] = bv; acc[c2][1] = bv;
        }
#pragma unroll 4
        for (int c1 = 0; c1 < 32; c1++) {
            float4 v = *(const float4*)(s_b + c1 * 260 + q * 4);
            ull v0 = pack2(v.x, v.y), v1 = pack2(v.z, v.w);
#pragma unroll
            for (int c2 = 0; c2 < 4; c2++) {
                ull w = dup2(__ldg(&d3w[(c2base + c2) * 32 + c1]));
                fma2(acc[c2][0], w, v0);
                fma2(acc[c2][1], w, v1);
            }
        }
#pragma unroll
        for (int c2 = 0; c2 < 4; c2++) {
            int c = c2base + c2;
            float sc = __ldg(&g_sc[80 + c]), sh = __ldg(&g_sh[80 + c]);
            float2 f0 = unpack2(acc[c2][0]), f1 = unpack2(acc[c2][1]);
            float4 o;
            o.x = fmaf(sc, fmaxf(f0.x, 0.f), sh);
            o.y = fmaf(sc, fmaxf(f0.y, 0.f), sh);
            o.z = fmaf(sc, fmaxf(f1.x, 0.f), sh);
            o.w = fmaf(sc, fmaxf(f1.y, 0.f), sh);
            *(float4*)(s_f + c * 256 + q * 4) = o;
        }
    }
    __syncthreads();

#pragma unroll
    for (int k = 0; k < 4; k++) {
        int o = tid + k * 256;
        int c = o >> 6, q = o & 63;
        int qy = q >> 3, qx = q & 7;
        const float* sp = &s_f[c * 256 + (qy * 2) * 16 + qx * 2];
        float mo = fmaxf(fmaxf(sp[0], sp[1]), fmaxf(sp[16], sp[17]));
        g_x1p[((n * 16 + c) * 256 + by * 8 + qy) * 256 + (bx * 8 + qx)] = mo;
    }
}

// ---------------------------------------------------------------------------
__global__ void __launch_bounds__(256, 3) stage2_kernel(
    const float* __restrict__ cw, const float* __restrict__ cb,
    const float* __restrict__ d1w, const float* __restrict__ d1b,
    const float* __restrict__ d2b,
    const float* __restrict__ d3w, const float* __restrict__ d3b)
{
    extern __shared__ float sm2[];
    float* s_halo = sm2 + 4;
    float* s_f    = sm2;
    float* s_b    = sm2 + 5764;   // stride 260
    float* s_xc   = s_b;          // [8][CS]

    __shared__ float s_wsum[8];
    __shared__ int s_active;

    const int bid = blockIdx.x;
    const int n = bid >> 8, by = (bid >> 4) & 15, bx = bid & 15;
    const int tid = threadIdx.x;
    const int py = tid >> 4, px_ = tid & 15;
    const int gy = by * 16 + py, gx = bx * 16 + px_;

    {
        float mv = g_mask2[(n * 256 + gy) * 256 + gx];
#pragma unroll
        for (int o = 16; o; o >>= 1) mv += __shfl_xor_sync(0xffffffffu, mv, o);
        if ((tid & 31) == 0) s_wsum[tid >> 5] = mv;
    }
    {
        float4 z4 = make_float4(0.f, 0.f, 0.f, 0.f);
        for (int i = tid; i < 1441; i += 256) ((float4*)sm2)[i] = z4;
    }
    __syncthreads();
    if (tid == 0) {
        float t = 0.f;
#pragma unroll
        for (int i = 0; i < 8; i++) t += s_wsum[i];
        s_active = (t > 128.0f) ? 1 : 0;
    }

    {
        const int ibase = ((n * 16) * 256 + gy) * 256 + gx;
        float xin[16];
#pragma unroll
        for (int c = 0; c < 16; c++) xin[c] = g_x1p[ibase + c * 65536];
        const int po = py * RS + px_;
#pragma unroll
        for (int c2 = 0; c2 < 8; c2++) {
            float t = __ldg(&cb[c2]);
#pragma unroll
            for (int c1 = 0; c1 < 16; c1++)
                t = fmaf(xin[c1], __ldg(&cw[c2 * 16 + c1]), t);
            t = fmaxf(t, 0.0f);
            s_xc[c2 * CS + po] = fmaf(__ldg(&g_sc[96 + c2]), t, __ldg(&g_sh[96 + c2]));
        }
    }
    __syncthreads();

    const int act = s_active;
    const int lane = tid & 31, wg = tid >> 5;
    const int prow = lane & 15, pcol = (lane >> 4) * 8;

    if (act) {
        // d1: 8 -> 16 into halo
        {
            const int c2base = wg * 2;
            const int po = prow * RS + pcol;
            ull acc[2][4];
#pragma unroll
            for (int c2 = 0; c2 < 2; c2++) {
                ull bv = dup2(__ldg(&d1b[c2base + c2]));
                acc[c2][0] = bv; acc[c2][1] = bv; acc[c2][2] = bv; acc[c2][3] = bv;
            }
#pragma unroll
            for (int c1 = 0; c1 < 8; c1++) {
                const float* p = s_xc + c1 * CS + po;
                float4 a = *(const float4*)p;
                float4 b = *(const float4*)(p + 4);
                ull va0 = pack2(a.x, a.y), va1 = pack2(a.z, a.w);
                ull vb0 = pack2(b.x, b.y), vb1 = pack2(b.z, b.w);
#pragma unroll
                for (int c2 = 0; c2 < 2; c2++) {
                    ull w = dup2(__ldg(&d1w[(c2base + c2) * 8 + c1]));
                    fma2(acc[c2][0], w, va0);
                    fma2(acc[c2][1], w, va1);
                    fma2(acc[c2][2], w, vb0);
                    fma2(acc[c2][3], w, vb1);
                }
            }
            const int ho = (prow + 1) * 20 + pcol;
#pragma unroll
            for (int c2 = 0; c2 < 2; c2++) {
                int c = c2base + c2;
                float sc = __ldg(&g_sc[104 + c]), sh = __ldg(&g_sh[104 + c]);
                float2 f0 = unpack2(acc[c2][0]), f1 = unpack2(acc[c2][1]);
                float2 f2 = unpack2(acc[c2][2]), f3 = unpack2(acc[c2][3]);
                float4 o0, o1;
                o0.x = fmaf(sc, fmaxf(f0.x, 0.f), sh); o0.y = fmaf(sc, fmaxf(f0.y, 0.f), sh);
                o0.z = fmaf(sc, fmaxf(f1.x, 0.f), sh); o0.w = fmaf(sc, fmaxf(f1.y, 0.f), sh);
                o1.x = fmaf(sc, fmaxf(f2.x, 0.f), sh); o1.y = fmaf(sc, fmaxf(f2.y, 0.f), sh);
                o1.z = fmaf(sc, fmaxf(f3.x, 0.f), sh); o1.w = fmaf(sc, fmaxf(f3.y, 0.f), sh);
                *(float4*)(s_halo + c * 360 + ho)     = o0;
                *(float4*)(s_halo + c * 360 + ho + 4) = o1;
            }
        }
        __syncthreads();

        // d2: 3x3, 16 -> 16 via tf32 mma (3-term, raw-bit residual)
        {
            const int tg = lane & 3, q = lane >> 2;
            float acc[4][4];
#pragma unroll
            for (int i = 0; i < 4; i++) {
                int c2 = (i & 1) * 8 + tg * 2;
                float b0 = __ldg(&d2b[c2]), b1 = __ldg(&d2b[c2 + 1]);
                acc[i][0] = b0; acc[i][1] = b1; acc[i][2] = b0; acc[i][3] = b1;
            }
            const float* hp0 = s_halo + tg * 360 + wg * 20 + q - 1;
            const uint4* bh = (const uint4*)g_qhi + lane;
            const uint4* bl = (const uint4*)g_qlo + lane;
#pragma unroll 1
            for (int tap = 0; tap < 9; tap++) {
                int dyq = (tap * 11) >> 5;
                const float* hp = hp0 + tap + 17 * dyq;
#pragma unroll
                for (int kl = 0; kl < 2; kl++) {
                    float av[8];
                    av[0] = hp[0];    av[1] = hp[8];    av[2] = hp[1440]; av[3] = hp[1448];
                    av[4] = hp[160];  av[5] = hp[168];  av[6] = hp[1600]; av[7] = hp[1608];
                    hp += 2880;
                    uint Ah[8], Al[8];
#pragma unroll
                    for (int i = 0; i < 8; i++) {
                        Ah[i] = tf32_rna(av[i]);
                        Al[i] = __float_as_uint(av[i] - __uint_as_float(Ah[i]));
                    }
                    uint4 H = __ldg(bh), L = __ldg(bl);
                    bh += 32; bl += 32;
                    mma8(acc[0], Ah,     H.x, H.y);
                    mma8(acc[0], Ah,     L.x, L.y);
                    mma8(acc[0], Al,     H.x, H.y);
                    mma8(acc[1], Ah,     H.z, H.w);
                    mma8(acc[1], Ah,     L.z, L.w);
                    mma8(acc[1], Al,     H.z, H.w);
                    mma8(acc[2], Ah + 4, H.x, H.y);
                    mma8(acc[2], Ah + 4, L.x, L.y);
                    mma8(acc[2], Al + 4, H.x, H.y);
                    mma8(acc[3], Ah + 4, H.z, H.w);
                    mma8(acc[3], Ah + 4, L.z, L.w);
                    mma8(acc[3], Al + 4, H.z, H.w);
                }
            }
#pragma unroll
            for (int i = 0; i < 4; i++) {
                int mt = i >> 1, nt = i & 1;
                int c2 = nt * 8 + tg * 2;
                float s0 = __ldg(&g_sc[120 + c2]), h0 = __ldg(&g_sh[120 + c2]);
                float s1 = __ldg(&g_sc[121 + c2]), h1 = __ldg(&g_sh[121 + c2]);
                float* o = s_b + c2 * 260 + (wg + mt * 8) * 16 + q;
                o[0]   = fmaf(s0, fmaxf(acc[i][0], 0.f), h0);
                o[260] = fmaf(s1, fmaxf(acc[i][1], 0.f), h1);
                o[8]   = fmaf(s0, fmaxf(acc[i][2], 0.f), h0);
                o[268] = fmaf(s1, fmaxf(acc[i][3], 0.f), h1);
            }
        }
        __syncthreads();

        // d3: 16 -> 8
        {
            const int q = tid & 63;
            const int c2base = (tid >> 6) * 2;
            ull acc[2][2];
#pragma unroll
            for (int c2 = 0; c2 < 2; c2++) {
                ull bv = dup2(__ldg(&d3b[c2base + c2]));
                acc[c2][0] = bv; acc[c2][1] = bv;
            }
#pragma unroll
            for (int c1 = 0; c1 < 16; c1++) {
                float4 v = *(const float4*)(s_b + c1 * 260 + q * 4);
                ull v0 = pack2(v.x, v.y), v1 = pack2(v.z, v.w);
#pragma unroll
                for (int c2 = 0; c2 < 2; c2++) {
                    ull w = dup2(__ldg(&d3w[(c2base + c2) * 16 + c1]));
                    fma2(acc[c2][0], w, v0);
                    fma2(acc[c2][1], w, v1);
                }
            }
#pragma unroll
            for (int c2 = 0; c2 < 2; c2++) {
                int c = c2base + c2;
                float sc = __ldg(&g_sc[136 + c]), sh = __ldg(&g_sh[136 + c]);
                float2 f0 = unpack2(acc[c2][0]), f1 = unpack2(acc[c2][1]);
                float4 o;
                o.x = fmaf(sc, fmaxf(f0.x, 0.f), sh);
                o.y = fmaf(sc, fmaxf(f0.y, 0.f), sh);
                o.z = fmaf(sc, fmaxf(f1.x, 0.f), sh);
                o.w = fmaf(sc, fmaxf(f1.y, 0.f), sh);
                *(float4*)(s_f + c * 256 + q * 4) = o;
            }
        }
        __syncthreads();
    }

    const float* srcp = act ? s_f : s_xc;
    const int chs = act ? 256 : CS;
    const int rs = act ? 16 : RS;
#pragma unroll
    for (int k = 0; k < 2; k++) {
        int o = tid + k * 256;
        int c = o >> 6, q = o & 63;
        int qy = q >> 3, qx = q & 7;
        const float* sp = &srcp[c * chs + (qy * 2) * rs + qx * 2];
        float mo = fmaxf(fmaxf(sp[0], sp[1]), fmaxf(sp[rs], sp[rs + 1]));
        g_x2p[((n * 8 + c) * 128 + by * 8 + qy) * 128 + (bx * 8 + qx)] = mo;
    }
}

// ---------------------------------------------------------------------------
__global__ void __launch_bounds__(256) fc_partial_kernel(const float* __restrict__ fc_w)
{
    const int b = blockIdx.x;
    const int n = b >> 5, s = b & 31;
    const int tid = threadIdx.x;
    const float4* f = (const float4*)(g_x2p + n * 131072 + s * 4096);
    const float4* w = (const float4*)(fc_w) + s * 1024;

    float part[10];
#pragma unroll
    for (int k = 0; k < 10; k++) part[k] = 0.0f;

#pragma unroll
    for (int j = tid; j < 1024; j += 256) {
        float4 fv = f[j];
#pragma unroll
        for (int k = 0; k < 10; k++) {
            float4 wv = __ldg(&w[k * 32768 + j]);
            part[k] += fv.x * wv.x + fv.y * wv.y + fv.z * wv.z + fv.w * wv.w;
        }
    }

    __shared__ float sred[10][256];
#pragma unroll
    for (int k = 0; k < 10; k++) sred[k][tid] = part[k];
    __syncthreads();
    for (int st = 128; st > 0; st >>= 1) {
        if (tid < st) {
#pragma unroll
            for (int k = 0; k < 10; k++) sred[k][tid] += sred[k][tid + st];
        }
        __syncthreads();
    }
    if (tid < 10) g_fcpart[(n * 32 + s) * 10 + tid] = sred[tid][0];
}

__global__ void fc_final_kernel(const float* __restrict__ fc_b, float* __restrict__ out)
{
    const int t = threadIdx.x;
    __shared__ float s_l[16][10];
    if (t < 160) {
        int n = t / 10, k = t - n * 10;
        float a = fc_b[k];
#pragma unroll
        for (int s = 0; s < 32; s++) a += g_fcpart[(n * 32 + s) * 10 + k];
        s_l[n][k] = a;
    }
    __syncthreads();
    if (t < 16) {
        float mx = -1e30f;
#pragma unroll
        for (int k = 0; k < 10; k++) mx = fmaxf(mx, s_l[t][k]);
        float e[10], se = 0.f;
#pragma unroll
        for (int k = 0; k < 10; k++) { e[k] = expf(s_l[t][k] - mx); se += e[k]; }
        float inv = 1.0f / se;
#pragma unroll
        for (int k = 0; k < 10; k++) out[t * 10 + k] = e[k] * inv;
    }
}

// ---------------------------------------------------------------------------
extern "C" void kernel_launch(void* const* d_in, const int* in_sizes, int n_in,
                              void* d_out, int out_size)
{
    const float* x      = (const float*)d_in[0];
    const float* mask   = (const float*)d_in[1];
    const float* s1_cw  = (const float*)d_in[2];
    const float* s1_cb  = (const float*)d_in[3];
    const float* s1_bn0 = (const float*)d_in[4];
    const float* s1_d1w = (const float*)d_in[5];
    const float* s1_d1b = (const float*)d_in[6];
    const float* s1_bn1 = (const float*)d_in[7];
    const float* s1_d2w = (const float*)d_in[8];
    const float* s1_d2b = (const float*)d_in[9];
    const float* s1_bn2 = (const float*)d_in[10];
    const float* s1_d3w = (const float*)d_in[11];
    const float* s1_d3b = (const float*)d_in[12];
    const float* s1_bn3 = (const float*)d_in[13];
    const float* s2_cw  = (const float*)d_in[14];
    const float* s2_cb  = (const float*)d_in[15];
    const float* s2_bn0 = (const float*)d_in[16];
    const float* s2_d1w = (const float*)d_in[17];
    const float* s2_d1b = (const float*)d_in[18];
    const float* s2_bn1 = (const float*)d_in[19];
    const float* s2_d2w = (const float*)d_in[20];
    const float* s2_d2b = (const float*)d_in[21];
    const float* s2_bn2 = (const float*)d_in[22];
    const float* s2_d3w = (const float*)d_in[23];
    const float* s2_d3b = (const float*)d_in[24];
    const float* s2_bn3 = (const float*)d_in[25];
    const float* fc_w   = (const float*)d_in[26];
    const float* fc_b   = (const float*)d_in[27];

    prep_kernel<<<1, 256>>>(s1_d2w, s2_d2w,
                            s1_bn0, s1_bn1, s1_bn2, s1_bn3,
                            s2_bn0, s2_bn1, s2_bn2, s2_bn3);

    stage1_all_kernel<<<16 * 32 * 32, 256>>>(x, mask, s1_cw, s1_cb);

    const int smem1 = 19848 * sizeof(float);
    cudaFuncSetAttribute(stage1_active_kernel, cudaFuncAttributeMaxDynamicSharedMemorySize, smem1);
    stage1_active_kernel<<<16 * 32 * 32, 256, smem1>>>(
        x, s1_cw, s1_cb, s1_d1w, s1_d1b, s1_d2b, s1_d3w, s1_d3b);

    const int smem2 = 9924 * sizeof(float);
    cudaFuncSetAttribute(stage2_kernel, cudaFuncAttributeMaxDynamicSharedMemorySize, smem2);
    stage2_kernel<<<16 * 16 * 16, 256, smem2>>>(
        s2_cw, s2_cb, s2_d1w, s2_d1b, s2_d2b, s2_d3w, s2_d3b);

    fc_partial_kernel<<<512, 256>>>(fc_w);
    fc_final_kernel<<<1, 256>>>(fc_b, (float*)d_out);
}

// round 11
// speedup vs baseline: 1.3078x; 1.0664x over previous
#include <cuda_runtime.h>

#define EPSV 1e-5f
typedef unsigned long long ull;
typedef unsigned int uint;

__device__ float g_x1p[16 * 16 * 256 * 256];
__device__ float g_mask2[16 * 256 * 256];
__device__ float g_x2p[16 * 8 * 128 * 128];
__device__ float g_fcpart[16 * 32 * 10];
__device__ int   g_cnt1;
__device__ int   g_list1[16384];

__device__ __align__(16) float g_bhi[9216];    // stage1 d2 tf32-hi fragments
__device__ __align__(16) float g_blo[9216];    // stage1 d2 tf32-lo fragments
__device__ __align__(16) float g_qhi[2304];    // stage2 d2 tf32-hi fragments
__device__ __align__(16) float g_qlo[2304];    // stage2 d2 tf32-lo fragments
__device__ float g_sc[144], g_sh[144];

__device__ __forceinline__ void fma2(ull& d, ull a, ull b) {
    asm("fma.rn.f32x2 %0, %1, %2, %0;" : "+l"(d) : "l"(a), "l"(b));
}
__device__ __forceinline__ ull pack2(float lo, float hi) {
    ull r; asm("mov.b64 %0, {%1, %2};" : "=l"(r) : "f"(lo), "f"(hi)); return r;
}
__device__ __forceinline__ ull dup2(float v) { return pack2(v, v); }
__device__ __forceinline__ float2 unpack2(ull u) {
    float2 f; asm("mov.b64 {%0, %1}, %2;" : "=f"(f.x), "=f"(f.y) : "l"(u)); return f;
}
__device__ __forceinline__ uint tf32_rna(float v) {
    uint r; asm("cvt.rna.tf32.f32 %0, %1;" : "=r"(r) : "f"(v)); return r;
}
__device__ __forceinline__ void mma8(float* a, const uint* A, uint b0, uint b1) {
    asm volatile("mma.sync.aligned.m16n8k8.row.col.f32.tf32.tf32.f32 "
        "{%0,%1,%2,%3},{%4,%5,%6,%7},{%8,%9},{%0,%1,%2,%3};"
        : "+f"(a[0]), "+f"(a[1]), "+f"(a[2]), "+f"(a[3])
        : "r"(A[0]), "r"(A[1]), "r"(A[2]), "r"(A[3]), "r"(b0), "r"(b1));
}

#define RS 20
#define CS 320

// ---------------------------------------------------------------------------
__global__ void prep_kernel(
    const float* __restrict__ s1d2w, const float* __restrict__ s2d2w,
    const float* __restrict__ b10, const float* __restrict__ b11,
    const float* __restrict__ b12, const float* __restrict__ b13,
    const float* __restrict__ b20, const float* __restrict__ b21,
    const float* __restrict__ b22, const float* __restrict__ b23)
{
    const int tid = threadIdx.x;
    if (tid == 0) g_cnt1 = 0;
    for (int i = tid; i < 9216; i += 256) {
        int kstep = i >> 8, r = i & 255;
        int ln = r >> 3, jj = r & 7;
        int kk = kstep * 8 + (ln & 3) + (jj & 1) * 4;
        int c2 = (jj >> 1) * 8 + (ln >> 2);
        int tap = kk >> 5, c1 = kk & 31;
        float wv = s1d2w[(c2 * 32 + c1) * 9 + tap];
        uint hu = tf32_rna(wv);
        g_bhi[i] = __uint_as_float(hu);
        g_blo[i] = __uint_as_float(tf32_rna(wv - __uint_as_float(hu)));
    }
    for (int i = tid; i < 2304; i += 256) {
        int kstep = i >> 7, r = i & 127;
        int ln = r >> 2, jj = r & 3;
        int kk = kstep * 8 + (ln & 3) + (jj & 1) * 4;
        int c2 = (jj >> 1) * 8 + (ln >> 2);
        int tap = kk >> 4, c1 = kk & 15;
        float wv = s2d2w[(c2 * 16 + c1) * 9 + tap];
        uint hu = tf32_rna(wv);
        g_qhi[i] = __uint_as_float(hu);
        g_qlo[i] = __uint_as_float(tf32_rna(wv - __uint_as_float(hu)));
    }
    if (tid < 144) {
        const float* bp; int c, C;
        if      (tid < 16)  { bp = b10; c = tid;       C = 16; }
        else if (tid < 48)  { bp = b11; c = tid - 16;  C = 32; }
        else if (tid < 80)  { bp = b12; c = tid - 48;  C = 32; }
        else if (tid < 96)  { bp = b13; c = tid - 80;  C = 16; }
        else if (tid < 104) { bp = b20; c = tid - 96;  C = 8;  }
        else if (tid < 120) { bp = b21; c = tid - 104; C = 16; }
        else if (tid < 136) { bp = b22; c = tid - 120; C = 16; }
        else                { bp = b23; c = tid - 136; C = 8;  }
        float g = bp[c], b = bp[C + c], m = bp[2 * C + c], v = bp[3 * C + c];
        float s = g * rsqrtf(v + EPSV);
        g_sc[tid] = s; g_sh[tid] = b - s * m;
    }
}

// ---------------------------------------------------------------------------
__global__ void __launch_bounds__(256) stage1_all_kernel(
    const float* __restrict__ x, const float* __restrict__ mask,
    const float* __restrict__ cw, const float* __restrict__ cb)
{
    __shared__ float s_red[256];
    __shared__ float s_wsum[8];
    __shared__ float s_xc[16 * CS];
    __shared__ int s_active;

    const int bid = blockIdx.x;
    const int n = bid >> 10, by = (bid >> 5) & 31, bx = bid & 31;
    const int tid = threadIdx.x;
    const int py = tid >> 4, px_ = tid & 15;
    const int gy = by * 16 + py, gx = bx * 16 + px_;

    float mval = mask[(n * 512 + gy) * 512 + gx];
    s_red[tid] = mval;
    float msum = mval;
#pragma unroll
    for (int o = 16; o; o >>= 1) msum += __shfl_xor_sync(0xffffffffu, msum, o);
    if ((tid & 31) == 0) s_wsum[tid >> 5] = msum;
    __syncthreads();

    if (tid < 64) {
        int qy = tid >> 3, qx = tid & 7;
        int p0 = (qy * 2) * 16 + qx * 2;
        float m0 = fmaxf(fmaxf(s_red[p0], s_red[p0 + 1]),
                         fmaxf(s_red[p0 + 16], s_red[p0 + 17]));
        g_mask2[(n * 256 + by * 8 + qy) * 256 + (bx * 8 + qx)] = m0;
    }
    if (tid == 0) {
        float t = 0.f;
#pragma unroll
        for (int i = 0; i < 8; i++) t += s_wsum[i];
        int act = (t > 128.0f) ? 1 : 0;
        s_active = act;
        if (act) { int pos = atomicAdd(&g_cnt1, 1); g_list1[pos] = bid; }
    }
    __syncthreads();
    if (s_active) return;

    {
        const int ibase = ((n * 3) * 512 + gy) * 512 + gx;
        float xv0 = x[ibase];
        float xv1 = x[ibase + 512 * 512];
        float xv2 = x[ibase + 2 * 512 * 512];
        const int po = py * RS + px_;
#pragma unroll
        for (int c = 0; c < 16; c++) {
            float t = __ldg(&cw[c * 3 + 0]) * xv0 + __ldg(&cw[c * 3 + 1]) * xv1 +
                      __ldg(&cw[c * 3 + 2]) * xv2 + __ldg(&cb[c]);
            t = fmaxf(t, 0.0f);
            s_xc[c * CS + po] = fmaf(__ldg(&g_sc[c]), t, __ldg(&g_sh[c]));
        }
    }
    __syncthreads();

#pragma unroll
    for (int k = 0; k < 4; k++) {
        int o = tid + k * 256;
        int c = o >> 6, q = o & 63;
        int qy = q >> 3, qx = q & 7;
        const float* sp = &s_xc[c * CS + (qy * 2) * RS + qx * 2];
        float mo = fmaxf(fmaxf(sp[0], sp[1]), fmaxf(sp[RS], sp[RS + 1]));
        g_x1p[((n * 16 + c) * 256 + by * 8 + qy) * 256 + (bx * 8 + qx)] = mo;
    }
}

// ---------------------------------------------------------------------------
// Stage 1b: SMEM re-aliased to 66.6 KB so 3 CTAs/SM fit; regs capped by
// __launch_bounds__(256,3). Layout (words): [0..4) guard, halo [4..11524),
// s_xc [11524..16644). After d2 loop: s_b = sm+4 (stride 260, reuses halo),
// s_f = sm+8324.
// ---------------------------------------------------------------------------
__global__ void __launch_bounds__(256, 3) stage1_active_kernel(
    const float* __restrict__ x,
    const float* __restrict__ cw, const float* __restrict__ cb,
    const float* __restrict__ d1w, const float* __restrict__ d1b,
    const float* __restrict__ d2b,
    const float* __restrict__ d3w, const float* __restrict__ d3b)
{
    if ((int)blockIdx.x >= g_cnt1) return;
    const int bid = g_list1[blockIdx.x];

    extern __shared__ float sm[];
    float* s_halo = sm + 4;
    float* s_xc   = sm + 11524;   // [16][CS]
    float* s_b    = sm + 4;       // [32][260], reuses halo after sync
    float* s_f    = sm + 8324;    // [16][256]

    const int n = bid >> 10, by = (bid >> 5) & 31, bx = bid & 31;
    const int tid = threadIdx.x;
    const int py = tid >> 4, px_ = tid & 15;
    const int gy = by * 16 + py, gx = bx * 16 + px_;

    {
        float4 z4 = make_float4(0.f, 0.f, 0.f, 0.f);
        for (int i = tid; i < 2881; i += 256) ((float4*)sm)[i] = z4;
    }
    {
        const int ibase = ((n * 3) * 512 + gy) * 512 + gx;
        float xv0 = x[ibase];
        float xv1 = x[ibase + 512 * 512];
        float xv2 = x[ibase + 2 * 512 * 512];
        const int po = py * RS + px_;
#pragma unroll
        for (int c = 0; c < 16; c++) {
            float t = __ldg(&cw[c * 3 + 0]) * xv0 + __ldg(&cw[c * 3 + 1]) * xv1 +
                      __ldg(&cw[c * 3 + 2]) * xv2 + __ldg(&cb[c]);
            t = fmaxf(t, 0.0f);
            s_xc[c * CS + po] = fmaf(__ldg(&g_sc[c]), t, __ldg(&g_sh[c]));
        }
    }
    __syncthreads();

    const int lane = tid & 31, wg = tid >> 5;
    const int prow = lane & 15, pcol = (lane >> 4) * 8;

    // d1: 16 -> 32 into halo
    {
        const int c2base = wg * 4;
        ull acc[4][4];
#pragma unroll
        for (int c2 = 0; c2 < 4; c2++) {
            ull bv = dup2(__ldg(&d1b[c2base + c2]));
            acc[c2][0] = bv; acc[c2][1] = bv; acc[c2][2] = bv; acc[c2][3] = bv;
        }
        const int po = prow * RS + pcol;
#pragma unroll
        for (int c1 = 0; c1 < 16; c1++) {
            const float* p = s_xc + c1 * CS + po;
            float4 a = *(const float4*)p;
            float4 b = *(const float4*)(p + 4);
            ull va0 = pack2(a.x, a.y), va1 = pack2(a.z, a.w);
            ull vb0 = pack2(b.x, b.y), vb1 = pack2(b.z, b.w);
#pragma unroll
            for (int c2 = 0; c2 < 4; c2++) {
                ull w = dup2(__ldg(&d1w[(c2base + c2) * 16 + c1]));
                fma2(acc[c2][0], w, va0);
                fma2(acc[c2][1], w, va1);
                fma2(acc[c2][2], w, vb0);
                fma2(acc[c2][3], w, vb1);
            }
        }
        const int ho = (prow + 1) * 20 + pcol;
#pragma unroll
        for (int c2 = 0; c2 < 4; c2++) {
            int c = c2base + c2;
            float sc = __ldg(&g_sc[16 + c]), sh = __ldg(&g_sh[16 + c]);
            float4 o0, o1;
            float2 f0 = unpack2(acc[c2][0]), f1 = unpack2(acc[c2][1]);
            float2 f2 = unpack2(acc[c2][2]), f3 = unpack2(acc[c2][3]);
            o0.x = fmaf(sc, fmaxf(f0.x, 0.f), sh); o0.y = fmaf(sc, fmaxf(f0.y, 0.f), sh);
            o0.z = fmaf(sc, fmaxf(f1.x, 0.f), sh); o0.w = fmaf(sc, fmaxf(f1.y, 0.f), sh);
            o1.x = fmaf(sc, fmaxf(f2.x, 0.f), sh); o1.y = fmaf(sc, fmaxf(f2.y, 0.f), sh);
            o1.z = fmaf(sc, fmaxf(f3.x, 0.f), sh); o1.w = fmaf(sc, fmaxf(f3.y, 0.f), sh);
            *(float4*)(s_halo + c * 360 + ho)     = o0;
            *(float4*)(s_halo + c * 360 + ho + 4) = o1;
        }
    }
    __syncthreads();

    // d2: tf32 mma 3-term (raw-bit residual)
    {
        const int tg = lane & 3, q = lane >> 2;
        float acc[8][4];
#pragma unroll
        for (int i = 0; i < 8; i++) {
            int c2 = (i & 3) * 8 + tg * 2;
            float b0 = __ldg(&d2b[c2]), b1 = __ldg(&d2b[c2 + 1]);
            acc[i][0] = b0; acc[i][1] = b1; acc[i][2] = b0; acc[i][3] = b1;
        }
        const float* hp0 = s_halo + tg * 360 + wg * 20 + q - 1;
        const uint4* bh = (const uint4*)g_bhi + lane * 2;
        const uint4* bl = (const uint4*)g_blo + lane * 2;
#pragma unroll 1
        for (int tap = 0; tap < 9; tap++) {
            int dyq = (tap * 11) >> 5;
            const float* hp = hp0 + tap + 17 * dyq;
#pragma unroll
            for (int kl = 0; kl < 4; kl++) {
                float av[8];
                av[0] = hp[0];    av[1] = hp[8];    av[2] = hp[1440]; av[3] = hp[1448];
                av[4] = hp[160];  av[5] = hp[168];  av[6] = hp[1600]; av[7] = hp[1608];
                hp += 2880;
                uint Ah[8], Al[8];
#pragma unroll
                for (int i = 0; i < 8; i++) {
                    Ah[i] = tf32_rna(av[i]);
                    Al[i] = __float_as_uint(av[i] - __uint_as_float(Ah[i]));
                }
                uint4 H0 = __ldg(bh), H1 = __ldg(bh + 1);
                uint4 L0 = __ldg(bl), L1 = __ldg(bl + 1);
                bh += 64; bl += 64;
                uint BH[8] = {H0.x, H0.y, H0.z, H0.w, H1.x, H1.y, H1.z, H1.w};
                uint BL[8] = {L0.x, L0.y, L0.z, L0.w, L1.x, L1.y, L1.z, L1.w};
#pragma unroll
                for (int nt = 0; nt < 4; nt++) {
                    mma8(acc[nt],     Ah,     BH[2*nt], BH[2*nt+1]);
                    mma8(acc[nt],     Ah,     BL[2*nt], BL[2*nt+1]);
                    mma8(acc[nt],     Al,     BH[2*nt], BH[2*nt+1]);
                    mma8(acc[nt + 4], Ah + 4, BH[2*nt], BH[2*nt+1]);
                    mma8(acc[nt + 4], Ah + 4, BL[2*nt], BL[2*nt+1]);
                    mma8(acc[nt + 4], Al + 4, BH[2*nt], BH[2*nt+1]);
                }
            }
        }
        __syncthreads();   // all halo reads done; s_b may now overwrite it
#pragma unroll
        for (int i = 0; i < 8; i++) {
            int mt = i >> 2, nt = i & 3;
            int c2 = nt * 8 + tg * 2;
            float s0 = __ldg(&g_sc[48 + c2]), h0 = __ldg(&g_sh[48 + c2]);
            float s1 = __ldg(&g_sc[49 + c2]), h1 = __ldg(&g_sh[49 + c2]);
            float* o = s_b + c2 * 260 + (wg + mt * 8) * 16 + q;
            o[0]   = fmaf(s0, fmaxf(acc[i][0], 0.f), h0);
            o[260] = fmaf(s1, fmaxf(acc[i][1], 0.f), h1);
            o[8]   = fmaf(s0, fmaxf(acc[i][2], 0.f), h0);
            o[268] = fmaf(s1, fmaxf(acc[i][3], 0.f), h1);
        }
    }
    __syncthreads();

    // d3: 32 -> 16
    {
        const int q = tid & 63;
        const int c2base = (tid >> 6) * 4;
        ull acc[4][2];
#pragma unroll
        for (int c2 = 0; c2 < 4; c2++) {
            ull bv = dup2(__ldg(&d3b[c2base + c2]));
            acc[c2][0] = bv; acc[c2][1] = bv;
        }
#pragma unroll 4
        for (int c1 = 0; c1 < 32; c1++) {
            float4 v = *(const float4*)(s_b + c1 * 260 + q * 4);
            ull v0 = pack2(v.x, v.y), v1 = pack2(v.z, v.w);
#pragma unroll
            for (int c2 = 0; c2 < 4; c2++) {
                ull w = dup2(__ldg(&d3w[(c2base + c2) * 32 + c1]));
                fma2(acc[c2][0], w, v0);
                fma2(acc[c2][1], w, v1);
            }
        }
#pragma unroll
        for (int c2 = 0; c2 < 4; c2++) {
            int c = c2base + c2;
            float sc = __ldg(&g_sc[80 + c]), sh = __ldg(&g_sh[80 + c]);
            float2 f0 = unpack2(acc[c2][0]), f1 = unpack2(acc[c2][1]);
            float4 o;
            o.x = fmaf(sc, fmaxf(f0.x, 0.f), sh);
            o.y = fmaf(sc, fmaxf(f0.y, 0.f), sh);
            o.z = fmaf(sc, fmaxf(f1.x, 0.f), sh);
            o.w = fmaf(sc, fmaxf(f1.y, 0.f), sh);
            *(float4*)(s_f + c * 256 + q * 4) = o;
        }
    }
    __syncthreads();

#pragma unroll
    for (int k = 0; k < 4; k++) {
        int o = tid + k * 256;
        int c = o >> 6, q = o & 63;
        int qy = q >> 3, qx = q & 7;
        const float* sp = &s_f[c * 256 + (qy * 2) * 16 + qx * 2];
        float mo = fmaxf(fmaxf(sp[0], sp[1]), fmaxf(sp[16], sp[17]));
        g_x1p[((n * 16 + c) * 256 + by * 8 + qy) * 256 + (bx * 8 + qx)] = mo;
    }
}

// ---------------------------------------------------------------------------
__global__ void __launch_bounds__(256, 4) stage2_kernel(
    const float* __restrict__ cw, const float* __restrict__ cb,
    const float* __restrict__ d1w, const float* __restrict__ d1b,
    const float* __restrict__ d2b,
    const float* __restrict__ d3w, const float* __restrict__ d3b)
{
    extern __shared__ float sm2[];
    float* s_halo = sm2 + 4;
    float* s_f    = sm2;
    float* s_b    = sm2 + 5764;   // stride 260
    float* s_xc   = s_b;          // [8][CS]

    __shared__ float s_wsum[8];
    __shared__ int s_active;

    const int bid = blockIdx.x;
    const int n = bid >> 8, by = (bid >> 4) & 15, bx = bid & 15;
    const int tid = threadIdx.x;
    const int py = tid >> 4, px_ = tid & 15;
    const int gy = by * 16 + py, gx = bx * 16 + px_;

    {
        float mv = g_mask2[(n * 256 + gy) * 256 + gx];
#pragma unroll
        for (int o = 16; o; o >>= 1) mv += __shfl_xor_sync(0xffffffffu, mv, o);
        if ((tid & 31) == 0) s_wsum[tid >> 5] = mv;
    }
    {
        float4 z4 = make_float4(0.f, 0.f, 0.f, 0.f);
        for (int i = tid; i < 1441; i += 256) ((float4*)sm2)[i] = z4;
    }
    __syncthreads();
    if (tid == 0) {
        float t = 0.f;
#pragma unroll
        for (int i = 0; i < 8; i++) t += s_wsum[i];
        s_active = (t > 128.0f) ? 1 : 0;
    }

    {
        const int ibase = ((n * 16) * 256 + gy) * 256 + gx;
        float xin[16];
#pragma unroll
        for (int c = 0; c < 16; c++) xin[c] = g_x1p[ibase + c * 65536];
        const int po = py * RS + px_;
#pragma unroll
        for (int c2 = 0; c2 < 8; c2++) {
            float t = __ldg(&cb[c2]);
#pragma unroll
            for (int c1 = 0; c1 < 16; c1++)
                t = fmaf(xin[c1], __ldg(&cw[c2 * 16 + c1]), t);
            t = fmaxf(t, 0.0f);
            s_xc[c2 * CS + po] = fmaf(__ldg(&g_sc[96 + c2]), t, __ldg(&g_sh[96 + c2]));
        }
    }
    __syncthreads();

    const int act = s_active;
    const int lane = tid & 31, wg = tid >> 5;
    const int prow = lane & 15, pcol = (lane >> 4) * 8;

    if (act) {
        // d1: 8 -> 16 into halo
        {
            const int c2base = wg * 2;
            const int po = prow * RS + pcol;
            ull acc[2][4];
#pragma unroll
            for (int c2 = 0; c2 < 2; c2++) {
                ull bv = dup2(__ldg(&d1b[c2base + c2]));
                acc[c2][0] = bv; acc[c2][1] = bv; acc[c2][2] = bv; acc[c2][3] = bv;
            }
#pragma unroll
            for (int c1 = 0; c1 < 8; c1++) {
                const float* p = s_xc + c1 * CS + po;
                float4 a = *(const float4*)p;
                float4 b = *(const float4*)(p + 4);
                ull va0 = pack2(a.x, a.y), va1 = pack2(a.z, a.w);
                ull vb0 = pack2(b.x, b.y), vb1 = pack2(b.z, b.w);
#pragma unroll
                for (int c2 = 0; c2 < 2; c2++) {
                    ull w = dup2(__ldg(&d1w[(c2base + c2) * 8 + c1]));
                    fma2(acc[c2][0], w, va0);
                    fma2(acc[c2][1], w, va1);
                    fma2(acc[c2][2], w, vb0);
                    fma2(acc[c2][3], w, vb1);
                }
            }
            const int ho = (prow + 1) * 20 + pcol;
#pragma unroll
            for (int c2 = 0; c2 < 2; c2++) {
                int c = c2base + c2;
                float sc = __ldg(&g_sc[104 + c]), sh = __ldg(&g_sh[104 + c]);
                float2 f0 = unpack2(acc[c2][0]), f1 = unpack2(acc[c2][1]);
                float2 f2 = unpack2(acc[c2][2]), f3 = unpack2(acc[c2][3]);
                float4 o0, o1;
                o0.x = fmaf(sc, fmaxf(f0.x, 0.f), sh); o0.y = fmaf(sc, fmaxf(f0.y, 0.f), sh);
                o0.z = fmaf(sc, fmaxf(f1.x, 0.f), sh); o0.w = fmaf(sc, fmaxf(f1.y, 0.f), sh);
                o1.x = fmaf(sc, fmaxf(f2.x, 0.f), sh); o1.y = fmaf(sc, fmaxf(f2.y, 0.f), sh);
                o1.z = fmaf(sc, fmaxf(f3.x, 0.f), sh); o1.w = fmaf(sc, fmaxf(f3.y, 0.f), sh);
                *(float4*)(s_halo + c * 360 + ho)     = o0;
                *(float4*)(s_halo + c * 360 + ho + 4) = o1;
            }
        }
        __syncthreads();

        // d2: 3x3, 16 -> 16 via tf32 mma
        {
            const int tg = lane & 3, q = lane >> 2;
            float acc[4][4];
#pragma unroll
            for (int i = 0; i < 4; i++) {
                int c2 = (i & 1) * 8 + tg * 2;
                float b0 = __ldg(&d2b[c2]), b1 = __ldg(&d2b[c2 + 1]);
                acc[i][0] = b0; acc[i][1] = b1; acc[i][2] = b0; acc[i][3] = b1;
            }
            const float* hp0 = s_halo + tg * 360 + wg * 20 + q - 1;
            const uint4* bh = (const uint4*)g_qhi + lane;
            const uint4* bl = (const uint4*)g_qlo + lane;
#pragma unroll 1
            for (int tap = 0; tap < 9; tap++) {
                int dyq = (tap * 11) >> 5;
                const float* hp = hp0 + tap + 17 * dyq;
#pragma unroll
                for (int kl = 0; kl < 2; kl++) {
                    float av[8];
                    av[0] = hp[0];    av[1] = hp[8];    av[2] = hp[1440]; av[3] = hp[1448];
                    av[4] = hp[160];  av[5] = hp[168];  av[6] = hp[1600]; av[7] = hp[1608];
                    hp += 2880;
                    uint Ah[8], Al[8];
#pragma unroll
                    for (int i = 0; i < 8; i++) {
                        Ah[i] = tf32_rna(av[i]);
                        Al[i] = __float_as_uint(av[i] - __uint_as_float(Ah[i]));
                    }
                    uint4 H = __ldg(bh), L = __ldg(bl);
                    bh += 32; bl += 32;
                    mma8(acc[0], Ah,     H.x, H.y);
                    mma8(acc[0], Ah,     L.x, L.y);
                    mma8(acc[0], Al,     H.x, H.y);
                    mma8(acc[1], Ah,     H.z, H.w);
                    mma8(acc[1], Ah,     L.z, L.w);
                    mma8(acc[1], Al,     H.z, H.w);
                    mma8(acc[2], Ah + 4, H.x, H.y);
                    mma8(acc[2], Ah + 4, L.x, L.y);
                    mma8(acc[2], Al + 4, H.x, H.y);
                    mma8(acc[3], Ah + 4, H.z, H.w);
                    mma8(acc[3], Ah + 4, L.z, L.w);
                    mma8(acc[3], Al + 4, H.z, H.w);
                }
            }
#pragma unroll
            for (int i = 0; i < 4; i++) {
                int mt = i >> 1, nt = i & 1;
                int c2 = nt * 8 + tg * 2;
                float s0 = __ldg(&g_sc[120 + c2]), h0 = __ldg(&g_sh[120 + c2]);
                float s1 = __ldg(&g_sc[121 + c2]), h1 = __ldg(&g_sh[121 + c2]);
                float* o = s_b + c2 * 260 + (wg + mt * 8) * 16 + q;
                o[0]   = fmaf(s0, fmaxf(acc[i][0], 0.f), h0);
                o[260] = fmaf(s1, fmaxf(acc[i][1], 0.f), h1);
                o[8]   = fmaf(s0, fmaxf(acc[i][2], 0.f), h0);
                o[268] = fmaf(s1, fmaxf(acc[i][3], 0.f), h1);
            }
        }
        __syncthreads();

        // d3: 16 -> 8
        {
            const int q = tid & 63;
            const int c2base = (tid >> 6) * 2;
            ull acc[2][2];
#pragma unroll
            for (int c2 = 0; c2 < 2; c2++) {
                ull bv = dup2(__ldg(&d3b[c2base + c2]));
                acc[c2][0] = bv; acc[c2][1] = bv;
            }
#pragma unroll
            for (int c1 = 0; c1 < 16; c1++) {
                float4 v = *(const float4*)(s_b + c1 * 260 + q * 4);
                ull v0 = pack2(v.x, v.y), v1 = pack2(v.z, v.w);
#pragma unroll
                for (int c2 = 0; c2 < 2; c2++) {
                    ull w = dup2(__ldg(&d3w[(c2base + c2) * 16 + c1]));
                    fma2(acc[c2][0], w, v0);
                    fma2(acc[c2][1], w, v1);
                }
            }
#pragma unroll
            for (int c2 = 0; c2 < 2; c2++) {
                int c = c2base + c2;
                float sc = __ldg(&g_sc[136 + c]), sh = __ldg(&g_sh[136 + c]);
                float2 f0 = unpack2(acc[c2][0]), f1 = unpack2(acc[c2][1]);
                float4 o;
                o.x = fmaf(sc, fmaxf(f0.x, 0.f), sh);
                o.y = fmaf(sc, fmaxf(f0.y, 0.f), sh);
                o.z = fmaf(sc, fmaxf(f1.x, 0.f), sh);
                o.w = fmaf(sc, fmaxf(f1.y, 0.f), sh);
                *(float4*)(s_f + c * 256 + q * 4) = o;
            }
        }
        __syncthreads();
    }

    const float* srcp = act ? s_f : s_xc;
    const int chs = act ? 256 : CS;
    const int rs = act ? 16 : RS;
#pragma unroll
    for (int k = 0; k < 2; k++) {
        int o = tid + k * 256;
        int c = o >> 6, q = o & 63;
        int qy = q >> 3, qx = q & 7;
        const float* sp = &srcp[c * chs + (qy * 2) * rs + qx * 2];
        float mo = fmaxf(fmaxf(sp[0], sp[1]), fmaxf(sp[rs], sp[rs + 1]));
        g_x2p[((n * 8 + c) * 128 + by * 8 + qy) * 128 + (bx * 8 + qx)] = mo;
    }
}

// ---------------------------------------------------------------------------
__global__ void __launch_bounds__(256) fc_partial_kernel(const float* __restrict__ fc_w)
{
    const int b = blockIdx.x;
    const int n = b >> 5, s = b & 31;
    const int tid = threadIdx.x;
    const float4* f = (const float4*)(g_x2p + n * 131072 + s * 4096);
    const float4* w = (const float4*)(fc_w) + s * 1024;

    float part[10];
#pragma unroll
    for (int k = 0; k < 10; k++) part[k] = 0.0f;

#pragma unroll
    for (int j = tid; j < 1024; j += 256) {
        float4 fv = f[j];
#pragma unroll
        for (int k = 0; k < 10; k++) {
            float4 wv = __ldg(&w[k * 32768 + j]);
            part[k] += fv.x * wv.x + fv.y * wv.y + fv.z * wv.z + fv.w * wv.w;
        }
    }

    __shared__ float sred[10][256];
#pragma unroll
    for (int k = 0; k < 10; k++) sred[k][tid] = part[k];
    __syncthreads();
    for (int st = 128; st > 0; st >>= 1) {
        if (tid < st) {
#pragma unroll
            for (int k = 0; k < 10; k++) sred[k][tid] += sred[k][tid + st];
        }
        __syncthreads();
    }
    if (tid < 10) g_fcpart[(n * 32 + s) * 10 + tid] = sred[tid][0];
}

__global__ void fc_final_kernel(const float* __restrict__ fc_b, float* __restrict__ out)
{
    const int t = threadIdx.x;
    __shared__ float s_l[16][10];
    if (t < 160) {
        int n = t / 10, k = t - n * 10;
        float a = fc_b[k];
#pragma unroll
        for (int s = 0; s < 32; s++) a += g_fcpart[(n * 32 + s) * 10 + k];
        s_l[n][k] = a;
    }
    __syncthreads();
    if (t < 16) {
        float mx = -1e30f;
#pragma unroll
        for (int k = 0; k < 10; k++) mx = fmaxf(mx, s_l[t][k]);
        float e[10], se = 0.f;
#pragma unroll
        for (int k = 0; k < 10; k++) { e[k] = expf(s_l[t][k] - mx); se += e[k]; }
        float inv = 1.0f / se;
#pragma unroll
        for (int k = 0; k < 10; k++) out[t * 10 + k] = e[k] * inv;
    }
}

// ---------------------------------------------------------------------------
extern "C" void kernel_launch(void* const* d_in, const int* in_sizes, int n_in,
                              void* d_out, int out_size)
{
    const float* x      = (const float*)d_in[0];
    const float* mask   = (const float*)d_in[1];
    const float* s1_cw  = (const float*)d_in[2];
    const float* s1_cb  = (const float*)d_in[3];
    const float* s1_bn0 = (const float*)d_in[4];
    const float* s1_d1w = (const float*)d_in[5];
    const float* s1_d1b = (const float*)d_in[6];
    const float* s1_bn1 = (const float*)d_in[7];
    const float* s1_d2w = (const float*)d_in[8];
    const float* s1_d2b = (const float*)d_in[9];
    const float* s1_bn2 = (const float*)d_in[10];
    const float* s1_d3w = (const float*)d_in[11];
    const float* s1_d3b = (const float*)d_in[12];
    const float* s1_bn3 = (const float*)d_in[13];
    const float* s2_cw  = (const float*)d_in[14];
    const float* s2_cb  = (const float*)d_in[15];
    const float* s2_bn0 = (const float*)d_in[16];
    const float* s2_d1w = (const float*)d_in[17];
    const float* s2_d1b = (const float*)d_in[18];
    const float* s2_bn1 = (const float*)d_in[19];
    const float* s2_d2w = (const float*)d_in[20];
    const float* s2_d2b = (const float*)d_in[21];
    const float* s2_bn2 = (const float*)d_in[22];
    const float* s2_d3w = (const float*)d_in[23];
    const float* s2_d3b = (const float*)d_in[24];
    const float* s2_bn3 = (const float*)d_in[25];
    const float* fc_w   = (const float*)d_in[26];
    const float* fc_b   = (const float*)d_in[27];

    prep_kernel<<<1, 256>>>(s1_d2w, s2_d2w,
                            s1_bn0, s1_bn1, s1_bn2, s1_bn3,
                            s2_bn0, s2_bn1, s2_bn2, s2_bn3);

    stage1_all_kernel<<<16 * 32 * 32, 256>>>(x, mask, s1_cw, s1_cb);

    const int smem1 = 16644 * sizeof(float);   // 66.6 KB -> 3 CTAs/SM
    cudaFuncSetAttribute(stage1_active_kernel, cudaFuncAttributeMaxDynamicSharedMemorySize, smem1);
    stage1_active_kernel<<<16 * 32 * 32, 256, smem1>>>(
        x, s1_cw, s1_cb, s1_d1w, s1_d1b, s1_d2b, s1_d3w, s1_d3b);

    const int smem2 = 9924 * sizeof(float);    // 39.7 KB -> 4 CTAs/SM
    cudaFuncSetAttribute(stage2_kernel, cudaFuncAttributeMaxDynamicSharedMemorySize, smem2);
    stage2_kernel<<<16 * 16 * 16, 256, smem2>>>(
        s2_cw, s2_cb, s2_d1w, s2_d1b, s2_d2b, s2_d3w, s2_d3b);

    fc_partial_kernel<<<512, 256>>>(fc_w);
    fc_final_kernel<<<1, 256>>>(fc_b, (float*)d_out);
}

// round 12
// speedup vs baseline: 1.4493x; 1.1082x over previous
#include <cuda_runtime.h>

#define EPSV 1e-5f
typedef unsigned long long ull;
typedef unsigned int uint;

__device__ float g_x1p[16 * 16 * 256 * 256];
__device__ float g_mask2[16 * 256 * 256];
__device__ float g_x2p[16 * 8 * 128 * 128];
__device__ float g_fcpart[16 * 32 * 10];
__device__ int   g_cnt1;
__device__ int   g_list1[16384];

__device__ __align__(16) float g_bhi[9216];    // stage1 d2 tf32-hi fragments
__device__ __align__(16) float g_blo[9216];    // stage1 d2 tf32-lo fragments
__device__ __align__(16) float g_qhi[2304];    // stage2 d2 tf32-hi fragments
__device__ __align__(16) float g_qlo[2304];    // stage2 d2 tf32-lo fragments
__device__ float g_sc[144], g_sh[144];

__device__ __forceinline__ void fma2(ull& d, ull a, ull b) {
    asm("fma.rn.f32x2 %0, %1, %2, %0;" : "+l"(d) : "l"(a), "l"(b));
}
__device__ __forceinline__ ull pack2(float lo, float hi) {
    ull r; asm("mov.b64 %0, {%1, %2};" : "=l"(r) : "f"(lo), "f"(hi)); return r;
}
__device__ __forceinline__ ull dup2(float v) { return pack2(v, v); }
__device__ __forceinline__ float2 unpack2(ull u) {
    float2 f; asm("mov.b64 {%0, %1}, %2;" : "=f"(f.x), "=f"(f.y) : "l"(u)); return f;
}
__device__ __forceinline__ uint tf32_rna(float v) {
    uint r; asm("cvt.rna.tf32.f32 %0, %1;" : "=r"(r) : "f"(v)); return r;
}
__device__ __forceinline__ void mma8(float* a, const uint* A, uint b0, uint b1) {
    asm volatile("mma.sync.aligned.m16n8k8.row.col.f32.tf32.tf32.f32 "
        "{%0,%1,%2,%3},{%4,%5,%6,%7},{%8,%9},{%0,%1,%2,%3};"
        : "+f"(a[0]), "+f"(a[1]), "+f"(a[2]), "+f"(a[3])
        : "r"(A[0]), "r"(A[1]), "r"(A[2]), "r"(A[3]), "r"(b0), "r"(b1));
}

#define RS 20
#define CS 320

// ---------------------------------------------------------------------------
__global__ void prep_kernel(
    const float* __restrict__ s1d2w, const float* __restrict__ s2d2w,
    const float* __restrict__ b10, const float* __restrict__ b11,
    const float* __restrict__ b12, const float* __restrict__ b13,
    const float* __restrict__ b20, const float* __restrict__ b21,
    const float* __restrict__ b22, const float* __restrict__ b23)
{
    const int tid = threadIdx.x;
    if (tid == 0) g_cnt1 = 0;
    for (int i = tid; i < 9216; i += 256) {
        int kstep = i >> 8, r = i & 255;
        int ln = r >> 3, jj = r & 7;
        int kk = kstep * 8 + (ln & 3) + (jj & 1) * 4;
        int c2 = (jj >> 1) * 8 + (ln >> 2);
        int tap = kk >> 5, c1 = kk & 31;
        float wv = s1d2w[(c2 * 32 + c1) * 9 + tap];
        uint hu = tf32_rna(wv);
        g_bhi[i] = __uint_as_float(hu);
        g_blo[i] = __uint_as_float(tf32_rna(wv - __uint_as_float(hu)));
    }
    for (int i = tid; i < 2304; i += 256) {
        int kstep = i >> 7, r = i & 127;
        int ln = r >> 2, jj = r & 3;
        int kk = kstep * 8 + (ln & 3) + (jj & 1) * 4;
        int c2 = (jj >> 1) * 8 + (ln >> 2);
        int tap = kk >> 4, c1 = kk & 15;
        float wv = s2d2w[(c2 * 16 + c1) * 9 + tap];
        uint hu = tf32_rna(wv);
        g_qhi[i] = __uint_as_float(hu);
        g_qlo[i] = __uint_as_float(tf32_rna(wv - __uint_as_float(hu)));
    }
    if (tid < 144) {
        const float* bp; int c, C;
        if      (tid < 16)  { bp = b10; c = tid;       C = 16; }
        else if (tid < 48)  { bp = b11; c = tid - 16;  C = 32; }
        else if (tid < 80)  { bp = b12; c = tid - 48;  C = 32; }
        else if (tid < 96)  { bp = b13; c = tid - 80;  C = 16; }
        else if (tid < 104) { bp = b20; c = tid - 96;  C = 8;  }
        else if (tid < 120) { bp = b21; c = tid - 104; C = 16; }
        else if (tid < 136) { bp = b22; c = tid - 120; C = 16; }
        else                { bp = b23; c = tid - 136; C = 8;  }
        float g = bp[c], b = bp[C + c], m = bp[2 * C + c], v = bp[3 * C + c];
        float s = g * rsqrtf(v + EPSV);
        g_sc[tid] = s; g_sh[tid] = b - s * m;
    }
}

// ---------------------------------------------------------------------------
__global__ void __launch_bounds__(256) stage1_all_kernel(
    const float* __restrict__ x, const float* __restrict__ mask,
    const float* __restrict__ cw, const float* __restrict__ cb)
{
    __shared__ float s_red[256];
    __shared__ float s_wsum[8];
    __shared__ float s_xc[16 * CS];
    __shared__ int s_active;

    const int bid = blockIdx.x;
    const int n = bid >> 10, by = (bid >> 5) & 31, bx = bid & 31;
    const int tid = threadIdx.x;
    const int py = tid >> 4, px_ = tid & 15;
    const int gy = by * 16 + py, gx = bx * 16 + px_;

    float mval = mask[(n * 512 + gy) * 512 + gx];
    s_red[tid] = mval;
    float msum = mval;
#pragma unroll
    for (int o = 16; o; o >>= 1) msum += __shfl_xor_sync(0xffffffffu, msum, o);
    if ((tid & 31) == 0) s_wsum[tid >> 5] = msum;
    __syncthreads();

    if (tid < 64) {
        int qy = tid >> 3, qx = tid & 7;
        int p0 = (qy * 2) * 16 + qx * 2;
        float m0 = fmaxf(fmaxf(s_red[p0], s_red[p0 + 1]),
                         fmaxf(s_red[p0 + 16], s_red[p0 + 17]));
        g_mask2[(n * 256 + by * 8 + qy) * 256 + (bx * 8 + qx)] = m0;
    }
    if (tid == 0) {
        float t = 0.f;
#pragma unroll
        for (int i = 0; i < 8; i++) t += s_wsum[i];
        int act = (t > 128.0f) ? 1 : 0;
        s_active = act;
        if (act) { int pos = atomicAdd(&g_cnt1, 1); g_list1[pos] = bid; }
    }
    __syncthreads();
    if (s_active) return;

    {
        const int ibase = ((n * 3) * 512 + gy) * 512 + gx;
        float xv0 = x[ibase];
        float xv1 = x[ibase + 512 * 512];
        float xv2 = x[ibase + 2 * 512 * 512];
        const int po = py * RS + px_;
#pragma unroll
        for (int c = 0; c < 16; c++) {
            float t = __ldg(&cw[c * 3 + 0]) * xv0 + __ldg(&cw[c * 3 + 1]) * xv1 +
                      __ldg(&cw[c * 3 + 2]) * xv2 + __ldg(&cb[c]);
            t = fmaxf(t, 0.0f);
            s_xc[c * CS + po] = fmaf(__ldg(&g_sc[c]), t, __ldg(&g_sh[c]));
        }
    }
    __syncthreads();

#pragma unroll
    for (int k = 0; k < 4; k++) {
        int o = tid + k * 256;
        int c = o >> 6, q = o & 63;
        int qy = q >> 3, qx = q & 7;
        const float* sp = &s_xc[c * CS + (qy * 2) * RS + qx * 2];
        float mo = fmaxf(fmaxf(sp[0], sp[1]), fmaxf(sp[RS], sp[RS + 1]));
        g_x1p[((n * 16 + c) * 256 + by * 8 + qy) * 256 + (bx * 8 + qx)] = mo;
    }
}

// ---------------------------------------------------------------------------
// Stage 1b: 3 CTAs/SM; d2 now 2-term (Ah x (Bh+Bl)) — activation-side
// tf32 quantization only (~1e-4 rel, threshold 1e-3).
// ---------------------------------------------------------------------------
__global__ void __launch_bounds__(256, 3) stage1_active_kernel(
    const float* __restrict__ x,
    const float* __restrict__ cw, const float* __restrict__ cb,
    const float* __restrict__ d1w, const float* __restrict__ d1b,
    const float* __restrict__ d2b,
    const float* __restrict__ d3w, const float* __restrict__ d3b)
{
    if ((int)blockIdx.x >= g_cnt1) return;
    const int bid = g_list1[blockIdx.x];

    extern __shared__ float sm[];
    float* s_halo = sm + 4;
    float* s_xc   = sm + 11524;   // [16][CS]
    float* s_b    = sm + 4;       // [32][260], reuses halo after sync
    float* s_f    = sm + 8324;    // [16][256]

    const int n = bid >> 10, by = (bid >> 5) & 31, bx = bid & 31;
    const int tid = threadIdx.x;
    const int py = tid >> 4, px_ = tid & 15;
    const int gy = by * 16 + py, gx = bx * 16 + px_;

    {
        float4 z4 = make_float4(0.f, 0.f, 0.f, 0.f);
        for (int i = tid; i < 2881; i += 256) ((float4*)sm)[i] = z4;
    }
    {
        const int ibase = ((n * 3) * 512 + gy) * 512 + gx;
        float xv0 = x[ibase];
        float xv1 = x[ibase + 512 * 512];
        float xv2 = x[ibase + 2 * 512 * 512];
        const int po = py * RS + px_;
#pragma unroll
        for (int c = 0; c < 16; c++) {
            float t = __ldg(&cw[c * 3 + 0]) * xv0 + __ldg(&cw[c * 3 + 1]) * xv1 +
                      __ldg(&cw[c * 3 + 2]) * xv2 + __ldg(&cb[c]);
            t = fmaxf(t, 0.0f);
            s_xc[c * CS + po] = fmaf(__ldg(&g_sc[c]), t, __ldg(&g_sh[c]));
        }
    }
    __syncthreads();

    const int lane = tid & 31, wg = tid >> 5;
    const int prow = lane & 15, pcol = (lane >> 4) * 8;

    // d1: 16 -> 32 into halo
    {
        const int c2base = wg * 4;
        ull acc[4][4];
#pragma unroll
        for (int c2 = 0; c2 < 4; c2++) {
            ull bv = dup2(__ldg(&d1b[c2base + c2]));
            acc[c2][0] = bv; acc[c2][1] = bv; acc[c2][2] = bv; acc[c2][3] = bv;
        }
        const int po = prow * RS + pcol;
#pragma unroll
        for (int c1 = 0; c1 < 16; c1++) {
            const float* p = s_xc + c1 * CS + po;
            float4 a = *(const float4*)p;
            float4 b = *(const float4*)(p + 4);
            ull va0 = pack2(a.x, a.y), va1 = pack2(a.z, a.w);
            ull vb0 = pack2(b.x, b.y), vb1 = pack2(b.z, b.w);
#pragma unroll
            for (int c2 = 0; c2 < 4; c2++) {
                ull w = dup2(__ldg(&d1w[(c2base + c2) * 16 + c1]));
                fma2(acc[c2][0], w, va0);
                fma2(acc[c2][1], w, va1);
                fma2(acc[c2][2], w, vb0);
                fma2(acc[c2][3], w, vb1);
            }
        }
        const int ho = (prow + 1) * 20 + pcol;
#pragma unroll
        for (int c2 = 0; c2 < 4; c2++) {
            int c = c2base + c2;
            float sc = __ldg(&g_sc[16 + c]), sh = __ldg(&g_sh[16 + c]);
            float4 o0, o1;
            float2 f0 = unpack2(acc[c2][0]), f1 = unpack2(acc[c2][1]);
            float2 f2 = unpack2(acc[c2][2]), f3 = unpack2(acc[c2][3]);
            o0.x = fmaf(sc, fmaxf(f0.x, 0.f), sh); o0.y = fmaf(sc, fmaxf(f0.y, 0.f), sh);
            o0.z = fmaf(sc, fmaxf(f1.x, 0.f), sh); o0.w = fmaf(sc, fmaxf(f1.y, 0.f), sh);
            o1.x = fmaf(sc, fmaxf(f2.x, 0.f), sh); o1.y = fmaf(sc, fmaxf(f2.y, 0.f), sh);
            o1.z = fmaf(sc, fmaxf(f3.x, 0.f), sh); o1.w = fmaf(sc, fmaxf(f3.y, 0.f), sh);
            *(float4*)(s_halo + c * 360 + ho)     = o0;
            *(float4*)(s_halo + c * 360 + ho + 4) = o1;
        }
    }
    __syncthreads();

    // d2: tf32 mma 2-term (Ah x Bh + Ah x Bl)
    {
        const int tg = lane & 3, q = lane >> 2;
        float acc[8][4];
#pragma unroll
        for (int i = 0; i < 8; i++) {
            int c2 = (i & 3) * 8 + tg * 2;
            float b0 = __ldg(&d2b[c2]), b1 = __ldg(&d2b[c2 + 1]);
            acc[i][0] = b0; acc[i][1] = b1; acc[i][2] = b0; acc[i][3] = b1;
        }
        const float* hp0 = s_halo + tg * 360 + wg * 20 + q - 1;
        const uint4* bh = (const uint4*)g_bhi + lane * 2;
        const uint4* bl = (const uint4*)g_blo + lane * 2;
#pragma unroll 1
        for (int tap = 0; tap < 9; tap++) {
            int dyq = (tap * 11) >> 5;
            const float* hp = hp0 + tap + 17 * dyq;
#pragma unroll
            for (int kl = 0; kl < 4; kl++) {
                float av[8];
                av[0] = hp[0];    av[1] = hp[8];    av[2] = hp[1440]; av[3] = hp[1448];
                av[4] = hp[160];  av[5] = hp[168];  av[6] = hp[1600]; av[7] = hp[1608];
                hp += 2880;
                uint Ah[8];
#pragma unroll
                for (int i = 0; i < 8; i++) Ah[i] = tf32_rna(av[i]);
                uint4 H0 = __ldg(bh), H1 = __ldg(bh + 1);
                uint4 L0 = __ldg(bl), L1 = __ldg(bl + 1);
                bh += 64; bl += 64;
                uint BH[8] = {H0.x, H0.y, H0.z, H0.w, H1.x, H1.y, H1.z, H1.w};
                uint BL[8] = {L0.x, L0.y, L0.z, L0.w, L1.x, L1.y, L1.z, L1.w};
#pragma unroll
                for (int nt = 0; nt < 4; nt++) {
                    mma8(acc[nt],     Ah,     BH[2*nt], BH[2*nt+1]);
                    mma8(acc[nt],     Ah,     BL[2*nt], BL[2*nt+1]);
                    mma8(acc[nt + 4], Ah + 4, BH[2*nt], BH[2*nt+1]);
                    mma8(acc[nt + 4], Ah + 4, BL[2*nt], BL[2*nt+1]);
                }
            }
        }
        __syncthreads();   // all halo reads done; s_b may now overwrite it
#pragma unroll
        for (int i = 0; i < 8; i++) {
            int mt = i >> 2, nt = i & 3;
            int c2 = nt * 8 + tg * 2;
            float s0 = __ldg(&g_sc[48 + c2]), h0 = __ldg(&g_sh[48 + c2]);
            float s1 = __ldg(&g_sc[49 + c2]), h1 = __ldg(&g_sh[49 + c2]);
            float* o = s_b + c2 * 260 + (wg + mt * 8) * 16 + q;
            o[0]   = fmaf(s0, fmaxf(acc[i][0], 0.f), h0);
            o[260] = fmaf(s1, fmaxf(acc[i][1], 0.f), h1);
            o[8]   = fmaf(s0, fmaxf(acc[i][2], 0.f), h0);
            o[268] = fmaf(s1, fmaxf(acc[i][3], 0.f), h1);
        }
    }
    __syncthreads();

    // d3: 32 -> 16
    {
        const int q = tid & 63;
        const int c2base = (tid >> 6) * 4;
        ull acc[4][2];
#pragma unroll
        for (int c2 = 0; c2 < 4; c2++) {
            ull bv = dup2(__ldg(&d3b[c2base + c2]));
            acc[c2][0] = bv; acc[c2][1] = bv;
        }
#pragma unroll 4
        for (int c1 = 0; c1 < 32; c1++) {
            float4 v = *(const float4*)(s_b + c1 * 260 + q * 4);
            ull v0 = pack2(v.x, v.y), v1 = pack2(v.z, v.w);
#pragma unroll
            for (int c2 = 0; c2 < 4; c2++) {
                ull w = dup2(__ldg(&d3w[(c2base + c2) * 32 + c1]));
                fma2(acc[c2][0], w, v0);
                fma2(acc[c2][1], w, v1);
            }
        }
#pragma unroll
        for (int c2 = 0; c2 < 4; c2++) {
            int c = c2base + c2;
            float sc = __ldg(&g_sc[80 + c]), sh = __ldg(&g_sh[80 + c]);
            float2 f0 = unpack2(acc[c2][0]), f1 = unpack2(acc[c2][1]);
            float4 o;
            o.x = fmaf(sc, fmaxf(f0.x, 0.f), sh);
            o.y = fmaf(sc, fmaxf(f0.y, 0.f), sh);
            o.z = fmaf(sc, fmaxf(f1.x, 0.f), sh);
            o.w = fmaf(sc, fmaxf(f1.y, 0.f), sh);
            *(float4*)(s_f + c * 256 + q * 4) = o;
        }
    }
    __syncthreads();

#pragma unroll
    for (int k = 0; k < 4; k++) {
        int o = tid + k * 256;
        int c = o >> 6, q = o & 63;
        int qy = q >> 3, qx = q & 7;
        const float* sp = &s_f[c * 256 + (qy * 2) * 16 + qx * 2];
        float mo = fmaxf(fmaxf(sp[0], sp[1]), fmaxf(sp[16], sp[17]));
        g_x1p[((n * 16 + c) * 256 + by * 8 + qy) * 256 + (bx * 8 + qx)] = mo;
    }
}

// ---------------------------------------------------------------------------
__global__ void __launch_bounds__(256, 4) stage2_kernel(
    const float* __restrict__ cw, const float* __restrict__ cb,
    const float* __restrict__ d1w, const float* __restrict__ d1b,
    const float* __restrict__ d2b,
    const float* __restrict__ d3w, const float* __restrict__ d3b)
{
    extern __shared__ float sm2[];
    float* s_halo = sm2 + 4;
    float* s_f    = sm2;
    float* s_b    = sm2 + 5764;   // stride 260
    float* s_xc   = s_b;          // [8][CS]

    __shared__ float s_wsum[8];
    __shared__ int s_active;

    const int bid = blockIdx.x;
    const int n = bid >> 8, by = (bid >> 4) & 15, bx = bid & 15;
    const int tid = threadIdx.x;
    const int py = tid >> 4, px_ = tid & 15;
    const int gy = by * 16 + py, gx = bx * 16 + px_;

    {
        float mv = g_mask2[(n * 256 + gy) * 256 + gx];
#pragma unroll
        for (int o = 16; o; o >>= 1) mv += __shfl_xor_sync(0xffffffffu, mv, o);
        if ((tid & 31) == 0) s_wsum[tid >> 5] = mv;
    }
    {
        float4 z4 = make_float4(0.f, 0.f, 0.f, 0.f);
        for (int i = tid; i < 1441; i += 256) ((float4*)sm2)[i] = z4;
    }
    __syncthreads();
    if (tid == 0) {
        float t = 0.f;
#pragma unroll
        for (int i = 0; i < 8; i++) t += s_wsum[i];
        s_active = (t > 128.0f) ? 1 : 0;
    }

    {
        const int ibase = ((n * 16) * 256 + gy) * 256 + gx;
        float xin[16];
#pragma unroll
        for (int c = 0; c < 16; c++) xin[c] = g_x1p[ibase + c * 65536];
        const int po = py * RS + px_;
#pragma unroll
        for (int c2 = 0; c2 < 8; c2++) {
            float t = __ldg(&cb[c2]);
#pragma unroll
            for (int c1 = 0; c1 < 16; c1++)
                t = fmaf(xin[c1], __ldg(&cw[c2 * 16 + c1]), t);
            t = fmaxf(t, 0.0f);
            s_xc[c2 * CS + po] = fmaf(__ldg(&g_sc[96 + c2]), t, __ldg(&g_sh[96 + c2]));
        }
    }
    __syncthreads();

    const int act = s_active;
    const int lane = tid & 31, wg = tid >> 5;
    const int prow = lane & 15, pcol = (lane >> 4) * 8;

    if (act) {
        // d1: 8 -> 16 into halo
        {
            const int c2base = wg * 2;
            const int po = prow * RS + pcol;
            ull acc[2][4];
#pragma unroll
            for (int c2 = 0; c2 < 2; c2++) {
                ull bv = dup2(__ldg(&d1b[c2base + c2]));
                acc[c2][0] = bv; acc[c2][1] = bv; acc[c2][2] = bv; acc[c2][3] = bv;
            }
#pragma unroll
            for (int c1 = 0; c1 < 8; c1++) {
                const float* p = s_xc + c1 * CS + po;
                float4 a = *(const float4*)p;
                float4 b = *(const float4*)(p + 4);
                ull va0 = pack2(a.x, a.y), va1 = pack2(a.z, a.w);
                ull vb0 = pack2(b.x, b.y), vb1 = pack2(b.z, b.w);
#pragma unroll
                for (int c2 = 0; c2 < 2; c2++) {
                    ull w = dup2(__ldg(&d1w[(c2base + c2) * 8 + c1]));
                    fma2(acc[c2][0], w, va0);
                    fma2(acc[c2][1], w, va1);
                    fma2(acc[c2][2], w, vb0);
                    fma2(acc[c2][3], w, vb1);
                }
            }
            const int ho = (prow + 1) * 20 + pcol;
#pragma unroll
            for (int c2 = 0; c2 < 2; c2++) {
                int c = c2base + c2;
                float sc = __ldg(&g_sc[104 + c]), sh = __ldg(&g_sh[104 + c]);
                float2 f0 = unpack2(acc[c2][0]), f1 = unpack2(acc[c2][1]);
                float2 f2 = unpack2(acc[c2][2]), f3 = unpack2(acc[c2][3]);
                float4 o0, o1;
                o0.x = fmaf(sc, fmaxf(f0.x, 0.f), sh); o0.y = fmaf(sc, fmaxf(f0.y, 0.f), sh);
                o0.z = fmaf(sc, fmaxf(f1.x, 0.f), sh); o0.w = fmaf(sc, fmaxf(f1.y, 0.f), sh);
                o1.x = fmaf(sc, fmaxf(f2.x, 0.f), sh); o1.y = fmaf(sc, fmaxf(f2.y, 0.f), sh);
                o1.z = fmaf(sc, fmaxf(f3.x, 0.f), sh); o1.w = fmaf(sc, fmaxf(f3.y, 0.f), sh);
                *(float4*)(s_halo + c * 360 + ho)     = o0;
                *(float4*)(s_halo + c * 360 + ho + 4) = o1;
            }
        }
        __syncthreads();

        // d2: 3x3, 16 -> 16 via tf32 mma (2-term)
        {
            const int tg = lane & 3, q = lane >> 2;
            float acc[4][4];
#pragma unroll
            for (int i = 0; i < 4; i++) {
                int c2 = (i & 1) * 8 + tg * 2;
                float b0 = __ldg(&d2b[c2]), b1 = __ldg(&d2b[c2 + 1]);
                acc[i][0] = b0; acc[i][1] = b1; acc[i][2] = b0; acc[i][3] = b1;
            }
            const float* hp0 = s_halo + tg * 360 + wg * 20 + q - 1;
            const uint4* bh = (const uint4*)g_qhi + lane;
            const uint4* bl = (const uint4*)g_qlo + lane;
#pragma unroll 1
            for (int tap = 0; tap < 9; tap++) {
                int dyq = (tap * 11) >> 5;
                const float* hp = hp0 + tap + 17 * dyq;
#pragma unroll
                for (int kl = 0; kl < 2; kl++) {
                    float av[8];
                    av[0] = hp[0];    av[1] = hp[8];    av[2] = hp[1440]; av[3] = hp[1448];
                    av[4] = hp[160];  av[5] = hp[168];  av[6] = hp[1600]; av[7] = hp[1608];
                    hp += 2880;
                    uint Ah[8];
#pragma unroll
                    for (int i = 0; i < 8; i++) Ah[i] = tf32_rna(av[i]);
                    uint4 H = __ldg(bh), L = __ldg(bl);
                    bh += 32; bl += 32;
                    mma8(acc[0], Ah,     H.x, H.y);
                    mma8(acc[0], Ah,     L.x, L.y);
                    mma8(acc[1], Ah,     H.z, H.w);
                    mma8(acc[1], Ah,     L.z, L.w);
                    mma8(acc[2], Ah + 4, H.x, H.y);
                    mma8(acc[2], Ah + 4, L.x, L.y);
                    mma8(acc[3], Ah + 4, H.z, H.w);
                    mma8(acc[3], Ah + 4, L.z, L.w);
                }
            }
#pragma unroll
            for (int i = 0; i < 4; i++) {
                int mt = i >> 1, nt = i & 1;
                int c2 = nt * 8 + tg * 2;
                float s0 = __ldg(&g_sc[120 + c2]), h0 = __ldg(&g_sh[120 + c2]);
                float s1 = __ldg(&g_sc[121 + c2]), h1 = __ldg(&g_sh[121 + c2]);
                float* o = s_b + c2 * 260 + (wg + mt * 8) * 16 + q;
                o[0]   = fmaf(s0, fmaxf(acc[i][0], 0.f), h0);
                o[260] = fmaf(s1, fmaxf(acc[i][1], 0.f), h1);
                o[8]   = fmaf(s0, fmaxf(acc[i][2], 0.f), h0);
                o[268] = fmaf(s1, fmaxf(acc[i][3], 0.f), h1);
            }
        }
        __syncthreads();

        // d3: 16 -> 8
        {
            const int q = tid & 63;
            const int c2base = (tid >> 6) * 2;
            ull acc[2][2];
#pragma unroll
            for (int c2 = 0; c2 < 2; c2++) {
                ull bv = dup2(__ldg(&d3b[c2base + c2]));
                acc[c2][0] = bv; acc[c2][1] = bv;
            }
#pragma unroll
            for (int c1 = 0; c1 < 16; c1++) {
                float4 v = *(const float4*)(s_b + c1 * 260 + q * 4);
                ull v0 = pack2(v.x, v.y), v1 = pack2(v.z, v.w);
#pragma unroll
                for (int c2 = 0; c2 < 2; c2++) {
                    ull w = dup2(__ldg(&d3w[(c2base + c2) * 16 + c1]));
                    fma2(acc[c2][0], w, v0);
                    fma2(acc[c2][1], w, v1);
                }
            }
#pragma unroll
            for (int c2 = 0; c2 < 2; c2++) {
                int c = c2base + c2;
                float sc = __ldg(&g_sc[136 + c]), sh = __ldg(&g_sh[136 + c]);
                float2 f0 = unpack2(acc[c2][0]), f1 = unpack2(acc[c2][1]);
                float4 o;
                o.x = fmaf(sc, fmaxf(f0.x, 0.f), sh);
                o.y = fmaf(sc, fmaxf(f0.y, 0.f), sh);
                o.z = fmaf(sc, fmaxf(f1.x, 0.f), sh);
                o.w = fmaf(sc, fmaxf(f1.y, 0.f), sh);
                *(float4*)(s_f + c * 256 + q * 4) = o;
            }
        }
        __syncthreads();
    }

    const float* srcp = act ? s_f : s_xc;
    const int chs = act ? 256 : CS;
    const int rs = act ? 16 : RS;
#pragma unroll
    for (int k = 0; k < 2; k++) {
        int o = tid + k * 256;
        int c = o >> 6, q = o & 63;
        int qy = q >> 3, qx = q & 7;
        const float* sp = &srcp[c * chs + (qy * 2) * rs + qx * 2];
        float mo = fmaxf(fmaxf(sp[0], sp[1]), fmaxf(sp[rs], sp[rs + 1]));
        g_x2p[((n * 8 + c) * 128 + by * 8 + qy) * 128 + (bx * 8 + qx)] = mo;
    }
}

// ---------------------------------------------------------------------------
__global__ void __launch_bounds__(256) fc_partial_kernel(const float* __restrict__ fc_w)
{
    const int b = blockIdx.x;
    const int n = b >> 5, s = b & 31;
    const int tid = threadIdx.x;
    const float4* f = (const float4*)(g_x2p + n * 131072 + s * 4096);
    const float4* w = (const float4*)(fc_w) + s * 1024;

    float part[10];
#pragma unroll
    for (int k = 0; k < 10; k++) part[k] = 0.0f;

#pragma unroll
    for (int j = tid; j < 1024; j += 256) {
        float4 fv = f[j];
#pragma unroll
        for (int k = 0; k < 10; k++) {
            float4 wv = __ldg(&w[k * 32768 + j]);
            part[k] += fv.x * wv.x + fv.y * wv.y + fv.z * wv.z + fv.w * wv.w;
        }
    }

    __shared__ float sred[10][256];
#pragma unroll
    for (int k = 0; k < 10; k++) sred[k][tid] = part[k];
    __syncthreads();
    for (int st = 128; st > 0; st >>= 1) {
        if (tid < st) {
#pragma unroll
            for (int k = 0; k < 10; k++) sred[k][tid] += sred[k][tid + st];
        }
        __syncthreads();
    }
    if (tid < 10) g_fcpart[(n * 32 + s) * 10 + tid] = sred[tid][0];
}

__global__ void fc_final_kernel(const float* __restrict__ fc_b, float* __restrict__ out)
{
    const int t = threadIdx.x;
    __shared__ float s_l[16][10];
    if (t < 160) {
        int n = t / 10, k = t - n * 10;
        float a = fc_b[k];
#pragma unroll
        for (int s = 0; s < 32; s++) a += g_fcpart[(n * 32 + s) * 10 + k];
        s_l[n][k] = a;
    }
    __syncthreads();
    if (t < 16) {
        float mx = -1e30f;
#pragma unroll
        for (int k = 0; k < 10; k++) mx = fmaxf(mx, s_l[t][k]);
        float e[10], se = 0.f;
#pragma unroll
        for (int k = 0; k < 10; k++) { e[k] = expf(s_l[t][k] - mx); se += e[k]; }
        float inv = 1.0f / se;
#pragma unroll
        for (int k = 0; k < 10; k++) out[t * 10 + k] = e[k] * inv;
    }
}

// ---------------------------------------------------------------------------
extern "C" void kernel_launch(void* const* d_in, const int* in_sizes, int n_in,
                              void* d_out, int out_size)
{
    const float* x      = (const float*)d_in[0];
    const float* mask   = (const float*)d_in[1];
    const float* s1_cw  = (const float*)d_in[2];
    const float* s1_cb  = (const float*)d_in[3];
    const float* s1_bn0 = (const float*)d_in[4];
    const float* s1_d1w = (const float*)d_in[5];
    const float* s1_d1b = (const float*)d_in[6];
    const float* s1_bn1 = (const float*)d_in[7];
    const float* s1_d2w = (const float*)d_in[8];
    const float* s1_d2b = (const float*)d_in[9];
    const float* s1_bn2 = (const float*)d_in[10];
    const float* s1_d3w = (const float*)d_in[11];
    const float* s1_d3b = (const float*)d_in[12];
    const float* s1_bn3 = (const float*)d_in[13];
    const float* s2_cw  = (const float*)d_in[14];
    const float* s2_cb  = (const float*)d_in[15];
    const float* s2_bn0 = (const float*)d_in[16];
    const float* s2_d1w = (const float*)d_in[17];
    const float* s2_d1b = (const float*)d_in[18];
    const float* s2_bn1 = (const float*)d_in[19];
    const float* s2_d2w = (const float*)d_in[20];
    const float* s2_d2b = (const float*)d_in[21];
    const float* s2_bn2 = (const float*)d_in[22];
    const float* s2_d3w = (const float*)d_in[23];
    const float* s2_d3b = (const float*)d_in[24];
    const float* s2_bn3 = (const float*)d_in[25];
    const float* fc_w   = (const float*)d_in[26];
    const float* fc_b   = (const float*)d_in[27];

    prep_kernel<<<1, 256>>>(s1_d2w, s2_d2w,
                            s1_bn0, s1_bn1, s1_bn2, s1_bn3,
                            s2_bn0, s2_bn1, s2_bn2, s2_bn3);

    stage1_all_kernel<<<16 * 32 * 32, 256>>>(x, mask, s1_cw, s1_cb);

    const int smem1 = 16644 * sizeof(float);   // 66.6 KB -> 3 CTAs/SM
    cudaFuncSetAttribute(stage1_active_kernel, cudaFuncAttributeMaxDynamicSharedMemorySize, smem1);
    stage1_active_kernel<<<16 * 32 * 32, 256, smem1>>>(
        x, s1_cw, s1_cb, s1_d1w, s1_d1b, s1_d2b, s1_d3w, s1_d3b);

    const int smem2 = 9924 * sizeof(float);    // 39.7 KB -> 4 CTAs/SM
    cudaFuncSetAttribute(stage2_kernel, cudaFuncAttributeMaxDynamicSharedMemorySize, smem2);
    stage2_kernel<<<16 * 16 * 16, 256, smem2>>>(
        s2_cw, s2_cb, s2_d1w, s2_d1b, s2_d2b, s2_d3w, s2_d3b);

    fc_partial_kernel<<<512, 256>>>(fc_w);
    fc_final_kernel<<<1, 256>>>(fc_b, (float*)d_out);
}

// round 13
// speedup vs baseline: 1.4499x; 1.0004x over previous
#include <cuda_runtime.h>

#define EPSV 1e-5f
typedef unsigned long long ull;
typedef unsigned int uint;

__device__ float g_x1p[16 * 16 * 256 * 256];
__device__ float g_mask2[16 * 256 * 256];
__device__ float g_x2p[16 * 8 * 128 * 128];
__device__ float g_fcpart[16 * 32 * 10];
__device__ int   g_cnt1;
__device__ int   g_list1[16384];

__device__ __align__(16) float g_bhi[9216];    // stage1 d2 tf32-hi fragments
__device__ __align__(16) float g_blo[9216];    // stage1 d2 tf32-lo fragments
__device__ __align__(16) float g_qhi[2304];    // stage2 d2 tf32-hi fragments
__device__ __align__(16) float g_qlo[2304];    // stage2 d2 tf32-lo fragments
__device__ float g_sc[144], g_sh[144];

__device__ __forceinline__ void fma2(ull& d, ull a, ull b) {
    asm("fma.rn.f32x2 %0, %1, %2, %0;" : "+l"(d) : "l"(a), "l"(b));
}
__device__ __forceinline__ ull pack2(float lo, float hi) {
    ull r; asm("mov.b64 %0, {%1, %2};" : "=l"(r) : "f"(lo), "f"(hi)); return r;
}
__device__ __forceinline__ ull dup2(float v) { return pack2(v, v); }
__device__ __forceinline__ float2 unpack2(ull u) {
    float2 f; asm("mov.b64 {%0, %1}, %2;" : "=f"(f.x), "=f"(f.y) : "l"(u)); return f;
}
__device__ __forceinline__ uint tf32_rna(float v) {
    uint r; asm("cvt.rna.tf32.f32 %0, %1;" : "=r"(r) : "f"(v)); return r;
}
__device__ __forceinline__ float tf32f(float v) {
    return __uint_as_float(tf32_rna(v));
}
__device__ __forceinline__ void mma8(float* a, const uint* A, uint b0, uint b1) {
    asm volatile("mma.sync.aligned.m16n8k8.row.col.f32.tf32.tf32.f32 "
        "{%0,%1,%2,%3},{%4,%5,%6,%7},{%8,%9},{%0,%1,%2,%3};"
        : "+f"(a[0]), "+f"(a[1]), "+f"(a[2]), "+f"(a[3])
        : "r"(A[0]), "r"(A[1]), "r"(A[2]), "r"(A[3]), "r"(b0), "r"(b1));
}

#define RS 20
#define CS 320

// ---------------------------------------------------------------------------
__global__ void prep_kernel(
    const float* __restrict__ s1d2w, const float* __restrict__ s2d2w,
    const float* __restrict__ b10, const float* __restrict__ b11,
    const float* __restrict__ b12, const float* __restrict__ b13,
    const float* __restrict__ b20, const float* __restrict__ b21,
    const float* __restrict__ b22, const float* __restrict__ b23)
{
    const int tid = threadIdx.x;
    if (tid == 0) g_cnt1 = 0;
    for (int i = tid; i < 9216; i += 256) {
        int kstep = i >> 8, r = i & 255;
        int ln = r >> 3, jj = r & 7;
        int kk = kstep * 8 + (ln & 3) + (jj & 1) * 4;
        int c2 = (jj >> 1) * 8 + (ln >> 2);
        int tap = kk >> 5, c1 = kk & 31;
        float wv = s1d2w[(c2 * 32 + c1) * 9 + tap];
        uint hu = tf32_rna(wv);
        g_bhi[i] = __uint_as_float(hu);
        g_blo[i] = __uint_as_float(tf32_rna(wv - __uint_as_float(hu)));
    }
    for (int i = tid; i < 2304; i += 256) {
        int kstep = i >> 7, r = i & 127;
        int ln = r >> 2, jj = r & 3;
        int kk = kstep * 8 + (ln & 3) + (jj & 1) * 4;
        int c2 = (jj >> 1) * 8 + (ln >> 2);
        int tap = kk >> 4, c1 = kk & 15;
        float wv = s2d2w[(c2 * 16 + c1) * 9 + tap];
        uint hu = tf32_rna(wv);
        g_qhi[i] = __uint_as_float(hu);
        g_qlo[i] = __uint_as_float(tf32_rna(wv - __uint_as_float(hu)));
    }
    if (tid < 144) {
        const float* bp; int c, C;
        if      (tid < 16)  { bp = b10; c = tid;       C = 16; }
        else if (tid < 48)  { bp = b11; c = tid - 16;  C = 32; }
        else if (tid < 80)  { bp = b12; c = tid - 48;  C = 32; }
        else if (tid < 96)  { bp = b13; c = tid - 80;  C = 16; }
        else if (tid < 104) { bp = b20; c = tid - 96;  C = 8;  }
        else if (tid < 120) { bp = b21; c = tid - 104; C = 16; }
        else if (tid < 136) { bp = b22; c = tid - 120; C = 16; }
        else                { bp = b23; c = tid - 136; C = 8;  }
        float g = bp[c], b = bp[C + c], m = bp[2 * C + c], v = bp[3 * C + c];
        float s = g * rsqrtf(v + EPSV);
        g_sc[tid] = s; g_sh[tid] = b - s * m;
    }
}

// ---------------------------------------------------------------------------
__global__ void __launch_bounds__(256) stage1_all_kernel(
    const float* __restrict__ x, const float* __restrict__ mask,
    const float* __restrict__ cw, const float* __restrict__ cb)
{
    __shared__ float s_red[256];
    __shared__ float s_wsum[8];
    __shared__ float s_xc[16 * CS];
    __shared__ int s_active;

    const int bid = blockIdx.x;
    const int n = bid >> 10, by = (bid >> 5) & 31, bx = bid & 31;
    const int tid = threadIdx.x;
    const int py = tid >> 4, px_ = tid & 15;
    const int gy = by * 16 + py, gx = bx * 16 + px_;

    float mval = mask[(n * 512 + gy) * 512 + gx];
    s_red[tid] = mval;
    float msum = mval;
#pragma unroll
    for (int o = 16; o; o >>= 1) msum += __shfl_xor_sync(0xffffffffu, msum, o);
    if ((tid & 31) == 0) s_wsum[tid >> 5] = msum;
    __syncthreads();

    if (tid < 64) {
        int qy = tid >> 3, qx = tid & 7;
        int p0 = (qy * 2) * 16 + qx * 2;
        float m0 = fmaxf(fmaxf(s_red[p0], s_red[p0 + 1]),
                         fmaxf(s_red[p0 + 16], s_red[p0 + 17]));
        g_mask2[(n * 256 + by * 8 + qy) * 256 + (bx * 8 + qx)] = m0;
    }
    if (tid == 0) {
        float t = 0.f;
#pragma unroll
        for (int i = 0; i < 8; i++) t += s_wsum[i];
        int act = (t > 128.0f) ? 1 : 0;
        s_active = act;
        if (act) { int pos = atomicAdd(&g_cnt1, 1); g_list1[pos] = bid; }
    }
    __syncthreads();
    if (s_active) return;

    {
        const int ibase = ((n * 3) * 512 + gy) * 512 + gx;
        float xv0 = x[ibase];
        float xv1 = x[ibase + 512 * 512];
        float xv2 = x[ibase + 2 * 512 * 512];
        const int po = py * RS + px_;
#pragma unroll
        for (int c = 0; c < 16; c++) {
            float t = __ldg(&cw[c * 3 + 0]) * xv0 + __ldg(&cw[c * 3 + 1]) * xv1 +
                      __ldg(&cw[c * 3 + 2]) * xv2 + __ldg(&cb[c]);
            t = fmaxf(t, 0.0f);
            s_xc[c * CS + po] = fmaf(__ldg(&g_sc[c]), t, __ldg(&g_sh[c]));
        }
    }
    __syncthreads();

#pragma unroll
    for (int k = 0; k < 4; k++) {
        int o = tid + k * 256;
        int c = o >> 6, q = o & 63;
        int qy = q >> 3, qx = q & 7;
        const float* sp = &s_xc[c * CS + (qy * 2) * RS + qx * 2];
        float mo = fmaxf(fmaxf(sp[0], sp[1]), fmaxf(sp[RS], sp[RS + 1]));
        g_x1p[((n * 16 + c) * 256 + by * 8 + qy) * 256 + (bx * 8 + qx)] = mo;
    }
}

// ---------------------------------------------------------------------------
// Stage 1b: halo holds PRE-CONVERTED tf32 values (d1 epilogue converts once);
// d2 A-loads feed mma directly with zero cvt in the hot loop.
// ---------------------------------------------------------------------------
__global__ void __launch_bounds__(256, 3) stage1_active_kernel(
    const float* __restrict__ x,
    const float* __restrict__ cw, const float* __restrict__ cb,
    const float* __restrict__ d1w, const float* __restrict__ d1b,
    const float* __restrict__ d2b,
    const float* __restrict__ d3w, const float* __restrict__ d3b)
{
    if ((int)blockIdx.x >= g_cnt1) return;
    const int bid = g_list1[blockIdx.x];

    extern __shared__ float sm[];
    float* s_halo = sm + 4;
    float* s_xc   = sm + 11524;   // [16][CS]
    float* s_b    = sm + 4;       // [32][260], reuses halo after sync
    float* s_f    = sm + 8324;    // [16][256]

    const int n = bid >> 10, by = (bid >> 5) & 31, bx = bid & 31;
    const int tid = threadIdx.x;
    const int py = tid >> 4, px_ = tid & 15;
    const int gy = by * 16 + py, gx = bx * 16 + px_;

    {
        float4 z4 = make_float4(0.f, 0.f, 0.f, 0.f);
        for (int i = tid; i < 2881; i += 256) ((float4*)sm)[i] = z4;
    }
    {
        const int ibase = ((n * 3) * 512 + gy) * 512 + gx;
        float xv0 = x[ibase];
        float xv1 = x[ibase + 512 * 512];
        float xv2 = x[ibase + 2 * 512 * 512];
        const int po = py * RS + px_;
#pragma unroll
        for (int c = 0; c < 16; c++) {
            float t = __ldg(&cw[c * 3 + 0]) * xv0 + __ldg(&cw[c * 3 + 1]) * xv1 +
                      __ldg(&cw[c * 3 + 2]) * xv2 + __ldg(&cb[c]);
            t = fmaxf(t, 0.0f);
            s_xc[c * CS + po] = fmaf(__ldg(&g_sc[c]), t, __ldg(&g_sh[c]));
        }
    }
    __syncthreads();

    const int lane = tid & 31, wg = tid >> 5;
    const int prow = lane & 15, pcol = (lane >> 4) * 8;

    // d1: 16 -> 32 into halo (tf32-pre-rounded)
    {
        const int c2base = wg * 4;
        ull acc[4][4];
#pragma unroll
        for (int c2 = 0; c2 < 4; c2++) {
            ull bv = dup2(__ldg(&d1b[c2base + c2]));
            acc[c2][0] = bv; acc[c2][1] = bv; acc[c2][2] = bv; acc[c2][3] = bv;
        }
        const int po = prow * RS + pcol;
#pragma unroll
        for (int c1 = 0; c1 < 16; c1++) {
            const float* p = s_xc + c1 * CS + po;
            float4 a = *(const float4*)p;
            float4 b = *(const float4*)(p + 4);
            ull va0 = pack2(a.x, a.y), va1 = pack2(a.z, a.w);
            ull vb0 = pack2(b.x, b.y), vb1 = pack2(b.z, b.w);
#pragma unroll
            for (int c2 = 0; c2 < 4; c2++) {
                ull w = dup2(__ldg(&d1w[(c2base + c2) * 16 + c1]));
                fma2(acc[c2][0], w, va0);
                fma2(acc[c2][1], w, va1);
                fma2(acc[c2][2], w, vb0);
                fma2(acc[c2][3], w, vb1);
            }
        }
        const int ho = (prow + 1) * 20 + pcol;
#pragma unroll
        for (int c2 = 0; c2 < 4; c2++) {
            int c = c2base + c2;
            float sc = __ldg(&g_sc[16 + c]), sh = __ldg(&g_sh[16 + c]);
            float4 o0, o1;
            float2 f0 = unpack2(acc[c2][0]), f1 = unpack2(acc[c2][1]);
            float2 f2 = unpack2(acc[c2][2]), f3 = unpack2(acc[c2][3]);
            o0.x = tf32f(fmaf(sc, fmaxf(f0.x, 0.f), sh)); o0.y = tf32f(fmaf(sc, fmaxf(f0.y, 0.f), sh));
            o0.z = tf32f(fmaf(sc, fmaxf(f1.x, 0.f), sh)); o0.w = tf32f(fmaf(sc, fmaxf(f1.y, 0.f), sh));
            o1.x = tf32f(fmaf(sc, fmaxf(f2.x, 0.f), sh)); o1.y = tf32f(fmaf(sc, fmaxf(f2.y, 0.f), sh));
            o1.z = tf32f(fmaf(sc, fmaxf(f3.x, 0.f), sh)); o1.w = tf32f(fmaf(sc, fmaxf(f3.y, 0.f), sh));
            *(float4*)(s_halo + c * 360 + ho)     = o0;
            *(float4*)(s_halo + c * 360 + ho + 4) = o1;
        }
    }
    __syncthreads();

    // d2: tf32 mma 2-term; A loaded pre-converted (no cvt)
    {
        const int tg = lane & 3, q = lane >> 2;
        float acc[8][4];
#pragma unroll
        for (int i = 0; i < 8; i++) {
            int c2 = (i & 3) * 8 + tg * 2;
            float b0 = __ldg(&d2b[c2]), b1 = __ldg(&d2b[c2 + 1]);
            acc[i][0] = b0; acc[i][1] = b1; acc[i][2] = b0; acc[i][3] = b1;
        }
        const float* hp0 = s_halo + tg * 360 + wg * 20 + q - 1;
        const uint4* bh = (const uint4*)g_bhi + lane * 2;
        const uint4* bl = (const uint4*)g_blo + lane * 2;
#pragma unroll 1
        for (int tap = 0; tap < 9; tap++) {
            int dyq = (tap * 11) >> 5;
            const float* hp = hp0 + tap + 17 * dyq;
#pragma unroll
            for (int kl = 0; kl < 4; kl++) {
                uint Ah[8];
                Ah[0] = __float_as_uint(hp[0]);    Ah[1] = __float_as_uint(hp[8]);
                Ah[2] = __float_as_uint(hp[1440]); Ah[3] = __float_as_uint(hp[1448]);
                Ah[4] = __float_as_uint(hp[160]);  Ah[5] = __float_as_uint(hp[168]);
                Ah[6] = __float_as_uint(hp[1600]); Ah[7] = __float_as_uint(hp[1608]);
                hp += 2880;
                uint4 H0 = __ldg(bh), H1 = __ldg(bh + 1);
                uint4 L0 = __ldg(bl), L1 = __ldg(bl + 1);
                bh += 64; bl += 64;
                uint BH[8] = {H0.x, H0.y, H0.z, H0.w, H1.x, H1.y, H1.z, H1.w};
                uint BL[8] = {L0.x, L0.y, L0.z, L0.w, L1.x, L1.y, L1.z, L1.w};
#pragma unroll
                for (int nt = 0; nt < 4; nt++) {
                    mma8(acc[nt],     Ah,     BH[2*nt], BH[2*nt+1]);
                    mma8(acc[nt],     Ah,     BL[2*nt], BL[2*nt+1]);
                    mma8(acc[nt + 4], Ah + 4, BH[2*nt], BH[2*nt+1]);
                    mma8(acc[nt + 4], Ah + 4, BL[2*nt], BL[2*nt+1]);
                }
            }
        }
        __syncthreads();   // all halo reads done; s_b may now overwrite it
#pragma unroll
        for (int i = 0; i < 8; i++) {
            int mt = i >> 2, nt = i & 3;
            int c2 = nt * 8 + tg * 2;
            float s0 = __ldg(&g_sc[48 + c2]), h0 = __ldg(&g_sh[48 + c2]);
            float s1 = __ldg(&g_sc[49 + c2]), h1 = __ldg(&g_sh[49 + c2]);
            float* o = s_b + c2 * 260 + (wg + mt * 8) * 16 + q;
            o[0]   = fmaf(s0, fmaxf(acc[i][0], 0.f), h0);
            o[260] = fmaf(s1, fmaxf(acc[i][1], 0.f), h1);
            o[8]   = fmaf(s0, fmaxf(acc[i][2], 0.f), h0);
            o[268] = fmaf(s1, fmaxf(acc[i][3], 0.f), h1);
        }
    }
    __syncthreads();

    // d3: 32 -> 16
    {
        const int q = tid & 63;
        const int c2base = (tid >> 6) * 4;
        ull acc[4][2];
#pragma unroll
        for (int c2 = 0; c2 < 4; c2++) {
            ull bv = dup2(__ldg(&d3b[c2base + c2]));
            acc[c2][0] = bv; acc[c2][1] = bv;
        }
#pragma unroll 4
        for (int c1 = 0; c1 < 32; c1++) {
            float4 v = *(const float4*)(s_b + c1 * 260 + q * 4);
            ull v0 = pack2(v.x, v.y), v1 = pack2(v.z, v.w);
#pragma unroll
            for (int c2 = 0; c2 < 4; c2++) {
                ull w = dup2(__ldg(&d3w[(c2base + c2) * 32 + c1]));
                fma2(acc[c2][0], w, v0);
                fma2(acc[c2][1], w, v1);
            }
        }
#pragma unroll
        for (int c2 = 0; c2 < 4; c2++) {
            int c = c2base + c2;
            float sc = __ldg(&g_sc[80 + c]), sh = __ldg(&g_sh[80 + c]);
            float2 f0 = unpack2(acc[c2][0]), f1 = unpack2(acc[c2][1]);
            float4 o;
            o.x = fmaf(sc, fmaxf(f0.x, 0.f), sh);
            o.y = fmaf(sc, fmaxf(f0.y, 0.f), sh);
            o.z = fmaf(sc, fmaxf(f1.x, 0.f), sh);
            o.w = fmaf(sc, fmaxf(f1.y, 0.f), sh);
            *(float4*)(s_f + c * 256 + q * 4) = o;
        }
    }
    __syncthreads();

#pragma unroll
    for (int k = 0; k < 4; k++) {
        int o = tid + k * 256;
        int c = o >> 6, q = o & 63;
        int qy = q >> 3, qx = q & 7;
        const float* sp = &s_f[c * 256 + (qy * 2) * 16 + qx * 2];
        float mo = fmaxf(fmaxf(sp[0], sp[1]), fmaxf(sp[16], sp[17]));
        g_x1p[((n * 16 + c) * 256 + by * 8 + qy) * 256 + (bx * 8 + qx)] = mo;
    }
}

// ---------------------------------------------------------------------------
__global__ void __launch_bounds__(256, 4) stage2_kernel(
    const float* __restrict__ cw, const float* __restrict__ cb,
    const float* __restrict__ d1w, const float* __restrict__ d1b,
    const float* __restrict__ d2b,
    const float* __restrict__ d3w, const float* __restrict__ d3b)
{
    extern __shared__ float sm2[];
    float* s_halo = sm2 + 4;
    float* s_f    = sm2;
    float* s_b    = sm2 + 5764;   // stride 260
    float* s_xc   = s_b;          // [8][CS]

    __shared__ float s_wsum[8];
    __shared__ int s_active;

    const int bid = blockIdx.x;
    const int n = bid >> 8, by = (bid >> 4) & 15, bx = bid & 15;
    const int tid = threadIdx.x;
    const int py = tid >> 4, px_ = tid & 15;
    const int gy = by * 16 + py, gx = bx * 16 + px_;

    {
        float mv = g_mask2[(n * 256 + gy) * 256 + gx];
#pragma unroll
        for (int o = 16; o; o >>= 1) mv += __shfl_xor_sync(0xffffffffu, mv, o);
        if ((tid & 31) == 0) s_wsum[tid >> 5] = mv;
    }
    {
        float4 z4 = make_float4(0.f, 0.f, 0.f, 0.f);
        for (int i = tid; i < 1441; i += 256) ((float4*)sm2)[i] = z4;
    }
    __syncthreads();
    if (tid == 0) {
        float t = 0.f;
#pragma unroll
        for (int i = 0; i < 8; i++) t += s_wsum[i];
        s_active = (t > 128.0f) ? 1 : 0;
    }

    {
        const int ibase = ((n * 16) * 256 + gy) * 256 + gx;
        float xin[16];
#pragma unroll
        for (int c = 0; c < 16; c++) xin[c] = g_x1p[ibase + c * 65536];
        const int po = py * RS + px_;
#pragma unroll
        for (int c2 = 0; c2 < 8; c2++) {
            float t = __ldg(&cb[c2]);
#pragma unroll
            for (int c1 = 0; c1 < 16; c1++)
                t = fmaf(xin[c1], __ldg(&cw[c2 * 16 + c1]), t);
            t = fmaxf(t, 0.0f);
            s_xc[c2 * CS + po] = fmaf(__ldg(&g_sc[96 + c2]), t, __ldg(&g_sh[96 + c2]));
        }
    }
    __syncthreads();

    const int act = s_active;
    const int lane = tid & 31, wg = tid >> 5;
    const int prow = lane & 15, pcol = (lane >> 4) * 8;

    if (act) {
        // d1: 8 -> 16 into halo (tf32-pre-rounded)
        {
            const int c2base = wg * 2;
            const int po = prow * RS + pcol;
            ull acc[2][4];
#pragma unroll
            for (int c2 = 0; c2 < 2; c2++) {
                ull bv = dup2(__ldg(&d1b[c2base + c2]));
                acc[c2][0] = bv; acc[c2][1] = bv; acc[c2][2] = bv; acc[c2][3] = bv;
            }
#pragma unroll
            for (int c1 = 0; c1 < 8; c1++) {
                const float* p = s_xc + c1 * CS + po;
                float4 a = *(const float4*)p;
                float4 b = *(const float4*)(p + 4);
                ull va0 = pack2(a.x, a.y), va1 = pack2(a.z, a.w);
                ull vb0 = pack2(b.x, b.y), vb1 = pack2(b.z, b.w);
#pragma unroll
                for (int c2 = 0; c2 < 2; c2++) {
                    ull w = dup2(__ldg(&d1w[(c2base + c2) * 8 + c1]));
                    fma2(acc[c2][0], w, va0);
                    fma2(acc[c2][1], w, va1);
                    fma2(acc[c2][2], w, vb0);
                    fma2(acc[c2][3], w, vb1);
                }
            }
            const int ho = (prow + 1) * 20 + pcol;
#pragma unroll
            for (int c2 = 0; c2 < 2; c2++) {
                int c = c2base + c2;
                float sc = __ldg(&g_sc[104 + c]), sh = __ldg(&g_sh[104 + c]);
                float2 f0 = unpack2(acc[c2][0]), f1 = unpack2(acc[c2][1]);
                float2 f2 = unpack2(acc[c2][2]), f3 = unpack2(acc[c2][3]);
                float4 o0, o1;
                o0.x = tf32f(fmaf(sc, fmaxf(f0.x, 0.f), sh)); o0.y = tf32f(fmaf(sc, fmaxf(f0.y, 0.f), sh));
                o0.z = tf32f(fmaf(sc, fmaxf(f1.x, 0.f), sh)); o0.w = tf32f(fmaf(sc, fmaxf(f1.y, 0.f), sh));
                o1.x = tf32f(fmaf(sc, fmaxf(f2.x, 0.f), sh)); o1.y = tf32f(fmaf(sc, fmaxf(f2.y, 0.f), sh));
                o1.z = tf32f(fmaf(sc, fmaxf(f3.x, 0.f), sh)); o1.w = tf32f(fmaf(sc, fmaxf(f3.y, 0.f), sh));
                *(float4*)(s_halo + c * 360 + ho)     = o0;
                *(float4*)(s_halo + c * 360 + ho + 4) = o1;
            }
        }
        __syncthreads();

        // d2: 3x3, 16 -> 16 via tf32 mma (2-term, pre-converted A)
        {
            const int tg = lane & 3, q = lane >> 2;
            float acc[4][4];
#pragma unroll
            for (int i = 0; i < 4; i++) {
                int c2 = (i & 1) * 8 + tg * 2;
                float b0 = __ldg(&d2b[c2]), b1 = __ldg(&d2b[c2 + 1]);
                acc[i][0] = b0; acc[i][1] = b1; acc[i][2] = b0; acc[i][3] = b1;
            }
            const float* hp0 = s_halo + tg * 360 + wg * 20 + q - 1;
            const uint4* bh = (const uint4*)g_qhi + lane;
            const uint4* bl = (const uint4*)g_qlo + lane;
#pragma unroll 1
            for (int tap = 0; tap < 9; tap++) {
                int dyq = (tap * 11) >> 5;
                const float* hp = hp0 + tap + 17 * dyq;
#pragma unroll
                for (int kl = 0; kl < 2; kl++) {
                    uint Ah[8];
                    Ah[0] = __float_as_uint(hp[0]);    Ah[1] = __float_as_uint(hp[8]);
                    Ah[2] = __float_as_uint(hp[1440]); Ah[3] = __float_as_uint(hp[1448]);
                    Ah[4] = __float_as_uint(hp[160]);  Ah[5] = __float_as_uint(hp[168]);
                    Ah[6] = __float_as_uint(hp[1600]); Ah[7] = __float_as_uint(hp[1608]);
                    hp += 2880;
                    uint4 H = __ldg(bh), L = __ldg(bl);
                    bh += 32; bl += 32;
                    mma8(acc[0], Ah,     H.x, H.y);
                    mma8(acc[0], Ah,     L.x, L.y);
                    mma8(acc[1], Ah,     H.z, H.w);
                    mma8(acc[1], Ah,     L.z, L.w);
                    mma8(acc[2], Ah + 4, H.x, H.y);
                    mma8(acc[2], Ah + 4, L.x, L.y);
                    mma8(acc[3], Ah + 4, H.z, H.w);
                    mma8(acc[3], Ah + 4, L.z, L.w);
                }
            }
#pragma unroll
            for (int i = 0; i < 4; i++) {
                int mt = i >> 1, nt = i & 1;
                int c2 = nt * 8 + tg * 2;
                float s0 = __ldg(&g_sc[120 + c2]), h0 = __ldg(&g_sh[120 + c2]);
                float s1 = __ldg(&g_sc[121 + c2]), h1 = __ldg(&g_sh[121 + c2]);
                float* o = s_b + c2 * 260 + (wg + mt * 8) * 16 + q;
                o[0]   = fmaf(s0, fmaxf(acc[i][0], 0.f), h0);
                o[260] = fmaf(s1, fmaxf(acc[i][1], 0.f), h1);
                o[8]   = fmaf(s0, fmaxf(acc[i][2], 0.f), h0);
                o[268] = fmaf(s1, fmaxf(acc[i][3], 0.f), h1);
            }
        }
        __syncthreads();

        // d3: 16 -> 8
        {
            const int q = tid & 63;
            const int c2base = (tid >> 6) * 2;
            ull acc[2][2];
#pragma unroll
            for (int c2 = 0; c2 < 2; c2++) {
                ull bv = dup2(__ldg(&d3b[c2base + c2]));
                acc[c2][0] = bv; acc[c2][1] = bv;
            }
#pragma unroll
            for (int c1 = 0; c1 < 16; c1++) {
                float4 v = *(const float4*)(s_b + c1 * 260 + q * 4);
                ull v0 = pack2(v.x, v.y), v1 = pack2(v.z, v.w);
#pragma unroll
                for (int c2 = 0; c2 < 2; c2++) {
                    ull w = dup2(__ldg(&d3w[(c2base + c2) * 16 + c1]));
                    fma2(acc[c2][0], w, v0);
                    fma2(acc[c2][1], w, v1);
                }
            }
#pragma unroll
            for (int c2 = 0; c2 < 2; c2++) {
                int c = c2base + c2;
                float sc = __ldg(&g_sc[136 + c]), sh = __ldg(&g_sh[136 + c]);
                float2 f0 = unpack2(acc[c2][0]), f1 = unpack2(acc[c2][1]);
                float4 o;
                o.x = fmaf(sc, fmaxf(f0.x, 0.f), sh);
                o.y = fmaf(sc, fmaxf(f0.y, 0.f), sh);
                o.z = fmaf(sc, fmaxf(f1.x, 0.f), sh);
                o.w = fmaf(sc, fmaxf(f1.y, 0.f), sh);
                *(float4*)(s_f + c * 256 + q * 4) = o;
            }
        }
        __syncthreads();
    }

    const float* srcp = act ? s_f : s_xc;
    const int chs = act ? 256 : CS;
    const int rs = act ? 16 : RS;
#pragma unroll
    for (int k = 0; k < 2; k++) {
        int o = tid + k * 256;
        int c = o >> 6, q = o & 63;
        int qy = q >> 3, qx = q & 7;
        const float* sp = &srcp[c * chs + (qy * 2) * rs + qx * 2];
        float mo = fmaxf(fmaxf(sp[0], sp[1]), fmaxf(sp[rs], sp[rs + 1]));
        g_x2p[((n * 8 + c) * 128 + by * 8 + qy) * 128 + (bx * 8 + qx)] = mo;
    }
}

// ---------------------------------------------------------------------------
__global__ void __launch_bounds__(256) fc_partial_kernel(const float* __restrict__ fc_w)
{
    const int b = blockIdx.x;
    const int n = b >> 5, s = b & 31;
    const int tid = threadIdx.x;
    const float4* f = (const float4*)(g_x2p + n * 131072 + s * 4096);
    const float4* w = (const float4*)(fc_w) + s * 1024;

    float part[10];
#pragma unroll
    for (int k = 0; k < 10; k++) part[k] = 0.0f;

#pragma unroll
    for (int j = tid; j < 1024; j += 256) {
        float4 fv = f[j];
#pragma unroll
        for (int k = 0; k < 10; k++) {
            float4 wv = __ldg(&w[k * 32768 + j]);
            part[k] += fv.x * wv.x + fv.y * wv.y + fv.z * wv.z + fv.w * wv.w;
        }
    }

    __shared__ float sred[10][256];
#pragma unroll
    for (int k = 0; k < 10; k++) sred[k][tid] = part[k];
    __syncthreads();
    for (int st = 128; st > 0; st >>= 1) {
        if (tid < st) {
#pragma unroll
            for (int k = 0; k < 10; k++) sred[k][tid] += sred[k][tid + st];
        }
        __syncthreads();
    }
    if (tid < 10) g_fcpart[(n * 32 + s) * 10 + tid] = sred[tid][0];
}

__global__ void fc_final_kernel(const float* __restrict__ fc_b, float* __restrict__ out)
{
    const int t = threadIdx.x;
    __shared__ float s_l[16][10];
    if (t < 160) {
        int n = t / 10, k = t - n * 10;
        float a = fc_b[k];
#pragma unroll
        for (int s = 0; s < 32; s++) a += g_fcpart[(n * 32 + s) * 10 + k];
        s_l[n][k] = a;
    }
    __syncthreads();
    if (t < 16) {
        float mx = -1e30f;
#pragma unroll
        for (int k = 0; k < 10; k++) mx = fmaxf(mx, s_l[t][k]);
        float e[10], se = 0.f;
#pragma unroll
        for (int k = 0; k < 10; k++) { e[k] = expf(s_l[t][k] - mx); se += e[k]; }
        float inv = 1.0f / se;
#pragma unroll
        for (int k = 0; k < 10; k++) out[t * 10 + k] = e[k] * inv;
    }
}

// ---------------------------------------------------------------------------
extern "C" void kernel_launch(void* const* d_in, const int* in_sizes, int n_in,
                              void* d_out, int out_size)
{
    const float* x      = (const float*)d_in[0];
    const float* mask   = (const float*)d_in[1];
    const float* s1_cw  = (const float*)d_in[2];
    const float* s1_cb  = (const float*)d_in[3];
    const float* s1_bn0 = (const float*)d_in[4];
    const float* s1_d1w = (const float*)d_in[5];
    const float* s1_d1b = (const float*)d_in[6];
    const float* s1_bn1 = (const float*)d_in[7];
    const float* s1_d2w = (const float*)d_in[8];
    const float* s1_d2b = (const float*)d_in[9];
    const float* s1_bn2 = (const float*)d_in[10];
    const float* s1_d3w = (const float*)d_in[11];
    const float* s1_d3b = (const float*)d_in[12];
    const float* s1_bn3 = (const float*)d_in[13];
    const float* s2_cw  = (const float*)d_in[14];
    const float* s2_cb  = (const float*)d_in[15];
    const float* s2_bn0 = (const float*)d_in[16];
    const float* s2_d1w = (const float*)d_in[17];
    const float* s2_d1b = (const float*)d_in[18];
    const float* s2_bn1 = (const float*)d_in[19];
    const float* s2_d2w = (const float*)d_in[20];
    const float* s2_d2b = (const float*)d_in[21];
    const float* s2_bn2 = (const float*)d_in[22];
    const float* s2_d3w = (const float*)d_in[23];
    const float* s2_d3b = (const float*)d_in[24];
    const float* s2_bn3 = (const float*)d_in[25];
    const float* fc_w   = (const float*)d_in[26];
    const float* fc_b   = (const float*)d_in[27];

    prep_kernel<<<1, 256>>>(s1_d2w, s2_d2w,
                            s1_bn0, s1_bn1, s1_bn2, s1_bn3,
                            s2_bn0, s2_bn1, s2_bn2, s2_bn3);

    stage1_all_kernel<<<16 * 32 * 32, 256>>>(x, mask, s1_cw, s1_cb);

    const int smem1 = 16644 * sizeof(float);   // 66.6 KB -> 3 CTAs/SM
    cudaFuncSetAttribute(stage1_active_kernel, cudaFuncAttributeMaxDynamicSharedMemorySize, smem1);
    stage1_active_kernel<<<16 * 32 * 32, 256, smem1>>>(
        x, s1_cw, s1_cb, s1_d1w, s1_d1b, s1_d2b, s1_d3w, s1_d3b);

    const int smem2 = 9924 * sizeof(float);    // 39.7 KB -> 4 CTAs/SM
    cudaFuncSetAttribute(stage2_kernel, cudaFuncAttributeMaxDynamicSharedMemorySize, smem2);
    stage2_kernel<<<16 * 16 * 16, 256, smem2>>>(
        s2_cw, s2_cb, s2_d1w, s2_d1b, s2_d2b, s2_d3w, s2_d3b);

    fc_partial_kernel<<<512, 256>>>(fc_w);
    fc_final_kernel<<<1, 256>>>(fc_b, (float*)d_out);
}

// round 14
// speedup vs baseline: 1.8197x; 1.2550x over previous
#include <cuda_runtime.h>

#define EPSV 1e-5f
typedef unsigned long long ull;
typedef unsigned int uint;

__device__ float g_x1p[16 * 16 * 256 * 256];
__device__ float g_mask2[16 * 256 * 256];
__device__ float g_x2p[16 * 8 * 128 * 128];
__device__ float g_fcpart[16 * 32 * 10];
__device__ int   g_cnt1;
__device__ int   g_list1[16384];

__device__ __align__(16) float g_bhi[9216];    // stage1 d2 tf32 fragments
__device__ __align__(16) float g_qhi[2304];    // stage2 d2 tf32 fragments
__device__ float g_sc[144], g_sh[144];

__device__ __forceinline__ void fma2(ull& d, ull a, ull b) {
    asm("fma.rn.f32x2 %0, %1, %2, %0;" : "+l"(d) : "l"(a), "l"(b));
}
__device__ __forceinline__ ull pack2(float lo, float hi) {
    ull r; asm("mov.b64 %0, {%1, %2};" : "=l"(r) : "f"(lo), "f"(hi)); return r;
}
__device__ __forceinline__ ull dup2(float v) { return pack2(v, v); }
__device__ __forceinline__ float2 unpack2(ull u) {
    float2 f; asm("mov.b64 {%0, %1}, %2;" : "=f"(f.x), "=f"(f.y) : "l"(u)); return f;
}
__device__ __forceinline__ uint tf32_rna(float v) {
    uint r; asm("cvt.rna.tf32.f32 %0, %1;" : "=r"(r) : "f"(v)); return r;
}
__device__ __forceinline__ float tf32f(float v) {
    return __uint_as_float(tf32_rna(v));
}
__device__ __forceinline__ void mma8(float* a, const uint* A, uint b0, uint b1) {
    asm volatile("mma.sync.aligned.m16n8k8.row.col.f32.tf32.tf32.f32 "
        "{%0,%1,%2,%3},{%4,%5,%6,%7},{%8,%9},{%0,%1,%2,%3};"
        : "+f"(a[0]), "+f"(a[1]), "+f"(a[2]), "+f"(a[3])
        : "r"(A[0]), "r"(A[1]), "r"(A[2]), "r"(A[3]), "r"(b0), "r"(b1));
}

#define RS 20
#define CS 320

// ---------------------------------------------------------------------------
__global__ void prep_kernel(
    const float* __restrict__ s1d2w, const float* __restrict__ s2d2w,
    const float* __restrict__ b10, const float* __restrict__ b11,
    const float* __restrict__ b12, const float* __restrict__ b13,
    const float* __restrict__ b20, const float* __restrict__ b21,
    const float* __restrict__ b22, const float* __restrict__ b23)
{
    const int tid = threadIdx.x;
    if (tid == 0) g_cnt1 = 0;
    for (int i = tid; i < 9216; i += 256) {
        int kstep = i >> 8, r = i & 255;
        int ln = r >> 3, jj = r & 7;
        int kk = kstep * 8 + (ln & 3) + (jj & 1) * 4;
        int c2 = (jj >> 1) * 8 + (ln >> 2);
        int tap = kk >> 5, c1 = kk & 31;
        g_bhi[i] = tf32f(s1d2w[(c2 * 32 + c1) * 9 + tap]);
    }
    for (int i = tid; i < 2304; i += 256) {
        int kstep = i >> 7, r = i & 127;
        int ln = r >> 2, jj = r & 3;
        int kk = kstep * 8 + (ln & 3) + (jj & 1) * 4;
        int c2 = (jj >> 1) * 8 + (ln >> 2);
        int tap = kk >> 4, c1 = kk & 15;
        g_qhi[i] = tf32f(s2d2w[(c2 * 16 + c1) * 9 + tap]);
    }
    if (tid < 144) {
        const float* bp; int c, C;
        if      (tid < 16)  { bp = b10; c = tid;       C = 16; }
        else if (tid < 48)  { bp = b11; c = tid - 16;  C = 32; }
        else if (tid < 80)  { bp = b12; c = tid - 48;  C = 32; }
        else if (tid < 96)  { bp = b13; c = tid - 80;  C = 16; }
        else if (tid < 104) { bp = b20; c = tid - 96;  C = 8;  }
        else if (tid < 120) { bp = b21; c = tid - 104; C = 16; }
        else if (tid < 136) { bp = b22; c = tid - 120; C = 16; }
        else                { bp = b23; c = tid - 136; C = 8;  }
        float g = bp[c], b = bp[C + c], m = bp[2 * C + c], v = bp[3 * C + c];
        float s = g * rsqrtf(v + EPSV);
        g_sc[tid] = s; g_sh[tid] = b - s * m;
    }
}

// ---------------------------------------------------------------------------
__global__ void __launch_bounds__(256) stage1_all_kernel(
    const float* __restrict__ x, const float* __restrict__ mask,
    const float* __restrict__ cw, const float* __restrict__ cb)
{
    __shared__ float s_red[256];
    __shared__ float s_wsum[8];
    __shared__ float s_xc[16 * CS];
    __shared__ int s_active;

    const int bid = blockIdx.x;
    const int n = bid >> 10, by = (bid >> 5) & 31, bx = bid & 31;
    const int tid = threadIdx.x;
    const int py = tid >> 4, px_ = tid & 15;
    const int gy = by * 16 + py, gx = bx * 16 + px_;

    float mval = mask[(n * 512 + gy) * 512 + gx];
    s_red[tid] = mval;
    float msum = mval;
#pragma unroll
    for (int o = 16; o; o >>= 1) msum += __shfl_xor_sync(0xffffffffu, msum, o);
    if ((tid & 31) == 0) s_wsum[tid >> 5] = msum;
    __syncthreads();

    if (tid < 64) {
        int qy = tid >> 3, qx = tid & 7;
        int p0 = (qy * 2) * 16 + qx * 2;
        float m0 = fmaxf(fmaxf(s_red[p0], s_red[p0 + 1]),
                         fmaxf(s_red[p0 + 16], s_red[p0 + 17]));
        g_mask2[(n * 256 + by * 8 + qy) * 256 + (bx * 8 + qx)] = m0;
    }
    if (tid == 0) {
        float t = 0.f;
#pragma unroll
        for (int i = 0; i < 8; i++) t += s_wsum[i];
        int act = (t > 128.0f) ? 1 : 0;
        s_active = act;
        if (act) { int pos = atomicAdd(&g_cnt1, 1); g_list1[pos] = bid; }
    }
    __syncthreads();
    if (s_active) return;

    {
        const int ibase = ((n * 3) * 512 + gy) * 512 + gx;
        float xv0 = x[ibase];
        float xv1 = x[ibase + 512 * 512];
        float xv2 = x[ibase + 2 * 512 * 512];
        const int po = py * RS + px_;
#pragma unroll
        for (int c = 0; c < 16; c++) {
            float t = __ldg(&cw[c * 3 + 0]) * xv0 + __ldg(&cw[c * 3 + 1]) * xv1 +
                      __ldg(&cw[c * 3 + 2]) * xv2 + __ldg(&cb[c]);
            t = fmaxf(t, 0.0f);
            s_xc[c * CS + po] = fmaf(__ldg(&g_sc[c]), t, __ldg(&g_sh[c]));
        }
    }
    __syncthreads();

#pragma unroll
    for (int k = 0; k < 4; k++) {
        int o = tid + k * 256;
        int c = o >> 6, q = o & 63;
        int qy = q >> 3, qx = q & 7;
        const float* sp = &s_xc[c * CS + (qy * 2) * RS + qx * 2];
        float mo = fmaxf(fmaxf(sp[0], sp[1]), fmaxf(sp[RS], sp[RS + 1]));
        g_x1p[((n * 16 + c) * 256 + by * 8 + qy) * 256 + (bx * 8 + qx)] = mo;
    }
}

// ---------------------------------------------------------------------------
// Stage 1b: tf32-pre-rounded halo; d2 single-term Ah x Bh (weights and
// activations both tf32-rounded; rel_err budget 1e-3 >> ~2e-5 actual).
// ---------------------------------------------------------------------------
__global__ void __launch_bounds__(256, 3) stage1_active_kernel(
    const float* __restrict__ x,
    const float* __restrict__ cw, const float* __restrict__ cb,
    const float* __restrict__ d1w, const float* __restrict__ d1b,
    const float* __restrict__ d2b,
    const float* __restrict__ d3w, const float* __restrict__ d3b)
{
    if ((int)blockIdx.x >= g_cnt1) return;
    const int bid = g_list1[blockIdx.x];

    extern __shared__ float sm[];
    float* s_halo = sm + 4;
    float* s_xc   = sm + 11524;   // [16][CS]
    float* s_b    = sm + 4;       // [32][260], reuses halo after sync
    float* s_f    = sm + 8324;    // [16][256]

    const int n = bid >> 10, by = (bid >> 5) & 31, bx = bid & 31;
    const int tid = threadIdx.x;
    const int py = tid >> 4, px_ = tid & 15;
    const int gy = by * 16 + py, gx = bx * 16 + px_;

    {
        float4 z4 = make_float4(0.f, 0.f, 0.f, 0.f);
        for (int i = tid; i < 2881; i += 256) ((float4*)sm)[i] = z4;
    }
    {
        const int ibase = ((n * 3) * 512 + gy) * 512 + gx;
        float xv0 = x[ibase];
        float xv1 = x[ibase + 512 * 512];
        float xv2 = x[ibase + 2 * 512 * 512];
        const int po = py * RS + px_;
#pragma unroll
        for (int c = 0; c < 16; c++) {
            float t = __ldg(&cw[c * 3 + 0]) * xv0 + __ldg(&cw[c * 3 + 1]) * xv1 +
                      __ldg(&cw[c * 3 + 2]) * xv2 + __ldg(&cb[c]);
            t = fmaxf(t, 0.0f);
            s_xc[c * CS + po] = fmaf(__ldg(&g_sc[c]), t, __ldg(&g_sh[c]));
        }
    }
    __syncthreads();

    const int lane = tid & 31, wg = tid >> 5;
    const int prow = lane & 15, pcol = (lane >> 4) * 8;

    // d1: 16 -> 32 into halo (tf32-pre-rounded)
    {
        const int c2base = wg * 4;
        ull acc[4][4];
#pragma unroll
        for (int c2 = 0; c2 < 4; c2++) {
            ull bv = dup2(__ldg(&d1b[c2base + c2]));
            acc[c2][0] = bv; acc[c2][1] = bv; acc[c2][2] = bv; acc[c2][3] = bv;
        }
        const int po = prow * RS + pcol;
#pragma unroll
        for (int c1 = 0; c1 < 16; c1++) {
            const float* p = s_xc + c1 * CS + po;
            float4 a = *(const float4*)p;
            float4 b = *(const float4*)(p + 4);
            ull va0 = pack2(a.x, a.y), va1 = pack2(a.z, a.w);
            ull vb0 = pack2(b.x, b.y), vb1 = pack2(b.z, b.w);
#pragma unroll
            for (int c2 = 0; c2 < 4; c2++) {
                ull w = dup2(__ldg(&d1w[(c2base + c2) * 16 + c1]));
                fma2(acc[c2][0], w, va0);
                fma2(acc[c2][1], w, va1);
                fma2(acc[c2][2], w, vb0);
                fma2(acc[c2][3], w, vb1);
            }
        }
        const int ho = (prow + 1) * 20 + pcol;
#pragma unroll
        for (int c2 = 0; c2 < 4; c2++) {
            int c = c2base + c2;
            float sc = __ldg(&g_sc[16 + c]), sh = __ldg(&g_sh[16 + c]);
            float4 o0, o1;
            float2 f0 = unpack2(acc[c2][0]), f1 = unpack2(acc[c2][1]);
            float2 f2 = unpack2(acc[c2][2]), f3 = unpack2(acc[c2][3]);
            o0.x = tf32f(fmaf(sc, fmaxf(f0.x, 0.f), sh)); o0.y = tf32f(fmaf(sc, fmaxf(f0.y, 0.f), sh));
            o0.z = tf32f(fmaf(sc, fmaxf(f1.x, 0.f), sh)); o0.w = tf32f(fmaf(sc, fmaxf(f1.y, 0.f), sh));
            o1.x = tf32f(fmaf(sc, fmaxf(f2.x, 0.f), sh)); o1.y = tf32f(fmaf(sc, fmaxf(f2.y, 0.f), sh));
            o1.z = tf32f(fmaf(sc, fmaxf(f3.x, 0.f), sh)); o1.w = tf32f(fmaf(sc, fmaxf(f3.y, 0.f), sh));
            *(float4*)(s_halo + c * 360 + ho)     = o0;
            *(float4*)(s_halo + c * 360 + ho + 4) = o1;
        }
    }
    __syncthreads();

    // d2: tf32 mma single-term (Ah x Bh), pre-converted A
    {
        const int tg = lane & 3, q = lane >> 2;
        float acc[8][4];
#pragma unroll
        for (int i = 0; i < 8; i++) {
            int c2 = (i & 3) * 8 + tg * 2;
            float b0 = __ldg(&d2b[c2]), b1 = __ldg(&d2b[c2 + 1]);
            acc[i][0] = b0; acc[i][1] = b1; acc[i][2] = b0; acc[i][3] = b1;
        }
        const float* hp0 = s_halo + tg * 360 + wg * 20 + q - 1;
        const uint4* bh = (const uint4*)g_bhi + lane * 2;
#pragma unroll 1
        for (int tap = 0; tap < 9; tap++) {
            int dyq = (tap * 11) >> 5;
            const float* hp = hp0 + tap + 17 * dyq;
#pragma unroll
            for (int kl = 0; kl < 4; kl++) {
                uint Ah[8];
                Ah[0] = __float_as_uint(hp[0]);    Ah[1] = __float_as_uint(hp[8]);
                Ah[2] = __float_as_uint(hp[1440]); Ah[3] = __float_as_uint(hp[1448]);
                Ah[4] = __float_as_uint(hp[160]);  Ah[5] = __float_as_uint(hp[168]);
                Ah[6] = __float_as_uint(hp[1600]); Ah[7] = __float_as_uint(hp[1608]);
                hp += 2880;
                uint4 H0 = __ldg(bh), H1 = __ldg(bh + 1);
                bh += 64;
                uint BH[8] = {H0.x, H0.y, H0.z, H0.w, H1.x, H1.y, H1.z, H1.w};
#pragma unroll
                for (int nt = 0; nt < 4; nt++) {
                    mma8(acc[nt],     Ah,     BH[2*nt], BH[2*nt+1]);
                    mma8(acc[nt + 4], Ah + 4, BH[2*nt], BH[2*nt+1]);
                }
            }
        }
        __syncthreads();   // all halo reads done; s_b may now overwrite it
#pragma unroll
        for (int i = 0; i < 8; i++) {
            int mt = i >> 2, nt = i & 3;
            int c2 = nt * 8 + tg * 2;
            float s0 = __ldg(&g_sc[48 + c2]), h0 = __ldg(&g_sh[48 + c2]);
            float s1 = __ldg(&g_sc[49 + c2]), h1 = __ldg(&g_sh[49 + c2]);
            float* o = s_b + c2 * 260 + (wg + mt * 8) * 16 + q;
            o[0]   = fmaf(s0, fmaxf(acc[i][0], 0.f), h0);
            o[260] = fmaf(s1, fmaxf(acc[i][1], 0.f), h1);
            o[8]   = fmaf(s0, fmaxf(acc[i][2], 0.f), h0);
            o[268] = fmaf(s1, fmaxf(acc[i][3], 0.f), h1);
        }
    }
    __syncthreads();

    // d3: 32 -> 16
    {
        const int q = tid & 63;
        const int c2base = (tid >> 6) * 4;
        ull acc[4][2];
#pragma unroll
        for (int c2 = 0; c2 < 4; c2++) {
            ull bv = dup2(__ldg(&d3b[c2base + c2]));
            acc[c2][0] = bv; acc[c2][1] = bv;
        }
#pragma unroll 4
        for (int c1 = 0; c1 < 32; c1++) {
            float4 v = *(const float4*)(s_b + c1 * 260 + q * 4);
            ull v0 = pack2(v.x, v.y), v1 = pack2(v.z, v.w);
#pragma unroll
            for (int c2 = 0; c2 < 4; c2++) {
                ull w = dup2(__ldg(&d3w[(c2base + c2) * 32 + c1]));
                fma2(acc[c2][0], w, v0);
                fma2(acc[c2][1], w, v1);
            }
        }
#pragma unroll
        for (int c2 = 0; c2 < 4; c2++) {
            int c = c2base + c2;
            float sc = __ldg(&g_sc[80 + c]), sh = __ldg(&g_sh[80 + c]);
            float2 f0 = unpack2(acc[c2][0]), f1 = unpack2(acc[c2][1]);
            float4 o;
            o.x = fmaf(sc, fmaxf(f0.x, 0.f), sh);
            o.y = fmaf(sc, fmaxf(f0.y, 0.f), sh);
            o.z = fmaf(sc, fmaxf(f1.x, 0.f), sh);
            o.w = fmaf(sc, fmaxf(f1.y, 0.f), sh);
            *(float4*)(s_f + c * 256 + q * 4) = o;
        }
    }
    __syncthreads();

#pragma unroll
    for (int k = 0; k < 4; k++) {
        int o = tid + k * 256;
        int c = o >> 6, q = o & 63;
        int qy = q >> 3, qx = q & 7;
        const float* sp = &s_f[c * 256 + (qy * 2) * 16 + qx * 2];
        float mo = fmaxf(fmaxf(sp[0], sp[1]), fmaxf(sp[16], sp[17]));
        g_x1p[((n * 16 + c) * 256 + by * 8 + qy) * 256 + (bx * 8 + qx)] = mo;
    }
}

// ---------------------------------------------------------------------------
__global__ void __launch_bounds__(256, 4) stage2_kernel(
    const float* __restrict__ cw, const float* __restrict__ cb,
    const float* __restrict__ d1w, const float* __restrict__ d1b,
    const float* __restrict__ d2b,
    const float* __restrict__ d3w, const float* __restrict__ d3b)
{
    extern __shared__ float sm2[];
    float* s_halo = sm2 + 4;
    float* s_f    = sm2;
    float* s_b    = sm2 + 5764;   // stride 260
    float* s_xc   = s_b;          // [8][CS]

    __shared__ float s_wsum[8];
    __shared__ int s_active;

    const int bid = blockIdx.x;
    const int n = bid >> 8, by = (bid >> 4) & 15, bx = bid & 15;
    const int tid = threadIdx.x;
    const int py = tid >> 4, px_ = tid & 15;
    const int gy = by * 16 + py, gx = bx * 16 + px_;

    {
        float mv = g_mask2[(n * 256 + gy) * 256 + gx];
#pragma unroll
        for (int o = 16; o; o >>= 1) mv += __shfl_xor_sync(0xffffffffu, mv, o);
        if ((tid & 31) == 0) s_wsum[tid >> 5] = mv;
    }
    {
        float4 z4 = make_float4(0.f, 0.f, 0.f, 0.f);
        for (int i = tid; i < 1441; i += 256) ((float4*)sm2)[i] = z4;
    }
    __syncthreads();
    if (tid == 0) {
        float t = 0.f;
#pragma unroll
        for (int i = 0; i < 8; i++) t += s_wsum[i];
        s_active = (t > 128.0f) ? 1 : 0;
    }

    {
        const int ibase = ((n * 16) * 256 + gy) * 256 + gx;
        float xin[16];
#pragma unroll
        for (int c = 0; c < 16; c++) xin[c] = g_x1p[ibase + c * 65536];
        const int po = py * RS + px_;
#pragma unroll
        for (int c2 = 0; c2 < 8; c2++) {
            float t = __ldg(&cb[c2]);
#pragma unroll
            for (int c1 = 0; c1 < 16; c1++)
                t = fmaf(xin[c1], __ldg(&cw[c2 * 16 + c1]), t);
            t = fmaxf(t, 0.0f);
            s_xc[c2 * CS + po] = fmaf(__ldg(&g_sc[96 + c2]), t, __ldg(&g_sh[96 + c2]));
        }
    }
    __syncthreads();

    const int act = s_active;
    const int lane = tid & 31, wg = tid >> 5;
    const int prow = lane & 15, pcol = (lane >> 4) * 8;

    if (act) {
        // d1: 8 -> 16 into halo (tf32-pre-rounded)
        {
            const int c2base = wg * 2;
            const int po = prow * RS + pcol;
            ull acc[2][4];
#pragma unroll
            for (int c2 = 0; c2 < 2; c2++) {
                ull bv = dup2(__ldg(&d1b[c2base + c2]));
                acc[c2][0] = bv; acc[c2][1] = bv; acc[c2][2] = bv; acc[c2][3] = bv;
            }
#pragma unroll
            for (int c1 = 0; c1 < 8; c1++) {
                const float* p = s_xc + c1 * CS + po;
                float4 a = *(const float4*)p;
                float4 b = *(const float4*)(p + 4);
                ull va0 = pack2(a.x, a.y), va1 = pack2(a.z, a.w);
                ull vb0 = pack2(b.x, b.y), vb1 = pack2(b.z, b.w);
#pragma unroll
                for (int c2 = 0; c2 < 2; c2++) {
                    ull w = dup2(__ldg(&d1w[(c2base + c2) * 8 + c1]));
                    fma2(acc[c2][0], w, va0);
                    fma2(acc[c2][1], w, va1);
                    fma2(acc[c2][2], w, vb0);
                    fma2(acc[c2][3], w, vb1);
                }
            }
            const int ho = (prow + 1) * 20 + pcol;
#pragma unroll
            for (int c2 = 0; c2 < 2; c2++) {
                int c = c2base + c2;
                float sc = __ldg(&g_sc[104 + c]), sh = __ldg(&g_sh[104 + c]);
                float2 f0 = unpack2(acc[c2][0]), f1 = unpack2(acc[c2][1]);
                float2 f2 = unpack2(acc[c2][2]), f3 = unpack2(acc[c2][3]);
                float4 o0, o1;
                o0.x = tf32f(fmaf(sc, fmaxf(f0.x, 0.f), sh)); o0.y = tf32f(fmaf(sc, fmaxf(f0.y, 0.f), sh));
                o0.z = tf32f(fmaf(sc, fmaxf(f1.x, 0.f), sh)); o0.w = tf32f(fmaf(sc, fmaxf(f1.y, 0.f), sh));
                o1.x = tf32f(fmaf(sc, fmaxf(f2.x, 0.f), sh)); o1.y = tf32f(fmaf(sc, fmaxf(f2.y, 0.f), sh));
                o1.z = tf32f(fmaf(sc, fmaxf(f3.x, 0.f), sh)); o1.w = tf32f(fmaf(sc, fmaxf(f3.y, 0.f), sh));
                *(float4*)(s_halo + c * 360 + ho)     = o0;
                *(float4*)(s_halo + c * 360 + ho + 4) = o1;
            }
        }
        __syncthreads();

        // d2: 3x3, 16 -> 16 via tf32 mma (single-term, pre-converted A)
        {
            const int tg = lane & 3, q = lane >> 2;
            float acc[4][4];
#pragma unroll
            for (int i = 0; i < 4; i++) {
                int c2 = (i & 1) * 8 + tg * 2;
                float b0 = __ldg(&d2b[c2]), b1 = __ldg(&d2b[c2 + 1]);
                acc[i][0] = b0; acc[i][1] = b1; acc[i][2] = b0; acc[i][3] = b1;
            }
            const float* hp0 = s_halo + tg * 360 + wg * 20 + q - 1;
            const uint4* bh = (const uint4*)g_qhi + lane;
#pragma unroll 1
            for (int tap = 0; tap < 9; tap++) {
                int dyq = (tap * 11) >> 5;
                const float* hp = hp0 + tap + 17 * dyq;
#pragma unroll
                for (int kl = 0; kl < 2; kl++) {
                    uint Ah[8];
                    Ah[0] = __float_as_uint(hp[0]);    Ah[1] = __float_as_uint(hp[8]);
                    Ah[2] = __float_as_uint(hp[1440]); Ah[3] = __float_as_uint(hp[1448]);
                    Ah[4] = __float_as_uint(hp[160]);  Ah[5] = __float_as_uint(hp[168]);
                    Ah[6] = __float_as_uint(hp[1600]); Ah[7] = __float_as_uint(hp[1608]);
                    hp += 2880;
                    uint4 H = __ldg(bh);
                    bh += 32;
                    mma8(acc[0], Ah,     H.x, H.y);
                    mma8(acc[1], Ah,     H.z, H.w);
                    mma8(acc[2], Ah + 4, H.x, H.y);
                    mma8(acc[3], Ah + 4, H.z, H.w);
                }
            }
#pragma unroll
            for (int i = 0; i < 4; i++) {
                int mt = i >> 1, nt = i & 1;
                int c2 = nt * 8 + tg * 2;
                float s0 = __ldg(&g_sc[120 + c2]), h0 = __ldg(&g_sh[120 + c2]);
                float s1 = __ldg(&g_sc[121 + c2]), h1 = __ldg(&g_sh[121 + c2]);
                float* o = s_b + c2 * 260 + (wg + mt * 8) * 16 + q;
                o[0]   = fmaf(s0, fmaxf(acc[i][0], 0.f), h0);
                o[260] = fmaf(s1, fmaxf(acc[i][1], 0.f), h1);
                o[8]   = fmaf(s0, fmaxf(acc[i][2], 0.f), h0);
                o[268] = fmaf(s1, fmaxf(acc[i][3], 0.f), h1);
            }
        }
        __syncthreads();

        // d3: 16 -> 8
        {
            const int q = tid & 63;
            const int c2base = (tid >> 6) * 2;
            ull acc[2][2];
#pragma unroll
            for (int c2 = 0; c2 < 2; c2++) {
                ull bv = dup2(__ldg(&d3b[c2base + c2]));
                acc[c2][0] = bv; acc[c2][1] = bv;
            }
#pragma unroll
            for (int c1 = 0; c1 < 16; c1++) {
                float4 v = *(const float4*)(s_b + c1 * 260 + q * 4);
                ull v0 = pack2(v.x, v.y), v1 = pack2(v.z, v.w);
#pragma unroll
                for (int c2 = 0; c2 < 2; c2++) {
                    ull w = dup2(__ldg(&d3w[(c2base + c2) * 16 + c1]));
                    fma2(acc[c2][0], w, v0);
                    fma2(acc[c2][1], w, v1);
                }
            }
#pragma unroll
            for (int c2 = 0; c2 < 2; c2++) {
                int c = c2base + c2;
                float sc = __ldg(&g_sc[136 + c]), sh = __ldg(&g_sh[136 + c]);
                float2 f0 = unpack2(acc[c2][0]), f1 = unpack2(acc[c2][1]);
                float4 o;
                o.x = fmaf(sc, fmaxf(f0.x, 0.f), sh);
                o.y = fmaf(sc, fmaxf(f0.y, 0.f), sh);
                o.z = fmaf(sc, fmaxf(f1.x, 0.f), sh);
                o.w = fmaf(sc, fmaxf(f1.y, 0.f), sh);
                *(float4*)(s_f + c * 256 + q * 4) = o;
            }
        }
        __syncthreads();
    }

    const float* srcp = act ? s_f : s_xc;
    const int chs = act ? 256 : CS;
    const int rs = act ? 16 : RS;
#pragma unroll
    for (int k = 0; k < 2; k++) {
        int o = tid + k * 256;
        int c = o >> 6, q = o & 63;
        int qy = q >> 3, qx = q & 7;
        const float* sp = &srcp[c * chs + (qy * 2) * rs + qx * 2];
        float mo = fmaxf(fmaxf(sp[0], sp[1]), fmaxf(sp[rs], sp[rs + 1]));
        g_x2p[((n * 8 + c) * 128 + by * 8 + qy) * 128 + (bx * 8 + qx)] = mo;
    }
}

// ---------------------------------------------------------------------------
__global__ void __launch_bounds__(256) fc_partial_kernel(const float* __restrict__ fc_w)
{
    const int b = blockIdx.x;
    const int n = b >> 5, s = b & 31;
    const int tid = threadIdx.x;
    const float4* f = (const float4*)(g_x2p + n * 131072 + s * 4096);
    const float4* w = (const float4*)(fc_w) + s * 1024;

    float part[10];
#pragma unroll
    for (int k = 0; k < 10; k++) part[k] = 0.0f;

#pragma unroll
    for (int j = tid; j < 1024; j += 256) {
        float4 fv = f[j];
#pragma unroll
        for (int k = 0; k < 10; k++) {
            float4 wv = __ldg(&w[k * 32768 + j]);
            part[k] += fv.x * wv.x + fv.y * wv.y + fv.z * wv.z + fv.w * wv.w;
        }
    }

    __shared__ float sred[10][256];
#pragma unroll
    for (int k = 0; k < 10; k++) sred[k][tid] = part[k];
    __syncthreads();
    for (int st = 128; st > 0; st >>= 1) {
        if (tid < st) {
#pragma unroll
            for (int k = 0; k < 10; k++) sred[k][tid] += sred[k][tid + st];
        }
        __syncthreads();
    }
    if (tid < 10) g_fcpart[(n * 32 + s) * 10 + tid] = sred[tid][0];
}

__global__ void fc_final_kernel(const float* __restrict__ fc_b, float* __restrict__ out)
{
    const int t = threadIdx.x;
    __shared__ float s_l[16][10];
    if (t < 160) {
        int n = t / 10, k = t - n * 10;
        float a = fc_b[k];
#pragma unroll
        for (int s = 0; s < 32; s++) a += g_fcpart[(n * 32 + s) * 10 + k];
        s_l[n][k] = a;
    }
    __syncthreads();
    if (t < 16) {
        float mx = -1e30f;
#pragma unroll
        for (int k = 0; k < 10; k++) mx = fmaxf(mx, s_l[t][k]);
        float e[10], se = 0.f;
#pragma unroll
        for (int k = 0; k < 10; k++) { e[k] = expf(s_l[t][k] - mx); se += e[k]; }
        float inv = 1.0f / se;
#pragma unroll
        for (int k = 0; k < 10; k++) out[t * 10 + k] = e[k] * inv;
    }
}

// ---------------------------------------------------------------------------
extern "C" void kernel_launch(void* const* d_in, const int* in_sizes, int n_in,
                              void* d_out, int out_size)
{
    const float* x      = (const float*)d_in[0];
    const float* mask   = (const float*)d_in[1];
    const float* s1_cw  = (const float*)d_in[2];
    const float* s1_cb  = (const float*)d_in[3];
    const float* s1_bn0 = (const float*)d_in[4];
    const float* s1_d1w = (const float*)d_in[5];
    const float* s1_d1b = (const float*)d_in[6];
    const float* s1_bn1 = (const float*)d_in[7];
    const float* s1_d2w = (const float*)d_in[8];
    const float* s1_d2b = (const float*)d_in[9];
    const float* s1_bn2 = (const float*)d_in[10];
    const float* s1_d3w = (const float*)d_in[11];
    const float* s1_d3b = (const float*)d_in[12];
    const float* s1_bn3 = (const float*)d_in[13];
    const float* s2_cw  = (const float*)d_in[14];
    const float* s2_cb  = (const float*)d_in[15];
    const float* s2_bn0 = (const float*)d_in[16];
    const float* s2_d1w = (const float*)d_in[17];
    const float* s2_d1b = (const float*)d_in[18];
    const float* s2_bn1 = (const float*)d_in[19];
    const float* s2_d2w = (const float*)d_in[20];
    const float* s2_d2b = (const float*)d_in[21];
    const float* s2_bn2 = (const float*)d_in[22];
    const float* s2_d3w = (const float*)d_in[23];
    const float* s2_d3b = (const float*)d_in[24];
    const float* s2_bn3 = (const float*)d_in[25];
    const float* fc_w   = (const float*)d_in[26];
    const float* fc_b   = (const float*)d_in[27];

    prep_kernel<<<1, 256>>>(s1_d2w, s2_d2w,
                            s1_bn0, s1_bn1, s1_bn2, s1_bn3,
                            s2_bn0, s2_bn1, s2_bn2, s2_bn3);

    stage1_all_kernel<<<16 * 32 * 32, 256>>>(x, mask, s1_cw, s1_cb);

    const int smem1 = 16644 * sizeof(float);   // 66.6 KB -> 3 CTAs/SM
    cudaFuncSetAttribute(stage1_active_kernel, cudaFuncAttributeMaxDynamicSharedMemorySize, smem1);
    stage1_active_kernel<<<16 * 32 * 32, 256, smem1>>>(
        x, s1_cw, s1_cb, s1_d1w, s1_d1b, s1_d2b, s1_d3w, s1_d3b);

    const int smem2 = 9924 * sizeof(float);    // 39.7 KB -> 4 CTAs/SM
    cudaFuncSetAttribute(stage2_kernel, cudaFuncAttributeMaxDynamicSharedMemorySize, smem2);
    stage2_kernel<<<16 * 16 * 16, 256, smem2>>>(
        s2_cw, s2_cb, s2_d1w, s2_d1b, s2_d2b, s2_d3w, s2_d3b);

    fc_partial_kernel<<<512, 256>>>(fc_w);
    fc_final_kernel<<<1, 256>>>(fc_b, (float*)d_out);
}

// round 15
// speedup vs baseline: 2.0847x; 1.1456x over previous
#include <cuda_runtime.h>

#define EPSV 1e-5f
typedef unsigned long long ull;
typedef unsigned int uint;

__device__ float g_x1p[16 * 16 * 256 * 256];
__device__ float g_mask2[16 * 256 * 256];
__device__ float g_x2p[16 * 8 * 128 * 128];
__device__ float g_fcpart[16 * 32 * 10];
__device__ int   g_cnt1;
__device__ int   g_list1[16384];

__device__ __align__(16) float g_bhi[9216];   // stage1 d2 tf32 B-fragments
__device__ __align__(16) float g_qhi[2304];   // stage2 d2 tf32 B-fragments
__device__ __align__(16) float g_d1f[512];    // stage1 d1 [ks2][lane][nt4][half2]
__device__ __align__(16) float g_d3f[512];    // stage1 d3 [ks4][lane][nt2][half2]
__device__ __align__(16) float g_e1f[128];    // stage2 d1 [lane][nt2][half2]
__device__ __align__(16) float g_e3f[128];    // stage2 d3 [ks2][lane][half2]
__device__ float g_sc[144], g_sh[144];

__device__ __forceinline__ uint tf32_rna(float v) {
    uint r; asm("cvt.rna.tf32.f32 %0, %1;" : "=r"(r) : "f"(v)); return r;
}
__device__ __forceinline__ float tf32f(float v) {
    return __uint_as_float(tf32_rna(v));
}
__device__ __forceinline__ void mma8(float* a, const uint* A, uint b0, uint b1) {
    asm volatile("mma.sync.aligned.m16n8k8.row.col.f32.tf32.tf32.f32 "
        "{%0,%1,%2,%3},{%4,%5,%6,%7},{%8,%9},{%0,%1,%2,%3};"
        : "+f"(a[0]), "+f"(a[1]), "+f"(a[2]), "+f"(a[3])
        : "r"(A[0]), "r"(A[1]), "r"(A[2]), "r"(A[3]), "r"(b0), "r"(b1));
}

#define RS 20
#define CS 320   // stage1_all s_xc (unchanged, exact path)
#define CSX 328  // mma-kernel s_xc stride (banks 8*tg+q, conflict-free)
#define SBS 264  // s_b / s_f stride (banks 8*tg+q, conflict-free)

// ---------------------------------------------------------------------------
__global__ void prep_kernel(
    const float* __restrict__ s1d2w, const float* __restrict__ s2d2w,
    const float* __restrict__ s1d1w, const float* __restrict__ s1d3w,
    const float* __restrict__ s2d1w, const float* __restrict__ s2d3w,
    const float* __restrict__ b10, const float* __restrict__ b11,
    const float* __restrict__ b12, const float* __restrict__ b13,
    const float* __restrict__ b20, const float* __restrict__ b21,
    const float* __restrict__ b22, const float* __restrict__ b23)
{
    const int tid = threadIdx.x;
    if (tid == 0) g_cnt1 = 0;
    for (int i = tid; i < 9216; i += 256) {
        int kstep = i >> 8, r = i & 255;
        int ln = r >> 3, jj = r & 7;
        int kk = kstep * 8 + (ln & 3) + (jj & 1) * 4;
        int c2 = (jj >> 1) * 8 + (ln >> 2);
        int tap = kk >> 5, c1 = kk & 31;
        g_bhi[i] = tf32f(s1d2w[(c2 * 32 + c1) * 9 + tap]);
    }
    for (int i = tid; i < 2304; i += 256) {
        int kstep = i >> 7, r = i & 127;
        int ln = r >> 2, jj = r & 3;
        int kk = kstep * 8 + (ln & 3) + (jj & 1) * 4;
        int c2 = (jj >> 1) * 8 + (ln >> 2);
        int tap = kk >> 4, c1 = kk & 15;
        g_qhi[i] = tf32f(s2d2w[(c2 * 16 + c1) * 9 + tap]);
    }
    // stage1 d1: [ks2][lane][nt4][half2]  (B[k][n], k=c1, n=c2)
    for (int i = tid; i < 512; i += 256) {
        int ks = i >> 8, r = i & 255;
        int ln = r >> 3, j = r & 7;
        int nt = j >> 1, hf = j & 1;
        int c2 = nt * 8 + (ln >> 2), c1 = ks * 8 + (ln & 3) + hf * 4;
        g_d1f[i] = tf32f(s1d1w[c2 * 16 + c1]);
    }
    // stage1 d3: [ks4][lane][nt2][half2]
    for (int i = tid; i < 512; i += 256) {
        int ks = i >> 7, r = i & 127;
        int ln = r >> 2, j = r & 3;
        int nt = j >> 1, hf = j & 1;
        int c2 = nt * 8 + (ln >> 2), c1 = ks * 8 + (ln & 3) + hf * 4;
        g_d3f[i] = tf32f(s1d3w[c2 * 32 + c1]);
    }
    // stage2 d1: [lane][nt2][half2]
    if (tid < 128) {
        int ln = tid >> 2, j = tid & 3;
        int nt = j >> 1, hf = j & 1;
        int c2 = nt * 8 + (ln >> 2), c1 = (ln & 3) + hf * 4;
        g_e1f[tid] = tf32f(s2d1w[c2 * 8 + c1]);
    }
    // stage2 d3: [ks2][lane][half2]
    if (tid < 128) {
        int ks = tid >> 6, r = tid & 63;
        int ln = r >> 1, hf = r & 1;
        int c2 = ln >> 2, c1 = ks * 8 + (ln & 3) + hf * 4;
        g_e3f[tid] = tf32f(s2d3w[c2 * 16 + c1]);
    }
    if (tid < 144) {
        const float* bp; int c, C;
        if      (tid < 16)  { bp = b10; c = tid;       C = 16; }
        else if (tid < 48)  { bp = b11; c = tid - 16;  C = 32; }
        else if (tid < 80)  { bp = b12; c = tid - 48;  C = 32; }
        else if (tid < 96)  { bp = b13; c = tid - 80;  C = 16; }
        else if (tid < 104) { bp = b20; c = tid - 96;  C = 8;  }
        else if (tid < 120) { bp = b21; c = tid - 104; C = 16; }
        else if (tid < 136) { bp = b22; c = tid - 120; C = 16; }
        else                { bp = b23; c = tid - 136; C = 8;  }
        float g = bp[c], b = bp[C + c], m = bp[2 * C + c], v = bp[3 * C + c];
        float s = g * rsqrtf(v + EPSV);
        g_sc[tid] = s; g_sh[tid] = b - s * m;
    }
}

// ---------------------------------------------------------------------------
__global__ void __launch_bounds__(256) stage1_all_kernel(
    const float* __restrict__ x, const float* __restrict__ mask,
    const float* __restrict__ cw, const float* __restrict__ cb)
{
    __shared__ float s_red[256];
    __shared__ float s_wsum[8];
    __shared__ float s_xc[16 * CS];
    __shared__ int s_active;

    const int bid = blockIdx.x;
    const int n = bid >> 10, by = (bid >> 5) & 31, bx = bid & 31;
    const int tid = threadIdx.x;
    const int py = tid >> 4, px_ = tid & 15;
    const int gy = by * 16 + py, gx = bx * 16 + px_;

    float mval = mask[(n * 512 + gy) * 512 + gx];
    s_red[tid] = mval;
    float msum = mval;
#pragma unroll
    for (int o = 16; o; o >>= 1) msum += __shfl_xor_sync(0xffffffffu, msum, o);
    if ((tid & 31) == 0) s_wsum[tid >> 5] = msum;
    __syncthreads();

    if (tid < 64) {
        int qy = tid >> 3, qx = tid & 7;
        int p0 = (qy * 2) * 16 + qx * 2;
        float m0 = fmaxf(fmaxf(s_red[p0], s_red[p0 + 1]),
                         fmaxf(s_red[p0 + 16], s_red[p0 + 17]));
        g_mask2[(n * 256 + by * 8 + qy) * 256 + (bx * 8 + qx)] = m0;
    }
    if (tid == 0) {
        float t = 0.f;
#pragma unroll
        for (int i = 0; i < 8; i++) t += s_wsum[i];
        int act = (t > 128.0f) ? 1 : 0;
        s_active = act;
        if (act) { int pos = atomicAdd(&g_cnt1, 1); g_list1[pos] = bid; }
    }
    __syncthreads();
    if (s_active) return;

    {
        const int ibase = ((n * 3) * 512 + gy) * 512 + gx;
        float xv0 = x[ibase];
        float xv1 = x[ibase + 512 * 512];
        float xv2 = x[ibase + 2 * 512 * 512];
        const int po = py * RS + px_;
#pragma unroll
        for (int c = 0; c < 16; c++) {
            float t = __ldg(&cw[c * 3 + 0]) * xv0 + __ldg(&cw[c * 3 + 1]) * xv1 +
                      __ldg(&cw[c * 3 + 2]) * xv2 + __ldg(&cb[c]);
            t = fmaxf(t, 0.0f);
            s_xc[c * CS + po] = fmaf(__ldg(&g_sc[c]), t, __ldg(&g_sh[c]));
        }
    }
    __syncthreads();

#pragma unroll
    for (int k = 0; k < 4; k++) {
        int o = tid + k * 256;
        int c = o >> 6, q = o & 63;
        int qy = q >> 3, qx = q & 7;
        const float* sp = &s_xc[c * CS + (qy * 2) * RS + qx * 2];
        float mo = fmaxf(fmaxf(sp[0], sp[1]), fmaxf(sp[RS], sp[RS + 1]));
        g_x1p[((n * 16 + c) * 256 + by * 8 + qy) * 256 + (bx * 8 + qx)] = mo;
    }
}

// ---------------------------------------------------------------------------
// Stage 1b: all three bottleneck convs via tf32 mma (single-term).
// SMEM (floats): guard [0,4), halo [4,11524), s_xc [11524,16772);
// after d2: s_b = sm+4 (stride 264), s_f = sm+8452 (stride 264).
// ---------------------------------------------------------------------------
__global__ void __launch_bounds__(256, 3) stage1_active_kernel(
    const float* __restrict__ x,
    const float* __restrict__ cw, const float* __restrict__ cb,
    const float* __restrict__ d1b, const float* __restrict__ d2b,
    const float* __restrict__ d3b)
{
    if ((int)blockIdx.x >= g_cnt1) return;
    const int bid = g_list1[blockIdx.x];

    extern __shared__ float sm[];
    float* s_halo = sm + 4;
    float* s_xc   = sm + 11524;   // [16][CSX]
    float* s_b    = sm + 4;       // [32][SBS], reuses halo after sync
    float* s_f    = sm + 8452;    // [16][SBS]

    const int n = bid >> 10, by = (bid >> 5) & 31, bx = bid & 31;
    const int tid = threadIdx.x;
    const int py = tid >> 4, px_ = tid & 15;
    const int gy = by * 16 + py, gx = bx * 16 + px_;

    {
        float4 z4 = make_float4(0.f, 0.f, 0.f, 0.f);
        for (int i = tid; i < 2881; i += 256) ((float4*)sm)[i] = z4;
    }
    {
        const int ibase = ((n * 3) * 512 + gy) * 512 + gx;
        float xv0 = x[ibase];
        float xv1 = x[ibase + 512 * 512];
        float xv2 = x[ibase + 2 * 512 * 512];
        const int po = py * RS + px_;
#pragma unroll
        for (int c = 0; c < 16; c++) {
            float t = __ldg(&cw[c * 3 + 0]) * xv0 + __ldg(&cw[c * 3 + 1]) * xv1 +
                      __ldg(&cw[c * 3 + 2]) * xv2 + __ldg(&cb[c]);
            t = fmaxf(t, 0.0f);
            s_xc[c * CSX + po] = fmaf(__ldg(&g_sc[c]), t, __ldg(&g_sh[c]));
        }
    }
    __syncthreads();

    const int lane = tid & 31, wg = tid >> 5;
    const int tg = lane & 3, q = lane >> 2;

    // ---- d1: 1x1 16->32 via mma (M=2 tiles, N=4 tiles, K=2 steps) ----
    {
        float acc[8][4];
#pragma unroll
        for (int i = 0; i < 8; i++) {
            int n0 = (i & 3) * 8 + 2 * tg;
            float b0 = __ldg(&d1b[n0]), b1 = __ldg(&d1b[n0 + 1]);
            acc[i][0] = b0; acc[i][1] = b1; acc[i][2] = b0; acc[i][3] = b1;
        }
#pragma unroll
        for (int ks = 0; ks < 2; ks++) {
            uint4 F0 = __ldg((const uint4*)&g_d1f[(ks * 32 + lane) * 8]);
            uint4 F1 = __ldg((const uint4*)&g_d1f[(ks * 32 + lane) * 8 + 4]);
            uint BF[8] = {F0.x, F0.y, F0.z, F0.w, F1.x, F1.y, F1.z, F1.w};
#pragma unroll
            for (int mt = 0; mt < 2; mt++) {
                const float* ap = s_xc + (ks * 8 + tg) * CSX + (wg + mt * 8) * 20 + q;
                uint A[4];
                A[0] = tf32_rna(ap[0]);
                A[1] = tf32_rna(ap[8]);
                A[2] = tf32_rna(ap[4 * CSX]);
                A[3] = tf32_rna(ap[4 * CSX + 8]);
#pragma unroll
                for (int nt = 0; nt < 4; nt++)
                    mma8(acc[mt * 4 + nt], A, BF[2 * nt], BF[2 * nt + 1]);
            }
        }
#pragma unroll
        for (int i = 0; i < 8; i++) {
            int mt = i >> 2, nt = i & 3;
            int n0 = nt * 8 + 2 * tg;
            int t = wg + mt * 8;
            float s0 = __ldg(&g_sc[16 + n0]), h0 = __ldg(&g_sh[16 + n0]);
            float s1 = __ldg(&g_sc[17 + n0]), h1 = __ldg(&g_sh[17 + n0]);
            float* o = s_halo + n0 * 360 + (t + 1) * 20 + q;
            o[0]   = tf32f(fmaf(s0, fmaxf(acc[mt * 4 + nt][0], 0.f), h0));
            o[360] = tf32f(fmaf(s1, fmaxf(acc[mt * 4 + nt][1], 0.f), h1));
            o[8]   = tf32f(fmaf(s0, fmaxf(acc[mt * 4 + nt][2], 0.f), h0));
            o[368] = tf32f(fmaf(s1, fmaxf(acc[mt * 4 + nt][3], 0.f), h1));
        }
    }
    __syncthreads();

    // ---- d2: 3x3 32->32 via mma (single-term, pre-converted halo) ----
    {
        float acc[8][4];
#pragma unroll
        for (int i = 0; i < 8; i++) {
            int c2 = (i & 3) * 8 + tg * 2;
            float b0 = __ldg(&d2b[c2]), b1 = __ldg(&d2b[c2 + 1]);
            acc[i][0] = b0; acc[i][1] = b1; acc[i][2] = b0; acc[i][3] = b1;
        }
        const float* hp0 = s_halo + tg * 360 + wg * 20 + q - 1;
        const uint4* bh = (const uint4*)g_bhi + lane * 2;
#pragma unroll 1
        for (int tap = 0; tap < 9; tap++) {
            int dyq = (tap * 11) >> 5;
            const float* hp = hp0 + tap + 17 * dyq;
#pragma unroll
            for (int kl = 0; kl < 4; kl++) {
                uint Ah[8];
                Ah[0] = __float_as_uint(hp[0]);    Ah[1] = __float_as_uint(hp[8]);
                Ah[2] = __float_as_uint(hp[1440]); Ah[3] = __float_as_uint(hp[1448]);
                Ah[4] = __float_as_uint(hp[160]);  Ah[5] = __float_as_uint(hp[168]);
                Ah[6] = __float_as_uint(hp[1600]); Ah[7] = __float_as_uint(hp[1608]);
                hp += 2880;
                uint4 H0 = __ldg(bh), H1 = __ldg(bh + 1);
                bh += 64;
                uint BH[8] = {H0.x, H0.y, H0.z, H0.w, H1.x, H1.y, H1.z, H1.w};
#pragma unroll
                for (int nt = 0; nt < 4; nt++) {
                    mma8(acc[nt],     Ah,     BH[2*nt], BH[2*nt+1]);
                    mma8(acc[nt + 4], Ah + 4, BH[2*nt], BH[2*nt+1]);
                }
            }
        }
        __syncthreads();   // halo reads done; s_b may overwrite it
#pragma unroll
        for (int i = 0; i < 8; i++) {
            int mt = i >> 2, nt = i & 3;
            int c2 = nt * 8 + tg * 2;
            float s0 = __ldg(&g_sc[48 + c2]), h0 = __ldg(&g_sh[48 + c2]);
            float s1 = __ldg(&g_sc[49 + c2]), h1 = __ldg(&g_sh[49 + c2]);
            float* o = s_b + c2 * SBS + (wg + mt * 8) * 16 + q;
            o[0]       = tf32f(fmaf(s0, fmaxf(acc[i][0], 0.f), h0));
            o[SBS]     = tf32f(fmaf(s1, fmaxf(acc[i][1], 0.f), h1));
            o[8]       = tf32f(fmaf(s0, fmaxf(acc[i][2], 0.f), h0));
            o[SBS + 8] = tf32f(fmaf(s1, fmaxf(acc[i][3], 0.f), h1));
        }
    }
    __syncthreads();

    // ---- d3: 1x1 32->16 via mma (M=2, N=2, K=4) ----
    {
        float acc[4][4];
#pragma unroll
        for (int i = 0; i < 4; i++) {
            int n0 = (i & 1) * 8 + 2 * tg;
            float b0 = __ldg(&d3b[n0]), b1 = __ldg(&d3b[n0 + 1]);
            acc[i][0] = b0; acc[i][1] = b1; acc[i][2] = b0; acc[i][3] = b1;
        }
#pragma unroll
        for (int ks = 0; ks < 4; ks++) {
            uint4 F = __ldg((const uint4*)&g_d3f[(ks * 32 + lane) * 4]);
#pragma unroll
            for (int mt = 0; mt < 2; mt++) {
                const float* ap = s_b + (ks * 8 + tg) * SBS + (wg + mt * 8) * 16 + q;
                uint A[4];
                A[0] = __float_as_uint(ap[0]);
                A[1] = __float_as_uint(ap[8]);
                A[2] = __float_as_uint(ap[4 * SBS]);
                A[3] = __float_as_uint(ap[4 * SBS + 8]);
                mma8(acc[mt * 2 + 0], A, F.x, F.y);
                mma8(acc[mt * 2 + 1], A, F.z, F.w);
            }
        }
#pragma unroll
        for (int i = 0; i < 4; i++) {
            int mt = i >> 1, nt = i & 1;
            int n0 = nt * 8 + 2 * tg;
            int t = wg + mt * 8;
            float s0 = __ldg(&g_sc[80 + n0]), h0 = __ldg(&g_sh[80 + n0]);
            float s1 = __ldg(&g_sc[81 + n0]), h1 = __ldg(&g_sh[81 + n0]);
            float* o = s_f + n0 * SBS + t * 16 + q;
            o[0]       = fmaf(s0, fmaxf(acc[i][0], 0.f), h0);
            o[SBS]     = fmaf(s1, fmaxf(acc[i][1], 0.f), h1);
            o[8]       = fmaf(s0, fmaxf(acc[i][2], 0.f), h0);
            o[SBS + 8] = fmaf(s1, fmaxf(acc[i][3], 0.f), h1);
        }
    }
    __syncthreads();

#pragma unroll
    for (int k = 0; k < 4; k++) {
        int o = tid + k * 256;
        int c = o >> 6, qq = o & 63;
        int qy = qq >> 3, qx = qq & 7;
        const float* sp = &s_f[c * SBS + (qy * 2) * 16 + qx * 2];
        float mo = fmaxf(fmaxf(sp[0], sp[1]), fmaxf(sp[16], sp[17]));
        g_x1p[((n * 16 + c) * 256 + by * 8 + qy) * 256 + (bx * 8 + qx)] = mo;
    }
}

// ---------------------------------------------------------------------------
// Stage 2: all convs via mma. SMEM: guard [0,4), halo [4,5764);
// s_xc [5764,8388) stride 328 (s_b [5764,9988) stride 264 aliases after d1);
// s_f = sm2+4 (stride 264, reuses halo after d2).
// ---------------------------------------------------------------------------
__global__ void __launch_bounds__(256, 4) stage2_kernel(
    const float* __restrict__ cw, const float* __restrict__ cb,
    const float* __restrict__ d1b, const float* __restrict__ d2b,
    const float* __restrict__ d3b)
{
    extern __shared__ float sm2[];
    float* s_halo = sm2 + 4;
    float* s_xc   = sm2 + 5764;   // [8][CSX]
    float* s_b    = sm2 + 5764;   // [16][SBS] (aliases s_xc after d1)
    float* s_f    = sm2 + 4;      // [8][SBS] (reuses halo after d2)

    __shared__ float s_wsum[8];
    __shared__ int s_active;

    const int bid = blockIdx.x;
    const int n = bid >> 8, by = (bid >> 4) & 15, bx = bid & 15;
    const int tid = threadIdx.x;
    const int py = tid >> 4, px_ = tid & 15;
    const int gy = by * 16 + py, gx = bx * 16 + px_;

    {
        float mv = g_mask2[(n * 256 + gy) * 256 + gx];
#pragma unroll
        for (int o = 16; o; o >>= 1) mv += __shfl_xor_sync(0xffffffffu, mv, o);
        if ((tid & 31) == 0) s_wsum[tid >> 5] = mv;
    }
    {
        float4 z4 = make_float4(0.f, 0.f, 0.f, 0.f);
        for (int i = tid; i < 1441; i += 256) ((float4*)sm2)[i] = z4;
    }
    __syncthreads();
    if (tid == 0) {
        float t = 0.f;
#pragma unroll
        for (int i = 0; i < 8; i++) t += s_wsum[i];
        s_active = (t > 128.0f) ? 1 : 0;
    }

    {
        const int ibase = ((n * 16) * 256 + gy) * 256 + gx;
        float xin[16];
#pragma unroll
        for (int c = 0; c < 16; c++) xin[c] = g_x1p[ibase + c * 65536];
        const int po = py * 20 + px_;
#pragma unroll
        for (int c2 = 0; c2 < 8; c2++) {
            float t = __ldg(&cb[c2]);
#pragma unroll
            for (int c1 = 0; c1 < 16; c1++)
                t = fmaf(xin[c1], __ldg(&cw[c2 * 16 + c1]), t);
            t = fmaxf(t, 0.0f);
            s_xc[c2 * CSX + po] = fmaf(__ldg(&g_sc[96 + c2]), t, __ldg(&g_sh[96 + c2]));
        }
    }
    __syncthreads();

    const int act = s_active;
    const int lane = tid & 31, wg = tid >> 5;
    const int tg = lane & 3, q = lane >> 2;

    if (act) {
        // d1: 1x1 8->16 via mma (M=2, N=2, K=1)
        {
            float acc[4][4];
#pragma unroll
            for (int i = 0; i < 4; i++) {
                int n0 = (i & 1) * 8 + 2 * tg;
                float b0 = __ldg(&d1b[n0]), b1 = __ldg(&d1b[n0 + 1]);
                acc[i][0] = b0; acc[i][1] = b1; acc[i][2] = b0; acc[i][3] = b1;
            }
            uint4 F = __ldg((const uint4*)&g_e1f[lane * 4]);
#pragma unroll
            for (int mt = 0; mt < 2; mt++) {
                const float* ap = s_xc + tg * CSX + (wg + mt * 8) * 20 + q;
                uint A[4];
                A[0] = tf32_rna(ap[0]);
                A[1] = tf32_rna(ap[8]);
                A[2] = tf32_rna(ap[4 * CSX]);
                A[3] = tf32_rna(ap[4 * CSX + 8]);
                mma8(acc[mt * 2 + 0], A, F.x, F.y);
                mma8(acc[mt * 2 + 1], A, F.z, F.w);
            }
            __syncthreads();   // s_xc reads done; s_b (alias) may be written
#pragma unroll
            for (int i = 0; i < 4; i++) {
                int mt = i >> 1, nt = i & 1;
                int n0 = nt * 8 + 2 * tg;
                int t = wg + mt * 8;
                float s0 = __ldg(&g_sc[104 + n0]), h0 = __ldg(&g_sh[104 + n0]);
                float s1 = __ldg(&g_sc[105 + n0]), h1 = __ldg(&g_sh[105 + n0]);
                float* o = s_halo + n0 * 360 + (t + 1) * 20 + q;
                o[0]   = tf32f(fmaf(s0, fmaxf(acc[i][0], 0.f), h0));
                o[360] = tf32f(fmaf(s1, fmaxf(acc[i][1], 0.f), h1));
                o[8]   = tf32f(fmaf(s0, fmaxf(acc[i][2], 0.f), h0));
                o[368] = tf32f(fmaf(s1, fmaxf(acc[i][3], 0.f), h1));
            }
        }
        __syncthreads();

        // d2: 3x3 16->16 via mma (single-term)
        {
            float acc[4][4];
#pragma unroll
            for (int i = 0; i < 4; i++) {
                int c2 = (i & 1) * 8 + tg * 2;
                float b0 = __ldg(&d2b[c2]), b1 = __ldg(&d2b[c2 + 1]);
                acc[i][0] = b0; acc[i][1] = b1; acc[i][2] = b0; acc[i][3] = b1;
            }
            const float* hp0 = s_halo + tg * 360 + wg * 20 + q - 1;
            const uint4* bh = (const uint4*)g_qhi + lane;
#pragma unroll 1
            for (int tap = 0; tap < 9; tap++) {
                int dyq = (tap * 11) >> 5;
                const float* hp = hp0 + tap + 17 * dyq;
#pragma unroll
                for (int kl = 0; kl < 2; kl++) {
                    uint Ah[8];
                    Ah[0] = __float_as_uint(hp[0]);    Ah[1] = __float_as_uint(hp[8]);
                    Ah[2] = __float_as_uint(hp[1440]); Ah[3] = __float_as_uint(hp[1448]);
                    Ah[4] = __float_as_uint(hp[160]);  Ah[5] = __float_as_uint(hp[168]);
                    Ah[6] = __float_as_uint(hp[1600]); Ah[7] = __float_as_uint(hp[1608]);
                    hp += 2880;
                    uint4 H = __ldg(bh);
                    bh += 32;
                    mma8(acc[0], Ah,     H.x, H.y);
                    mma8(acc[1], Ah,     H.z, H.w);
                    mma8(acc[2], Ah + 4, H.x, H.y);
                    mma8(acc[3], Ah + 4, H.z, H.w);
                }
            }
#pragma unroll
            for (int i = 0; i < 4; i++) {
                int mt = i >> 1, nt = i & 1;
                int c2 = nt * 8 + tg * 2;
                float s0 = __ldg(&g_sc[120 + c2]), h0 = __ldg(&g_sh[120 + c2]);
                float s1 = __ldg(&g_sc[121 + c2]), h1 = __ldg(&g_sh[121 + c2]);
                float* o = s_b + c2 * SBS + (wg + mt * 8) * 16 + q;
                o[0]       = tf32f(fmaf(s0, fmaxf(acc[i][0], 0.f), h0));
                o[SBS]     = tf32f(fmaf(s1, fmaxf(acc[i][1], 0.f), h1));
                o[8]       = tf32f(fmaf(s0, fmaxf(acc[i][2], 0.f), h0));
                o[SBS + 8] = tf32f(fmaf(s1, fmaxf(acc[i][3], 0.f), h1));
            }
        }
        __syncthreads();

        // d3: 1x1 16->8 via mma (M=2, N=1, K=2)
        {
            float acc[2][4];
            {
                int n0 = 2 * tg;
                float b0 = __ldg(&d3b[n0]), b1 = __ldg(&d3b[n0 + 1]);
                acc[0][0] = b0; acc[0][1] = b1; acc[0][2] = b0; acc[0][3] = b1;
                acc[1][0] = b0; acc[1][1] = b1; acc[1][2] = b0; acc[1][3] = b1;
            }
#pragma unroll
            for (int ks = 0; ks < 2; ks++) {
                uint2 F = __ldg((const uint2*)&g_e3f[(ks * 32 + lane) * 2]);
#pragma unroll
                for (int mt = 0; mt < 2; mt++) {
                    const float* ap = s_b + (ks * 8 + tg) * SBS + (wg + mt * 8) * 16 + q;
                    uint A[4];
                    A[0] = __float_as_uint(ap[0]);
                    A[1] = __float_as_uint(ap[8]);
                    A[2] = __float_as_uint(ap[4 * SBS]);
                    A[3] = __float_as_uint(ap[4 * SBS + 8]);
                    mma8(acc[mt], A, F.x, F.y);
                }
            }
#pragma unroll
            for (int mt = 0; mt < 2; mt++) {
                int n0 = 2 * tg;
                int t = wg + mt * 8;
                float s0 = __ldg(&g_sc[136 + n0]), h0 = __ldg(&g_sh[136 + n0]);
                float s1 = __ldg(&g_sc[137 + n0]), h1 = __ldg(&g_sh[137 + n0]);
                float* o = s_f + n0 * SBS + t * 16 + q;
                o[0]       = fmaf(s0, fmaxf(acc[mt][0], 0.f), h0);
                o[SBS]     = fmaf(s1, fmaxf(acc[mt][1], 0.f), h1);
                o[8]       = fmaf(s0, fmaxf(acc[mt][2], 0.f), h0);
                o[SBS + 8] = fmaf(s1, fmaxf(acc[mt][3], 0.f), h1);
            }
        }
        __syncthreads();
    }

    const float* srcp = act ? s_f : s_xc;
    const int chs = act ? SBS : CSX;
    const int rs = act ? 16 : 20;
#pragma unroll
    for (int k = 0; k < 2; k++) {
        int o = tid + k * 256;
        int c = o >> 6, qq = o & 63;
        int qy = qq >> 3, qx = qq & 7;
        const float* sp = &srcp[c * chs + (qy * 2) * rs + qx * 2];
        float mo = fmaxf(fmaxf(sp[0], sp[1]), fmaxf(sp[rs], sp[rs + 1]));
        g_x2p[((n * 8 + c) * 128 + by * 8 + qy) * 128 + (bx * 8 + qx)] = mo;
    }
}

// ---------------------------------------------------------------------------
__global__ void __launch_bounds__(256) fc_partial_kernel(const float* __restrict__ fc_w)
{
    const int b = blockIdx.x;
    const int n = b >> 5, s = b & 31;
    const int tid = threadIdx.x;
    const float4* f = (const float4*)(g_x2p + n * 131072 + s * 4096);
    const float4* w = (const float4*)(fc_w) + s * 1024;

    float part[10];
#pragma unroll
    for (int k = 0; k < 10; k++) part[k] = 0.0f;

#pragma unroll
    for (int j = tid; j < 1024; j += 256) {
        float4 fv = f[j];
#pragma unroll
        for (int k = 0; k < 10; k++) {
            float4 wv = __ldg(&w[k * 32768 + j]);
            part[k] += fv.x * wv.x + fv.y * wv.y + fv.z * wv.z + fv.w * wv.w;
        }
    }

    __shared__ float sred[10][256];
#pragma unroll
    for (int k = 0; k < 10; k++) sred[k][tid] = part[k];
    __syncthreads();
    for (int st = 128; st > 0; st >>= 1) {
        if (tid < st) {
#pragma unroll
            for (int k = 0; k < 10; k++) sred[k][tid] += sred[k][tid + st];
        }
        __syncthreads();
    }
    if (tid < 10) g_fcpart[(n * 32 + s) * 10 + tid] = sred[tid][0];
}

__global__ void fc_final_kernel(const float* __restrict__ fc_b, float* __restrict__ out)
{
    const int t = threadIdx.x;
    __shared__ float s_l[16][10];
    if (t < 160) {
        int n = t / 10, k = t - n * 10;
        float a = fc_b[k];
#pragma unroll
        for (int s = 0; s < 32; s++) a += g_fcpart[(n * 32 + s) * 10 + k];
        s_l[n][k] = a;
    }
    __syncthreads();
    if (t < 16) {
        float mx = -1e30f;
#pragma unroll
        for (int k = 0; k < 10; k++) mx = fmaxf(mx, s_l[t][k]);
        float e[10], se = 0.f;
#pragma unroll
        for (int k = 0; k < 10; k++) { e[k] = expf(s_l[t][k] - mx); se += e[k]; }
        float inv = 1.0f / se;
#pragma unroll
        for (int k = 0; k < 10; k++) out[t * 10 + k] = e[k] * inv;
    }
}

// ---------------------------------------------------------------------------
extern "C" void kernel_launch(void* const* d_in, const int* in_sizes, int n_in,
                              void* d_out, int out_size)
{
    const float* x      = (const float*)d_in[0];
    const float* mask   = (const float*)d_in[1];
    const float* s1_cw  = (const float*)d_in[2];
    const float* s1_cb  = (const float*)d_in[3];
    const float* s1_d1w = (const float*)d_in[5];
    const float* s1_d1b = (const float*)d_in[6];
    const float* s1_d2w = (const float*)d_in[8];
    const float* s1_d2b = (const float*)d_in[9];
    const float* s1_d3w = (const float*)d_in[11];
    const float* s1_d3b = (const float*)d_in[12];
    const float* s1_bn0 = (const float*)d_in[4];
    const float* s1_bn1 = (const float*)d_in[7];
    const float* s1_bn2 = (const float*)d_in[10];
    const float* s1_bn3 = (const float*)d_in[13];
    const float* s2_cw  = (const float*)d_in[14];
    const float* s2_cb  = (const float*)d_in[15];
    const float* s2_bn0 = (const float*)d_in[16];
    const float* s2_d1w = (const float*)d_in[17];
    const float* s2_d1b = (const float*)d_in[18];
    const float* s2_bn1 = (const float*)d_in[19];
    const float* s2_d2w = (const float*)d_in[20];
    const float* s2_d2b = (const float*)d_in[21];
    const float* s2_bn2 = (const float*)d_in[22];
    const float* s2_d3w = (const float*)d_in[23];
    const float* s2_d3b = (const float*)d_in[24];
    const float* s2_bn3 = (const float*)d_in[25];
    const float* fc_w   = (const float*)d_in[26];
    const float* fc_b   = (const float*)d_in[27];

    prep_kernel<<<1, 256>>>(s1_d2w, s2_d2w, s1_d1w, s1_d3w, s2_d1w, s2_d3w,
                            s1_bn0, s1_bn1, s1_bn2, s1_bn3,
                            s2_bn0, s2_bn1, s2_bn2, s2_bn3);

    stage1_all_kernel<<<16 * 32 * 32, 256>>>(x, mask, s1_cw, s1_cb);

    const int smem1 = 16772 * sizeof(float);   // 67.1 KB -> 3 CTAs/SM
    cudaFuncSetAttribute(stage1_active_kernel, cudaFuncAttributeMaxDynamicSharedMemorySize, smem1);
    stage1_active_kernel<<<16 * 32 * 32, 256, smem1>>>(
        x, s1_cw, s1_cb, s1_d1b, s1_d2b, s1_d3b);

    const int smem2 = 9988 * sizeof(float);    // 40 KB -> 4 CTAs/SM
    cudaFuncSetAttribute(stage2_kernel, cudaFuncAttributeMaxDynamicSharedMemorySize, smem2);
    stage2_kernel<<<16 * 16 * 16, 256, smem2>>>(
        s2_cw, s2_cb, s2_d1b, s2_d2b, s2_d3b);

    fc_partial_kernel<<<512, 256>>>(fc_w);
    fc_final_kernel<<<1, 256>>>(fc_b, (float*)d_out);
}

// round 16
// speedup vs baseline: 2.8017x; 1.3439x over previous
#include <cuda_runtime.h>
#include <cuda_fp16.h>

#define EPSV 1e-5f
typedef unsigned long long ull;
typedef unsigned int uint;

__device__ float g_x1p[16 * 16 * 256 * 256];
__device__ float g_mask2[16 * 256 * 256];
__device__ float g_x2p[16 * 8 * 128 * 128];
__device__ float g_fcpart[16 * 32 * 10];
__device__ int   g_cnt1;
__device__ int   g_list1[16384];

__device__ __align__(16) uint  g_bh16[4608];  // stage1 d2 fp16 B-frags [18][32][8]
__device__ __align__(16) uint  g_qh16[1152];  // stage2 d2 fp16 B-frags [9][32][4]
__device__ __align__(16) float g_d1f[512];    // stage1 d1 tf32 frags
__device__ __align__(16) float g_d3f[512];    // stage1 d3 tf32 frags
__device__ __align__(16) float g_e1f[128];    // stage2 d1 tf32 frags
__device__ __align__(16) float g_e3f[128];    // stage2 d3 tf32 frags
__device__ float g_sc[144], g_sh[144];

__device__ __forceinline__ uint tf32_rna(float v) {
    uint r; asm("cvt.rna.tf32.f32 %0, %1;" : "=r"(r) : "f"(v)); return r;
}
__device__ __forceinline__ float tf32f(float v) {
    return __uint_as_float(tf32_rna(v));
}
__device__ __forceinline__ uint packh2(float lo, float hi) {
    __half2 h = __floats2half2_rn(lo, hi);
    return *reinterpret_cast<uint*>(&h);
}
__device__ __forceinline__ void mma8(float* a, const uint* A, uint b0, uint b1) {
    asm volatile("mma.sync.aligned.m16n8k8.row.col.f32.tf32.tf32.f32 "
        "{%0,%1,%2,%3},{%4,%5,%6,%7},{%8,%9},{%0,%1,%2,%3};"
        : "+f"(a[0]), "+f"(a[1]), "+f"(a[2]), "+f"(a[3])
        : "r"(A[0]), "r"(A[1]), "r"(A[2]), "r"(A[3]), "r"(b0), "r"(b1));
}
__device__ __forceinline__ void mma16(float* a, const uint* A, uint b0, uint b1) {
    asm volatile("mma.sync.aligned.m16n8k16.row.col.f32.f16.f16.f32 "
        "{%0,%1,%2,%3},{%4,%5,%6,%7},{%8,%9},{%0,%1,%2,%3};"
        : "+f"(a[0]), "+f"(a[1]), "+f"(a[2]), "+f"(a[3])
        : "r"(A[0]), "r"(A[1]), "r"(A[2]), "r"(A[3]), "r"(b0), "r"(b1));
}

#define RS 20
#define CS 320
#define CSX 328
#define SBS 264

// ---------------------------------------------------------------------------
__global__ void prep_kernel(
    const float* __restrict__ s1d2w, const float* __restrict__ s2d2w,
    const float* __restrict__ s1d1w, const float* __restrict__ s1d3w,
    const float* __restrict__ s2d1w, const float* __restrict__ s2d3w,
    const float* __restrict__ b10, const float* __restrict__ b11,
    const float* __restrict__ b12, const float* __restrict__ b13,
    const float* __restrict__ b20, const float* __restrict__ b21,
    const float* __restrict__ b22, const float* __restrict__ b23)
{
    const int tid = threadIdx.x;
    if (tid == 0) g_cnt1 = 0;
    // stage1 d2 fp16 fragments: step s covers k16 = (s&1)*16.. of tap s>>1
    for (int i = tid; i < 4608; i += 256) {
        int s = i >> 8, r = i & 255;
        int ln = r >> 3, j = r & 7;
        int nt = j >> 1, rr = j & 1;
        int tg = ln & 3, g = ln >> 2;
        int n = nt * 8 + g;
        int tap = s >> 1;
        int c1 = (s & 1) * 16 + 2 * tg + rr * 8;
        float w0 = s1d2w[(n * 32 + c1) * 9 + tap];
        float w1 = s1d2w[(n * 32 + c1 + 1) * 9 + tap];
        g_bh16[i] = packh2(w0, w1);
    }
    // stage2 d2 fp16 fragments: step = tap (k16 = all 16 ch)
    for (int i = tid; i < 1152; i += 256) {
        int s = i >> 7, r = i & 127;
        int ln = r >> 2, j = r & 3;
        int nt = j >> 1, rr = j & 1;
        int tg = ln & 3, g = ln >> 2;
        int n = nt * 8 + g;
        int c1 = 2 * tg + rr * 8;
        float w0 = s2d2w[(n * 16 + c1) * 9 + s];
        float w1 = s2d2w[(n * 16 + c1 + 1) * 9 + s];
        g_qh16[i] = packh2(w0, w1);
    }
    for (int i = tid; i < 512; i += 256) {
        int ks = i >> 8, r = i & 255;
        int ln = r >> 3, j = r & 7;
        int nt = j >> 1, hf = j & 1;
        int c2 = nt * 8 + (ln >> 2), c1 = ks * 8 + (ln & 3) + hf * 4;
        g_d1f[i] = tf32f(s1d1w[c2 * 16 + c1]);
    }
    for (int i = tid; i < 512; i += 256) {
        int ks = i >> 7, r = i & 127;
        int ln = r >> 2, j = r & 3;
        int nt = j >> 1, hf = j & 1;
        int c2 = nt * 8 + (ln >> 2), c1 = ks * 8 + (ln & 3) + hf * 4;
        g_d3f[i] = tf32f(s1d3w[c2 * 32 + c1]);
    }
    if (tid < 128) {
        int ln = tid >> 2, j = tid & 3;
        int nt = j >> 1, hf = j & 1;
        int c2 = nt * 8 + (ln >> 2), c1 = (ln & 3) + hf * 4;
        g_e1f[tid] = tf32f(s2d1w[c2 * 8 + c1]);
    }
    if (tid < 128) {
        int ks = tid >> 6, r = tid & 63;
        int ln = r >> 1, hf = r & 1;
        int c2 = ln >> 2, c1 = ks * 8 + (ln & 3) + hf * 4;
        g_e3f[tid] = tf32f(s2d3w[c2 * 16 + c1]);
    }
    if (tid < 144) {
        const float* bp; int c, C;
        if      (tid < 16)  { bp = b10; c = tid;       C = 16; }
        else if (tid < 48)  { bp = b11; c = tid - 16;  C = 32; }
        else if (tid < 80)  { bp = b12; c = tid - 48;  C = 32; }
        else if (tid < 96)  { bp = b13; c = tid - 80;  C = 16; }
        else if (tid < 104) { bp = b20; c = tid - 96;  C = 8;  }
        else if (tid < 120) { bp = b21; c = tid - 104; C = 16; }
        else if (tid < 136) { bp = b22; c = tid - 120; C = 16; }
        else                { bp = b23; c = tid - 136; C = 8;  }
        float g = bp[c], b = bp[C + c], m = bp[2 * C + c], v = bp[3 * C + c];
        float s = g * rsqrtf(v + EPSV);
        g_sc[tid] = s; g_sh[tid] = b - s * m;
    }
}

// ---------------------------------------------------------------------------
__global__ void __launch_bounds__(256) stage1_all_kernel(
    const float* __restrict__ x, const float* __restrict__ mask,
    const float* __restrict__ cw, const float* __restrict__ cb)
{
    __shared__ float s_red[256];
    __shared__ float s_wsum[8];
    __shared__ float s_xc[16 * CS];
    __shared__ int s_active;

    const int bid = blockIdx.x;
    const int n = bid >> 10, by = (bid >> 5) & 31, bx = bid & 31;
    const int tid = threadIdx.x;
    const int py = tid >> 4, px_ = tid & 15;
    const int gy = by * 16 + py, gx = bx * 16 + px_;

    float mval = mask[(n * 512 + gy) * 512 + gx];
    s_red[tid] = mval;
    float msum = mval;
#pragma unroll
    for (int o = 16; o; o >>= 1) msum += __shfl_xor_sync(0xffffffffu, msum, o);
    if ((tid & 31) == 0) s_wsum[tid >> 5] = msum;
    __syncthreads();

    if (tid < 64) {
        int qy = tid >> 3, qx = tid & 7;
        int p0 = (qy * 2) * 16 + qx * 2;
        float m0 = fmaxf(fmaxf(s_red[p0], s_red[p0 + 1]),
                         fmaxf(s_red[p0 + 16], s_red[p0 + 17]));
        g_mask2[(n * 256 + by * 8 + qy) * 256 + (bx * 8 + qx)] = m0;
    }
    if (tid == 0) {
        float t = 0.f;
#pragma unroll
        for (int i = 0; i < 8; i++) t += s_wsum[i];
        int act = (t > 128.0f) ? 1 : 0;
        s_active = act;
        if (act) { int pos = atomicAdd(&g_cnt1, 1); g_list1[pos] = bid; }
    }
    __syncthreads();
    if (s_active) return;

    {
        const int ibase = ((n * 3) * 512 + gy) * 512 + gx;
        float xv0 = x[ibase];
        float xv1 = x[ibase + 512 * 512];
        float xv2 = x[ibase + 2 * 512 * 512];
        const int po = py * RS + px_;
#pragma unroll
        for (int c = 0; c < 16; c++) {
            float t = __ldg(&cw[c * 3 + 0]) * xv0 + __ldg(&cw[c * 3 + 1]) * xv1 +
                      __ldg(&cw[c * 3 + 2]) * xv2 + __ldg(&cb[c]);
            t = fmaxf(t, 0.0f);
            s_xc[c * CS + po] = fmaf(__ldg(&g_sc[c]), t, __ldg(&g_sh[c]));
        }
    }
    __syncthreads();

#pragma unroll
    for (int k = 0; k < 4; k++) {
        int o = tid + k * 256;
        int c = o >> 6, q = o & 63;
        int qy = q >> 3, qx = q & 7;
        const float* sp = &s_xc[c * CS + (qy * 2) * RS + qx * 2];
        float mo = fmaxf(fmaxf(sp[0], sp[1]), fmaxf(sp[RS], sp[RS + 1]));
        g_x1p[((n * 16 + c) * 256 + by * 8 + qy) * 256 + (bx * 8 + qx)] = mo;
    }
}

// ---------------------------------------------------------------------------
// Stage 1b: d2 via fp16 m16n8k16 (halo = half2 channel-pairs); d1/d3 tf32.
// SMEM words: guard [0,4), halo_h2 [4,5764), s_xc [5764,11012);
// s_b = sm+4 [32][264] (reuses halo+s_xc), s_f = sm+8452 [16][264].
// ---------------------------------------------------------------------------
__global__ void __launch_bounds__(256, 4) stage1_active_kernel(
    const float* __restrict__ x,
    const float* __restrict__ cw, const float* __restrict__ cb,
    const float* __restrict__ d1b, const float* __restrict__ d2b,
    const float* __restrict__ d3b)
{
    if ((int)blockIdx.x >= g_cnt1) return;
    const int bid = g_list1[blockIdx.x];

    extern __shared__ float sm[];
    uint*  halo_u = (uint*)(sm + 4);
    float* s_xc   = sm + 5764;
    float* s_b    = sm + 4;
    float* s_f    = sm + 8452;

    const int n = bid >> 10, by = (bid >> 5) & 31, bx = bid & 31;
    const int tid = threadIdx.x;
    const int py = tid >> 4, px_ = tid & 15;
    const int gy = by * 16 + py, gx = bx * 16 + px_;

    {
        float4 z4 = make_float4(0.f, 0.f, 0.f, 0.f);
        for (int i = tid; i < 1441; i += 256) ((float4*)sm)[i] = z4;
    }
    {
        const int ibase = ((n * 3) * 512 + gy) * 512 + gx;
        float xv0 = x[ibase];
        float xv1 = x[ibase + 512 * 512];
        float xv2 = x[ibase + 2 * 512 * 512];
        const int po = py * RS + px_;
#pragma unroll
        for (int c = 0; c < 16; c++) {
            float t = __ldg(&cw[c * 3 + 0]) * xv0 + __ldg(&cw[c * 3 + 1]) * xv1 +
                      __ldg(&cw[c * 3 + 2]) * xv2 + __ldg(&cb[c]);
            t = fmaxf(t, 0.0f);
            s_xc[c * CSX + po] = fmaf(__ldg(&g_sc[c]), t, __ldg(&g_sh[c]));
        }
    }
    __syncthreads();

    const int lane = tid & 31, wg = tid >> 5;
    const int tg = lane & 3, q = lane >> 2;

    // ---- d1: 1x1 16->32 via tf32 mma; epilogue packs half2 channel-pairs ----
    {
        float acc[8][4];
#pragma unroll
        for (int i = 0; i < 8; i++) {
            int n0 = (i & 3) * 8 + 2 * tg;
            float b0 = __ldg(&d1b[n0]), b1 = __ldg(&d1b[n0 + 1]);
            acc[i][0] = b0; acc[i][1] = b1; acc[i][2] = b0; acc[i][3] = b1;
        }
#pragma unroll
        for (int ks = 0; ks < 2; ks++) {
            uint4 F0 = __ldg((const uint4*)&g_d1f[(ks * 32 + lane) * 8]);
            uint4 F1 = __ldg((const uint4*)&g_d1f[(ks * 32 + lane) * 8 + 4]);
            uint BF[8] = {F0.x, F0.y, F0.z, F0.w, F1.x, F1.y, F1.z, F1.w};
#pragma unroll
            for (int mt = 0; mt < 2; mt++) {
                const float* ap = s_xc + (ks * 8 + tg) * CSX + (wg + mt * 8) * 20 + q;
                uint A[4];
                A[0] = tf32_rna(ap[0]);
                A[1] = tf32_rna(ap[8]);
                A[2] = tf32_rna(ap[4 * CSX]);
                A[3] = tf32_rna(ap[4 * CSX + 8]);
#pragma unroll
                for (int nt = 0; nt < 4; nt++)
                    mma8(acc[mt * 4 + nt], A, BF[2 * nt], BF[2 * nt + 1]);
            }
        }
#pragma unroll
        for (int i = 0; i < 8; i++) {
            int mt = i >> 2, nt = i & 3;
            int n0 = nt * 8 + 2 * tg;
            int pair = nt * 4 + tg;
            int t = wg + mt * 8;
            float s0 = __ldg(&g_sc[16 + n0]), h0 = __ldg(&g_sh[16 + n0]);
            float s1 = __ldg(&g_sc[17 + n0]), h1 = __ldg(&g_sh[17 + n0]);
            float v0 = fmaf(s0, fmaxf(acc[i][0], 0.f), h0);
            float v1 = fmaf(s1, fmaxf(acc[i][1], 0.f), h1);
            float v2 = fmaf(s0, fmaxf(acc[i][2], 0.f), h0);
            float v3 = fmaf(s1, fmaxf(acc[i][3], 0.f), h1);
            halo_u[pair * 360 + (t + 1) * 20 + q]     = packh2(v0, v1);
            halo_u[pair * 360 + (t + 1) * 20 + q + 8] = packh2(v2, v3);
        }
    }
    __syncthreads();

    // ---- d2: 3x3 32->32 via fp16 m16n8k16 (18 ksteps) ----
    {
        float acc[8][4];
#pragma unroll
        for (int i = 0; i < 8; i++) {
            int c2 = (i & 3) * 8 + tg * 2;
            float b0 = __ldg(&d2b[c2]), b1 = __ldg(&d2b[c2 + 1]);
            acc[i][0] = b0; acc[i][1] = b1; acc[i][2] = b0; acc[i][3] = b1;
        }
        const uint* hp0 = halo_u + tg * 360 + wg * 20 + q - 1;
        const uint4* bh = (const uint4*)g_bh16 + lane * 2;
#pragma unroll 1
        for (int tap = 0; tap < 9; tap++) {
            int dyq = (tap * 11) >> 5;
            int off = tap + 17 * dyq;   // = 20*dy + dx
#pragma unroll
            for (int kc = 0; kc < 2; kc++) {
                const uint* hp = hp0 + kc * 2880 + off;
                uint A0[4] = {hp[0],   hp[8],   hp[1440], hp[1448]};
                uint A1[4] = {hp[160], hp[168], hp[1600], hp[1608]};
                uint4 B0 = __ldg(bh), B1 = __ldg(bh + 1);
                bh += 64;
                uint Bu[8] = {B0.x, B0.y, B0.z, B0.w, B1.x, B1.y, B1.z, B1.w};
#pragma unroll
                for (int nt = 0; nt < 4; nt++) {
                    mma16(acc[nt],     A0, Bu[2*nt], Bu[2*nt+1]);
                    mma16(acc[nt + 4], A1, Bu[2*nt], Bu[2*nt+1]);
                }
            }
        }
        __syncthreads();   // halo reads done; s_b may overwrite it
#pragma unroll
        for (int i = 0; i < 8; i++) {
            int mt = i >> 2, nt = i & 3;
            int c2 = nt * 8 + tg * 2;
            float s0 = __ldg(&g_sc[48 + c2]), h0 = __ldg(&g_sh[48 + c2]);
            float s1 = __ldg(&g_sc[49 + c2]), h1 = __ldg(&g_sh[49 + c2]);
            float* o = s_b + c2 * SBS + (wg + mt * 8) * 16 + q;
            o[0]       = tf32f(fmaf(s0, fmaxf(acc[i][0], 0.f), h0));
            o[SBS]     = tf32f(fmaf(s1, fmaxf(acc[i][1], 0.f), h1));
            o[8]       = tf32f(fmaf(s0, fmaxf(acc[i][2], 0.f), h0));
            o[SBS + 8] = tf32f(fmaf(s1, fmaxf(acc[i][3], 0.f), h1));
        }
    }
    __syncthreads();

    // ---- d3: 1x1 32->16 via tf32 mma ----
    {
        float acc[4][4];
#pragma unroll
        for (int i = 0; i < 4; i++) {
            int n0 = (i & 1) * 8 + 2 * tg;
            float b0 = __ldg(&d3b[n0]), b1 = __ldg(&d3b[n0 + 1]);
            acc[i][0] = b0; acc[i][1] = b1; acc[i][2] = b0; acc[i][3] = b1;
        }
#pragma unroll
        for (int ks = 0; ks < 4; ks++) {
            uint4 F = __ldg((const uint4*)&g_d3f[(ks * 32 + lane) * 4]);
#pragma unroll
            for (int mt = 0; mt < 2; mt++) {
                const float* ap = s_b + (ks * 8 + tg) * SBS + (wg + mt * 8) * 16 + q;
                uint A[4];
                A[0] = __float_as_uint(ap[0]);
                A[1] = __float_as_uint(ap[8]);
                A[2] = __float_as_uint(ap[4 * SBS]);
                A[3] = __float_as_uint(ap[4 * SBS + 8]);
                mma8(acc[mt * 2 + 0], A, F.x, F.y);
                mma8(acc[mt * 2 + 1], A, F.z, F.w);
            }
        }
#pragma unroll
        for (int i = 0; i < 4; i++) {
            int mt = i >> 1, nt = i & 1;
            int n0 = nt * 8 + 2 * tg;
            int t = wg + mt * 8;
            float s0 = __ldg(&g_sc[80 + n0]), h0 = __ldg(&g_sh[80 + n0]);
            float s1 = __ldg(&g_sc[81 + n0]), h1 = __ldg(&g_sh[81 + n0]);
            float* o = s_f + n0 * SBS + t * 16 + q;
            o[0]       = fmaf(s0, fmaxf(acc[i][0], 0.f), h0);
            o[SBS]     = fmaf(s1, fmaxf(acc[i][1], 0.f), h1);
            o[8]       = fmaf(s0, fmaxf(acc[i][2], 0.f), h0);
            o[SBS + 8] = fmaf(s1, fmaxf(acc[i][3], 0.f), h1);
        }
    }
    __syncthreads();

#pragma unroll
    for (int k = 0; k < 4; k++) {
        int o = tid + k * 256;
        int c = o >> 6, qq = o & 63;
        int qy = qq >> 3, qx = qq & 7;
        const float* sp = &s_f[c * SBS + (qy * 2) * 16 + qx * 2];
        float mo = fmaxf(fmaxf(sp[0], sp[1]), fmaxf(sp[16], sp[17]));
        g_x1p[((n * 16 + c) * 256 + by * 8 + qy) * 256 + (bx * 8 + qx)] = mo;
    }
}

// ---------------------------------------------------------------------------
// Stage 2: d2 via fp16 m16n8k16. SMEM: guard [0,4), halo_h2 [4,2884),
// s_xc [2884,5508); s_b = sm2+4 [16][264], s_f = sm2+4228 [8][264].
// ---------------------------------------------------------------------------
__global__ void __launch_bounds__(256, 5) stage2_kernel(
    const float* __restrict__ cw, const float* __restrict__ cb,
    const float* __restrict__ d1b, const float* __restrict__ d2b,
    const float* __restrict__ d3b)
{
    extern __shared__ float sm2[];
    uint*  halo_u = (uint*)(sm2 + 4);
    float* s_xc   = sm2 + 2884;
    float* s_b    = sm2 + 4;
    float* s_f    = sm2 + 4228;

    __shared__ float s_wsum[8];
    __shared__ int s_active;

    const int bid = blockIdx.x;
    const int n = bid >> 8, by = (bid >> 4) & 15, bx = bid & 15;
    const int tid = threadIdx.x;
    const int py = tid >> 4, px_ = tid & 15;
    const int gy = by * 16 + py, gx = bx * 16 + px_;

    {
        float mv = g_mask2[(n * 256 + gy) * 256 + gx];
#pragma unroll
        for (int o = 16; o; o >>= 1) mv += __shfl_xor_sync(0xffffffffu, mv, o);
        if ((tid & 31) == 0) s_wsum[tid >> 5] = mv;
    }
    {
        float4 z4 = make_float4(0.f, 0.f, 0.f, 0.f);
        for (int i = tid; i < 721; i += 256) ((float4*)sm2)[i] = z4;
    }
    __syncthreads();
    if (tid == 0) {
        float t = 0.f;
#pragma unroll
        for (int i = 0; i < 8; i++) t += s_wsum[i];
        s_active = (t > 128.0f) ? 1 : 0;
    }

    {
        const int ibase = ((n * 16) * 256 + gy) * 256 + gx;
        float xin[16];
#pragma unroll
        for (int c = 0; c < 16; c++) xin[c] = g_x1p[ibase + c * 65536];
        const int po = py * 20 + px_;
#pragma unroll
        for (int c2 = 0; c2 < 8; c2++) {
            float t = __ldg(&cb[c2]);
#pragma unroll
            for (int c1 = 0; c1 < 16; c1++)
                t = fmaf(xin[c1], __ldg(&cw[c2 * 16 + c1]), t);
            t = fmaxf(t, 0.0f);
            s_xc[c2 * CSX + po] = fmaf(__ldg(&g_sc[96 + c2]), t, __ldg(&g_sh[96 + c2]));
        }
    }
    __syncthreads();

    const int act = s_active;
    const int lane = tid & 31, wg = tid >> 5;
    const int tg = lane & 3, q = lane >> 2;

    if (act) {
        // d1: 1x1 8->16 via tf32 mma; half2 epilogue
        {
            float acc[4][4];
#pragma unroll
            for (int i = 0; i < 4; i++) {
                int n0 = (i & 1) * 8 + 2 * tg;
                float b0 = __ldg(&d1b[n0]), b1 = __ldg(&d1b[n0 + 1]);
                acc[i][0] = b0; acc[i][1] = b1; acc[i][2] = b0; acc[i][3] = b1;
            }
            uint4 F = __ldg((const uint4*)&g_e1f[lane * 4]);
#pragma unroll
            for (int mt = 0; mt < 2; mt++) {
                const float* ap = s_xc + tg * CSX + (wg + mt * 8) * 20 + q;
                uint A[4];
                A[0] = tf32_rna(ap[0]);
                A[1] = tf32_rna(ap[8]);
                A[2] = tf32_rna(ap[4 * CSX]);
                A[3] = tf32_rna(ap[4 * CSX + 8]);
                mma8(acc[mt * 2 + 0], A, F.x, F.y);
                mma8(acc[mt * 2 + 1], A, F.z, F.w);
            }
#pragma unroll
            for (int i = 0; i < 4; i++) {
                int mt = i >> 1, nt = i & 1;
                int n0 = nt * 8 + 2 * tg;
                int pair = nt * 4 + tg;
                int t = wg + mt * 8;
                float s0 = __ldg(&g_sc[104 + n0]), h0 = __ldg(&g_sh[104 + n0]);
                float s1 = __ldg(&g_sc[105 + n0]), h1 = __ldg(&g_sh[105 + n0]);
                float v0 = fmaf(s0, fmaxf(acc[i][0], 0.f), h0);
                float v1 = fmaf(s1, fmaxf(acc[i][1], 0.f), h1);
                float v2 = fmaf(s0, fmaxf(acc[i][2], 0.f), h0);
                float v3 = fmaf(s1, fmaxf(acc[i][3], 0.f), h1);
                halo_u[pair * 360 + (t + 1) * 20 + q]     = packh2(v0, v1);
                halo_u[pair * 360 + (t + 1) * 20 + q + 8] = packh2(v2, v3);
            }
        }
        __syncthreads();

        // d2: 3x3 16->16 via fp16 m16n8k16 (9 ksteps)
        {
            float acc[4][4];
#pragma unroll
            for (int i = 0; i < 4; i++) {
                int c2 = (i & 1) * 8 + tg * 2;
                float b0 = __ldg(&d2b[c2]), b1 = __ldg(&d2b[c2 + 1]);
                acc[i][0] = b0; acc[i][1] = b1; acc[i][2] = b0; acc[i][3] = b1;
            }
            const uint* hp0 = halo_u + tg * 360 + wg * 20 + q - 1;
            const uint4* bh = (const uint4*)g_qh16 + lane;
#pragma unroll 1
            for (int tap = 0; tap < 9; tap++) {
                int dyq = (tap * 11) >> 5;
                const uint* hp = hp0 + tap + 17 * dyq;
                uint A0[4] = {hp[0],   hp[8],   hp[1440], hp[1448]};
                uint A1[4] = {hp[160], hp[168], hp[1600], hp[1608]};
                uint4 B = __ldg(bh);
                bh += 32;
                mma16(acc[0], A0, B.x, B.y);
                mma16(acc[1], A0, B.z, B.w);
                mma16(acc[2], A1, B.x, B.y);
                mma16(acc[3], A1, B.z, B.w);
            }
            __syncthreads();   // halo reads done; s_b may overwrite it
#pragma unroll
            for (int i = 0; i < 4; i++) {
                int mt = i >> 1, nt = i & 1;
                int c2 = nt * 8 + tg * 2;
                float s0 = __ldg(&g_sc[120 + c2]), h0 = __ldg(&g_sh[120 + c2]);
                float s1 = __ldg(&g_sc[121 + c2]), h1 = __ldg(&g_sh[121 + c2]);
                float* o = s_b + c2 * SBS + (wg + mt * 8) * 16 + q;
                o[0]       = tf32f(fmaf(s0, fmaxf(acc[i][0], 0.f), h0));
                o[SBS]     = tf32f(fmaf(s1, fmaxf(acc[i][1], 0.f), h1));
                o[8]       = tf32f(fmaf(s0, fmaxf(acc[i][2], 0.f), h0));
                o[SBS + 8] = tf32f(fmaf(s1, fmaxf(acc[i][3], 0.f), h1));
            }
        }
        __syncthreads();

        // d3: 1x1 16->8 via tf32 mma
        {
            float acc[2][4];
            {
                int n0 = 2 * tg;
                float b0 = __ldg(&d3b[n0]), b1 = __ldg(&d3b[n0 + 1]);
                acc[0][0] = b0; acc[0][1] = b1; acc[0][2] = b0; acc[0][3] = b1;
                acc[1][0] = b0; acc[1][1] = b1; acc[1][2] = b0; acc[1][3] = b1;
            }
#pragma unroll
            for (int ks = 0; ks < 2; ks++) {
                uint2 F = __ldg((const uint2*)&g_e3f[(ks * 32 + lane) * 2]);
#pragma unroll
                for (int mt = 0; mt < 2; mt++) {
                    const float* ap = s_b + (ks * 8 + tg) * SBS + (wg + mt * 8) * 16 + q;
                    uint A[4];
                    A[0] = __float_as_uint(ap[0]);
                    A[1] = __float_as_uint(ap[8]);
                    A[2] = __float_as_uint(ap[4 * SBS]);
                    A[3] = __float_as_uint(ap[4 * SBS + 8]);
                    mma8(acc[mt], A, F.x, F.y);
                }
            }
#pragma unroll
            for (int mt = 0; mt < 2; mt++) {
                int n0 = 2 * tg;
                int t = wg + mt * 8;
                float s0 = __ldg(&g_sc[136 + n0]), h0 = __ldg(&g_sh[136 + n0]);
                float s1 = __ldg(&g_sc[137 + n0]), h1 = __ldg(&g_sh[137 + n0]);
                float* o = s_f + n0 * SBS + t * 16 + q;
                o[0]       = fmaf(s0, fmaxf(acc[mt][0], 0.f), h0);
                o[SBS]     = fmaf(s1, fmaxf(acc[mt][1], 0.f), h1);
                o[8]       = fmaf(s0, fmaxf(acc[mt][2], 0.f), h0);
                o[SBS + 8] = fmaf(s1, fmaxf(acc[mt][3], 0.f), h1);
            }
        }
        __syncthreads();
    }

    const float* srcp = act ? s_f : s_xc;
    const int chs = act ? SBS : CSX;
    const int rs = act ? 16 : 20;
#pragma unroll
    for (int k = 0; k < 2; k++) {
        int o = tid + k * 256;
        int c = o >> 6, qq = o & 63;
        int qy = qq >> 3, qx = qq & 7;
        const float* sp = &srcp[c * chs + (qy * 2) * rs + qx * 2];
        float mo = fmaxf(fmaxf(sp[0], sp[1]), fmaxf(sp[rs], sp[rs + 1]));
        g_x2p[((n * 8 + c) * 128 + by * 8 + qy) * 128 + (bx * 8 + qx)] = mo;
    }
}

// ---------------------------------------------------------------------------
__global__ void __launch_bounds__(256) fc_partial_kernel(const float* __restrict__ fc_w)
{
    const int b = blockIdx.x;
    const int n = b >> 5, s = b & 31;
    const int tid = threadIdx.x;
    const float4* f = (const float4*)(g_x2p + n * 131072 + s * 4096);
    const float4* w = (const float4*)(fc_w) + s * 1024;

    float part[10];
#pragma unroll
    for (int k = 0; k < 10; k++) part[k] = 0.0f;

#pragma unroll
    for (int j = tid; j < 1024; j += 256) {
        float4 fv = f[j];
#pragma unroll
        for (int k = 0; k < 10; k++) {
            float4 wv = __ldg(&w[k * 32768 + j]);
            part[k] += fv.x * wv.x + fv.y * wv.y + fv.z * wv.z + fv.w * wv.w;
        }
    }

    __shared__ float sred[10][256];
#pragma unroll
    for (int k = 0; k < 10; k++) sred[k][tid] = part[k];
    __syncthreads();
    for (int st = 128; st > 0; st >>= 1) {
        if (tid < st) {
#pragma unroll
            for (int k = 0; k < 10; k++) sred[k][tid] += sred[k][tid + st];
        }
        __syncthreads();
    }
    if (tid < 10) g_fcpart[(n * 32 + s) * 10 + tid] = sred[tid][0];
}

__global__ void fc_final_kernel(const float* __restrict__ fc_b, float* __restrict__ out)
{
    const int t = threadIdx.x;
    __shared__ float s_l[16][10];
    if (t < 160) {
        int n = t / 10, k = t - n * 10;
        float a = fc_b[k];
#pragma unroll
        for (int s = 0; s < 32; s++) a += g_fcpart[(n * 32 + s) * 10 + k];
        s_l[n][k] = a;
    }
    __syncthreads();
    if (t < 16) {
        float mx = -1e30f;
#pragma unroll
        for (int k = 0; k < 10; k++) mx = fmaxf(mx, s_l[t][k]);
        float e[10], se = 0.f;
#pragma unroll
        for (int k = 0; k < 10; k++) { e[k] = expf(s_l[t][k] - mx); se += e[k]; }
        float inv = 1.0f / se;
#pragma unroll
        for (int k = 0; k < 10; k++) out[t * 10 + k] = e[k] * inv;
    }
}

// ---------------------------------------------------------------------------
extern "C" void kernel_launch(void* const* d_in, const int* in_sizes, int n_in,
                              void* d_out, int out_size)
{
    const float* x      = (const float*)d_in[0];
    const float* mask   = (const float*)d_in[1];
    const float* s1_cw  = (const float*)d_in[2];
    const float* s1_cb  = (const float*)d_in[3];
    const float* s1_bn0 = (const float*)d_in[4];
    const float* s1_d1w = (const float*)d_in[5];
    const float* s1_d1b = (const float*)d_in[6];
    const float* s1_bn1 = (const float*)d_in[7];
    const float* s1_d2w = (const float*)d_in[8];
    const float* s1_d2b = (const float*)d_in[9];
    const float* s1_bn2 = (const float*)d_in[10];
    const float* s1_d3w = (const float*)d_in[11];
    const float* s1_d3b = (const float*)d_in[12];
    const float* s1_bn3 = (const float*)d_in[13];
    const float* s2_cw  = (const float*)d_in[14];
    const float* s2_cb  = (const float*)d_in[15];
    const float* s2_bn0 = (const float*)d_in[16];
    const float* s2_d1w = (const float*)d_in[17];
    const float* s2_d1b = (const float*)d_in[18];
    const float* s2_bn1 = (const float*)d_in[19];
    const float* s2_d2w = (const float*)d_in[20];
    const float* s2_d2b = (const float*)d_in[21];
    const float* s2_bn2 = (const float*)d_in[22];
    const float* s2_d3w = (const float*)d_in[23];
    const float* s2_d3b = (const float*)d_in[24];
    const float* s2_bn3 = (const float*)d_in[25];
    const float* fc_w   = (const float*)d_in[26];
    const float* fc_b   = (const float*)d_in[27];

    prep_kernel<<<1, 256>>>(s1_d2w, s2_d2w, s1_d1w, s1_d3w, s2_d1w, s2_d3w,
                            s1_bn0, s1_bn1, s1_bn2, s1_bn3,
                            s2_bn0, s2_bn1, s2_bn2, s2_bn3);

    stage1_all_kernel<<<16 * 32 * 32, 256>>>(x, mask, s1_cw, s1_cb);

    const int smem1 = 12676 * sizeof(float);   // 50.7 KB -> 4 CTAs/SM
    cudaFuncSetAttribute(stage1_active_kernel, cudaFuncAttributeMaxDynamicSharedMemorySize, smem1);
    stage1_active_kernel<<<16 * 32 * 32, 256, smem1>>>(
        x, s1_cw, s1_cb, s1_d1b, s1_d2b, s1_d3b);

    const int smem2 = 6340 * sizeof(float);    // 25.4 KB -> 5 CTAs/SM
    cudaFuncSetAttribute(stage2_kernel, cudaFuncAttributeMaxDynamicSharedMemorySize, smem2);
    stage2_kernel<<<16 * 16 * 16, 256, smem2>>>(
        s2_cw, s2_cb, s2_d1b, s2_d2b, s2_d3b);

    fc_partial_kernel<<<512, 256>>>(fc_w);
    fc_final_kernel<<<1, 256>>>(fc_b, (float*)d_out);
}

// round 17
// speedup vs baseline: 3.1212x; 1.1140x over previous
#include <cuda_runtime.h>
#include <cuda_fp16.h>

#define EPSV 1e-5f
typedef unsigned long long ull;
typedef unsigned int uint;

__device__ float g_x1p[16 * 16 * 256 * 256];
__device__ float g_mask2[16 * 256 * 256];
__device__ float g_x2p[16 * 8 * 128 * 128];
__device__ float g_fcpart[16 * 32 * 10];
__device__ int   g_cnt1;
__device__ int   g_list1[16384];

__device__ __align__(16) uint  g_bh16[4608];  // stage1 d2 fp16 B [18][32][8]
__device__ __align__(16) uint  g_qh16[1152];  // stage2 d2 fp16 B [9][32][4]
__device__ __align__(16) uint  g_d1h[256];    // stage1 d1 fp16 B [lane][nt4][2]
__device__ __align__(16) uint  g_d3h[256];    // stage1 d3 fp16 B [ks2][lane][nt2][2]
__device__ __align__(16) float g_e1f[128];    // stage2 d1 tf32 B
__device__ __align__(16) uint  g_e3h[64];     // stage2 d3 fp16 B [lane][2]
__device__ float g_sc[144], g_sh[144];

__device__ __forceinline__ uint tf32_rna(float v) {
    uint r; asm("cvt.rna.tf32.f32 %0, %1;" : "=r"(r) : "f"(v)); return r;
}
__device__ __forceinline__ float tf32f(float v) {
    return __uint_as_float(tf32_rna(v));
}
__device__ __forceinline__ uint packh2(float lo, float hi) {
    __half2 h = __floats2half2_rn(lo, hi);
    return *reinterpret_cast<uint*>(&h);
}
__device__ __forceinline__ void mma8(float* a, const uint* A, uint b0, uint b1) {
    asm volatile("mma.sync.aligned.m16n8k8.row.col.f32.tf32.tf32.f32 "
        "{%0,%1,%2,%3},{%4,%5,%6,%7},{%8,%9},{%0,%1,%2,%3};"
        : "+f"(a[0]), "+f"(a[1]), "+f"(a[2]), "+f"(a[3])
        : "r"(A[0]), "r"(A[1]), "r"(A[2]), "r"(A[3]), "r"(b0), "r"(b1));
}
__device__ __forceinline__ void mma16(float* a, const uint* A, uint b0, uint b1) {
    asm volatile("mma.sync.aligned.m16n8k16.row.col.f32.f16.f16.f32 "
        "{%0,%1,%2,%3},{%4,%5,%6,%7},{%8,%9},{%0,%1,%2,%3};"
        : "+f"(a[0]), "+f"(a[1]), "+f"(a[2]), "+f"(a[3])
        : "r"(A[0]), "r"(A[1]), "r"(A[2]), "r"(A[3]), "r"(b0), "r"(b1));
}

#define RS 20
#define CS 320
#define CSX 328   // s_xc stride (fp32 stage2 / half2 stage1): mod 32 == 8
#define SBS 264   // s_b/s_f stride: mod 32 == 8

// ---------------------------------------------------------------------------
__global__ void prep_kernel(
    const float* __restrict__ s1d2w, const float* __restrict__ s2d2w,
    const float* __restrict__ s1d1w, const float* __restrict__ s1d3w,
    const float* __restrict__ s2d1w, const float* __restrict__ s2d3w,
    const float* __restrict__ b10, const float* __restrict__ b11,
    const float* __restrict__ b12, const float* __restrict__ b13,
    const float* __restrict__ b20, const float* __restrict__ b21,
    const float* __restrict__ b22, const float* __restrict__ b23)
{
    const int tid = threadIdx.x;
    if (tid == 0) g_cnt1 = 0;
    for (int i = tid; i < 4608; i += 256) {
        int s = i >> 8, r = i & 255;
        int ln = r >> 3, j = r & 7;
        int nt = j >> 1, rr = j & 1;
        int tg = ln & 3, g = ln >> 2;
        int n = nt * 8 + g;
        int tap = s >> 1;
        int c1 = (s & 1) * 16 + 2 * tg + rr * 8;
        g_bh16[i] = packh2(s1d2w[(n * 32 + c1) * 9 + tap],
                           s1d2w[(n * 32 + c1 + 1) * 9 + tap]);
    }
    for (int i = tid; i < 1152; i += 256) {
        int s = i >> 7, r = i & 127;
        int ln = r >> 2, j = r & 3;
        int nt = j >> 1, rr = j & 1;
        int tg = ln & 3, g = ln >> 2;
        int n = nt * 8 + g;
        int c1 = 2 * tg + rr * 8;
        g_qh16[i] = packh2(s2d2w[(n * 16 + c1) * 9 + s],
                           s2d2w[(n * 16 + c1 + 1) * 9 + s]);
    }
    // stage1 d1 fp16 B: [lane][nt4][b2]
    if (tid < 256) {
        int ln = tid >> 3, j = tid & 7;
        int nt = j >> 1, hb = j & 1;
        int tg = ln & 3, g = ln >> 2;
        int n = nt * 8 + g;
        int k0 = 2 * tg + hb * 8;
        g_d1h[tid] = packh2(s1d1w[n * 16 + k0], s1d1w[n * 16 + k0 + 1]);
    }
    // stage1 d3 fp16 B: [ks2][lane][nt2][b2]
    if (tid < 256) {
        int ks = tid >> 7, r = tid & 127;
        int ln = r >> 2, j = r & 3;
        int nt = j >> 1, hb = j & 1;
        int tg = ln & 3, g = ln >> 2;
        int n = nt * 8 + g;
        int k0 = ks * 16 + 2 * tg + hb * 8;
        g_d3h[tid] = packh2(s1d3w[n * 32 + k0], s1d3w[n * 32 + k0 + 1]);
    }
    // stage2 d1 tf32 B
    if (tid < 128) {
        int ln = tid >> 2, j = tid & 3;
        int nt = j >> 1, hf = j & 1;
        int c2 = nt * 8 + (ln >> 2), c1 = (ln & 3) + hf * 4;
        g_e1f[tid] = tf32f(s2d1w[c2 * 8 + c1]);
    }
    // stage2 d3 fp16 B: [lane][b2]
    if (tid < 64) {
        int ln = tid >> 1, hb = tid & 1;
        int tg = ln & 3, g = ln >> 2;
        int k0 = 2 * tg + hb * 8;
        g_e3h[tid] = packh2(s2d3w[g * 16 + k0], s2d3w[g * 16 + k0 + 1]);
    }
    if (tid < 144) {
        const float* bp; int c, C;
        if      (tid < 16)  { bp = b10; c = tid;       C = 16; }
        else if (tid < 48)  { bp = b11; c = tid - 16;  C = 32; }
        else if (tid < 80)  { bp = b12; c = tid - 48;  C = 32; }
        else if (tid < 96)  { bp = b13; c = tid - 80;  C = 16; }
        else if (tid < 104) { bp = b20; c = tid - 96;  C = 8;  }
        else if (tid < 120) { bp = b21; c = tid - 104; C = 16; }
        else if (tid < 136) { bp = b22; c = tid - 120; C = 16; }
        else                { bp = b23; c = tid - 136; C = 8;  }
        float g = bp[c], b = bp[C + c], m = bp[2 * C + c], v = bp[3 * C + c];
        float s = g * rsqrtf(v + EPSV);
        g_sc[tid] = s; g_sh[tid] = b - s * m;
    }
}

// ---------------------------------------------------------------------------
__global__ void __launch_bounds__(256) stage1_all_kernel(
    const float* __restrict__ x, const float* __restrict__ mask,
    const float* __restrict__ cw, const float* __restrict__ cb)
{
    __shared__ float s_red[256];
    __shared__ float s_wsum[8];
    __shared__ float s_xc[16 * CS];
    __shared__ int s_active;

    const int bid = blockIdx.x;
    const int n = bid >> 10, by = (bid >> 5) & 31, bx = bid & 31;
    const int tid = threadIdx.x;
    const int py = tid >> 4, px_ = tid & 15;
    const int gy = by * 16 + py, gx = bx * 16 + px_;

    float mval = mask[(n * 512 + gy) * 512 + gx];
    s_red[tid] = mval;
    float msum = mval;
#pragma unroll
    for (int o = 16; o; o >>= 1) msum += __shfl_xor_sync(0xffffffffu, msum, o);
    if ((tid & 31) == 0) s_wsum[tid >> 5] = msum;
    __syncthreads();

    if (tid < 64) {
        int qy = tid >> 3, qx = tid & 7;
        int p0 = (qy * 2) * 16 + qx * 2;
        float m0 = fmaxf(fmaxf(s_red[p0], s_red[p0 + 1]),
                         fmaxf(s_red[p0 + 16], s_red[p0 + 17]));
        g_mask2[(n * 256 + by * 8 + qy) * 256 + (bx * 8 + qx)] = m0;
    }
    if (tid == 0) {
        float t = 0.f;
#pragma unroll
        for (int i = 0; i < 8; i++) t += s_wsum[i];
        int act = (t > 128.0f) ? 1 : 0;
        s_active = act;
        if (act) { int pos = atomicAdd(&g_cnt1, 1); g_list1[pos] = bid; }
    }
    __syncthreads();
    if (s_active) return;

    {
        const int ibase = ((n * 3) * 512 + gy) * 512 + gx;
        float xv0 = x[ibase];
        float xv1 = x[ibase + 512 * 512];
        float xv2 = x[ibase + 2 * 512 * 512];
        const int po = py * RS + px_;
#pragma unroll
        for (int c = 0; c < 16; c++) {
            float t = __ldg(&cw[c * 3 + 0]) * xv0 + __ldg(&cw[c * 3 + 1]) * xv1 +
                      __ldg(&cw[c * 3 + 2]) * xv2 + __ldg(&cb[c]);
            t = fmaxf(t, 0.0f);
            s_xc[c * CS + po] = fmaf(__ldg(&g_sc[c]), t, __ldg(&g_sh[c]));
        }
    }
    __syncthreads();

#pragma unroll
    for (int k = 0; k < 4; k++) {
        int o = tid + k * 256;
        int c = o >> 6, q = o & 63;
        int qy = q >> 3, qx = q & 7;
        const float* sp = &s_xc[c * CS + (qy * 2) * RS + qx * 2];
        float mo = fmaxf(fmaxf(sp[0], sp[1]), fmaxf(sp[RS], sp[RS + 1]));
        g_x1p[((n * 16 + c) * 256 + by * 8 + qy) * 256 + (bx * 8 + qx)] = mo;
    }
}

// ---------------------------------------------------------------------------
// Stage 1b: all three convs fp16 mma. SMEM (floats): guard [0,4),
// halo_u [4,5764) (16 pairs x 360 uints), s_xcu [5764,8388) (8 pairs x 328);
// after d2: s_bu = sm+4 (16 pairs x 264), s_f = sm+4228 [16][264] fp32.
// ---------------------------------------------------------------------------
__global__ void __launch_bounds__(256, 4) stage1_active_kernel(
    const float* __restrict__ x,
    const float* __restrict__ cw, const float* __restrict__ cb,
    const float* __restrict__ d1b, const float* __restrict__ d2b,
    const float* __restrict__ d3b)
{
    if ((int)blockIdx.x >= g_cnt1) return;
    const int bid = g_list1[blockIdx.x];

    extern __shared__ float sm[];
    uint*  halo_u = (uint*)(sm + 4);
    uint*  s_xcu  = (uint*)(sm + 5764);
    uint*  s_bu   = (uint*)(sm + 4);
    float* s_f    = sm + 4228;

    const int n = bid >> 10, by = (bid >> 5) & 31, bx = bid & 31;
    const int tid = threadIdx.x;
    const int py = tid >> 4, px_ = tid & 15;
    const int gy = by * 16 + py, gx = bx * 16 + px_;

    {
        float4 z4 = make_float4(0.f, 0.f, 0.f, 0.f);
        for (int i = tid; i < 1441; i += 256) ((float4*)sm)[i] = z4;
    }
    // channel conv -> packed half2 channel-pairs
    {
        const int ibase = ((n * 3) * 512 + gy) * 512 + gx;
        float xv0 = x[ibase];
        float xv1 = x[ibase + 512 * 512];
        float xv2 = x[ibase + 2 * 512 * 512];
        const int po = py * 20 + px_;
#pragma unroll
        for (int p = 0; p < 8; p++) {
            int c = 2 * p;
            float t0 = __ldg(&cw[c * 3 + 0]) * xv0 + __ldg(&cw[c * 3 + 1]) * xv1 +
                       __ldg(&cw[c * 3 + 2]) * xv2 + __ldg(&cb[c]);
            float t1 = __ldg(&cw[c * 3 + 3]) * xv0 + __ldg(&cw[c * 3 + 4]) * xv1 +
                       __ldg(&cw[c * 3 + 5]) * xv2 + __ldg(&cb[c + 1]);
            t0 = fmaf(__ldg(&g_sc[c]), fmaxf(t0, 0.f), __ldg(&g_sh[c]));
            t1 = fmaf(__ldg(&g_sc[c + 1]), fmaxf(t1, 0.f), __ldg(&g_sh[c + 1]));
            s_xcu[p * CSX + po] = packh2(t0, t1);
        }
    }
    __syncthreads();

    const int lane = tid & 31, wg = tid >> 5;
    const int tg = lane & 3, q = lane >> 2;

    // ---- d1: 1x1 16->32 via fp16 mma (1 kstep) ----
    {
        float acc[8][4];
#pragma unroll
        for (int i = 0; i < 8; i++) {
            int n0 = (i & 3) * 8 + 2 * tg;
            float b0 = __ldg(&d1b[n0]), b1 = __ldg(&d1b[n0 + 1]);
            acc[i][0] = b0; acc[i][1] = b1; acc[i][2] = b0; acc[i][3] = b1;
        }
        uint4 F0 = __ldg((const uint4*)&g_d1h[lane * 8]);
        uint4 F1 = __ldg((const uint4*)&g_d1h[lane * 8 + 4]);
        uint BF[8] = {F0.x, F0.y, F0.z, F0.w, F1.x, F1.y, F1.z, F1.w};
#pragma unroll
        for (int mt = 0; mt < 2; mt++) {
            const uint* ap = s_xcu + tg * CSX + (wg + mt * 8) * 20 + q;
            uint A[4] = {ap[0], ap[8], ap[4 * CSX], ap[4 * CSX + 8]};
#pragma unroll
            for (int nt = 0; nt < 4; nt++)
                mma16(acc[mt * 4 + nt], A, BF[2 * nt], BF[2 * nt + 1]);
        }
#pragma unroll
        for (int i = 0; i < 8; i++) {
            int mt = i >> 2, nt = i & 3;
            int n0 = nt * 8 + 2 * tg;
            int pair = nt * 4 + tg;
            int t = wg + mt * 8;
            float s0 = __ldg(&g_sc[16 + n0]), h0 = __ldg(&g_sh[16 + n0]);
            float s1 = __ldg(&g_sc[17 + n0]), h1 = __ldg(&g_sh[17 + n0]);
            float v0 = fmaf(s0, fmaxf(acc[i][0], 0.f), h0);
            float v1 = fmaf(s1, fmaxf(acc[i][1], 0.f), h1);
            float v2 = fmaf(s0, fmaxf(acc[i][2], 0.f), h0);
            float v3 = fmaf(s1, fmaxf(acc[i][3], 0.f), h1);
            halo_u[pair * 360 + (t + 1) * 20 + q]     = packh2(v0, v1);
            halo_u[pair * 360 + (t + 1) * 20 + q + 8] = packh2(v2, v3);
        }
    }
    __syncthreads();

    // ---- d2: 3x3 32->32 via fp16 mma (18 ksteps) ----
    {
        float acc[8][4];
#pragma unroll
        for (int i = 0; i < 8; i++) {
            int c2 = (i & 3) * 8 + tg * 2;
            float b0 = __ldg(&d2b[c2]), b1 = __ldg(&d2b[c2 + 1]);
            acc[i][0] = b0; acc[i][1] = b1; acc[i][2] = b0; acc[i][3] = b1;
        }
        const uint* hp0 = halo_u + tg * 360 + wg * 20 + q - 1;
        const uint4* bh = (const uint4*)g_bh16 + lane * 2;
#pragma unroll 1
        for (int tap = 0; tap < 9; tap++) {
            int dyq = (tap * 11) >> 5;
            int off = tap + 17 * dyq;
#pragma unroll
            for (int kc = 0; kc < 2; kc++) {
                const uint* hp = hp0 + kc * 2880 + off;
                uint A0[4] = {hp[0],   hp[8],   hp[1440], hp[1448]};
                uint A1[4] = {hp[160], hp[168], hp[1600], hp[1608]};
                uint4 B0 = __ldg(bh), B1 = __ldg(bh + 1);
                bh += 64;
                uint Bu[8] = {B0.x, B0.y, B0.z, B0.w, B1.x, B1.y, B1.z, B1.w};
#pragma unroll
                for (int nt = 0; nt < 4; nt++) {
                    mma16(acc[nt],     A0, Bu[2*nt], Bu[2*nt+1]);
                    mma16(acc[nt + 4], A1, Bu[2*nt], Bu[2*nt+1]);
                }
            }
        }
        __syncthreads();   // halo reads done; s_bu may overwrite it
#pragma unroll
        for (int i = 0; i < 8; i++) {
            int mt = i >> 2, nt = i & 3;
            int c2 = nt * 8 + tg * 2;
            int pair = nt * 4 + tg;
            float s0 = __ldg(&g_sc[48 + c2]), h0 = __ldg(&g_sh[48 + c2]);
            float s1 = __ldg(&g_sc[49 + c2]), h1 = __ldg(&g_sh[49 + c2]);
            float v0 = fmaf(s0, fmaxf(acc[i][0], 0.f), h0);
            float v1 = fmaf(s1, fmaxf(acc[i][1], 0.f), h1);
            float v2 = fmaf(s0, fmaxf(acc[i][2], 0.f), h0);
            float v3 = fmaf(s1, fmaxf(acc[i][3], 0.f), h1);
            uint* o = s_bu + pair * SBS + (wg + mt * 8) * 16 + q;
            o[0] = packh2(v0, v1);
            o[8] = packh2(v2, v3);
        }
    }
    __syncthreads();

    // ---- d3: 1x1 32->16 via fp16 mma (2 ksteps) ----
    {
        float acc[4][4];
#pragma unroll
        for (int i = 0; i < 4; i++) {
            int n0 = (i & 1) * 8 + 2 * tg;
            float b0 = __ldg(&d3b[n0]), b1 = __ldg(&d3b[n0 + 1]);
            acc[i][0] = b0; acc[i][1] = b1; acc[i][2] = b0; acc[i][3] = b1;
        }
#pragma unroll
        for (int ks = 0; ks < 2; ks++) {
            uint4 F = __ldg((const uint4*)&g_d3h[(ks * 32 + lane) * 4]);
#pragma unroll
            for (int mt = 0; mt < 2; mt++) {
                const uint* ap = s_bu + (ks * 8 + tg) * SBS + (wg + mt * 8) * 16 + q;
                uint A[4] = {ap[0], ap[8], ap[4 * SBS], ap[4 * SBS + 8]};
                mma16(acc[mt * 2 + 0], A, F.x, F.y);
                mma16(acc[mt * 2 + 1], A, F.z, F.w);
            }
        }
#pragma unroll
        for (int i = 0; i < 4; i++) {
            int mt = i >> 1, nt = i & 1;
            int n0 = nt * 8 + 2 * tg;
            int t = wg + mt * 8;
            float s0 = __ldg(&g_sc[80 + n0]), h0 = __ldg(&g_sh[80 + n0]);
            float s1 = __ldg(&g_sc[81 + n0]), h1 = __ldg(&g_sh[81 + n0]);
            float* o = s_f + n0 * SBS + t * 16 + q;
            o[0]       = fmaf(s0, fmaxf(acc[i][0], 0.f), h0);
            o[SBS]     = fmaf(s1, fmaxf(acc[i][1], 0.f), h1);
            o[8]       = fmaf(s0, fmaxf(acc[i][2], 0.f), h0);
            o[SBS + 8] = fmaf(s1, fmaxf(acc[i][3], 0.f), h1);
        }
    }
    __syncthreads();

#pragma unroll
    for (int k = 0; k < 4; k++) {
        int o = tid + k * 256;
        int c = o >> 6, qq = o & 63;
        int qy = qq >> 3, qx = qq & 7;
        const float* sp = &s_f[c * SBS + (qy * 2) * 16 + qx * 2];
        float mo = fmaxf(fmaxf(sp[0], sp[1]), fmaxf(sp[16], sp[17]));
        g_x1p[((n * 16 + c) * 256 + by * 8 + qy) * 256 + (bx * 8 + qx)] = mo;
    }
}

// ---------------------------------------------------------------------------
// Stage 2: d2/d3 fp16, d1 tf32 (s_xc stays fp32 for exact inactive pooling).
// SMEM: guard [0,4), halo_u [4,2884); s_xc fp32 [2884,5508) stride 328;
// after d2: s_bu = sm2+4 (8 pairs x 264), s_f = sm2+2116 [8][264] fp32.
// ---------------------------------------------------------------------------
__global__ void __launch_bounds__(256, 5) stage2_kernel(
    const float* __restrict__ cw, const float* __restrict__ cb,
    const float* __restrict__ d1b, const float* __restrict__ d2b,
    const float* __restrict__ d3b)
{
    extern __shared__ float sm2[];
    uint*  halo_u = (uint*)(sm2 + 4);
    float* s_xc   = sm2 + 2884;
    uint*  s_bu   = (uint*)(sm2 + 4);
    float* s_f    = sm2 + 2116;

    __shared__ float s_wsum[8];
    __shared__ int s_active;

    const int bid = blockIdx.x;
    const int n = bid >> 8, by = (bid >> 4) & 15, bx = bid & 15;
    const int tid = threadIdx.x;
    const int py = tid >> 4, px_ = tid & 15;
    const int gy = by * 16 + py, gx = bx * 16 + px_;

    {
        float mv = g_mask2[(n * 256 + gy) * 256 + gx];
#pragma unroll
        for (int o = 16; o; o >>= 1) mv += __shfl_xor_sync(0xffffffffu, mv, o);
        if ((tid & 31) == 0) s_wsum[tid >> 5] = mv;
    }
    {
        float4 z4 = make_float4(0.f, 0.f, 0.f, 0.f);
        for (int i = tid; i < 721; i += 256) ((float4*)sm2)[i] = z4;
    }
    __syncthreads();
    if (tid == 0) {
        float t = 0.f;
#pragma unroll
        for (int i = 0; i < 8; i++) t += s_wsum[i];
        s_active = (t > 128.0f) ? 1 : 0;
    }

    {
        const int ibase = ((n * 16) * 256 + gy) * 256 + gx;
        float xin[16];
#pragma unroll
        for (int c = 0; c < 16; c++) xin[c] = g_x1p[ibase + c * 65536];
        const int po = py * 20 + px_;
#pragma unroll
        for (int c2 = 0; c2 < 8; c2++) {
            float t = __ldg(&cb[c2]);
#pragma unroll
            for (int c1 = 0; c1 < 16; c1++)
                t = fmaf(xin[c1], __ldg(&cw[c2 * 16 + c1]), t);
            t = fmaxf(t, 0.0f);
            s_xc[c2 * CSX + po] = fmaf(__ldg(&g_sc[96 + c2]), t, __ldg(&g_sh[96 + c2]));
        }
    }
    __syncthreads();

    const int act = s_active;
    const int lane = tid & 31, wg = tid >> 5;
    const int tg = lane & 3, q = lane >> 2;

    if (act) {
        // d1: 1x1 8->16 via tf32 mma; half2 epilogue
        {
            float acc[4][4];
#pragma unroll
            for (int i = 0; i < 4; i++) {
                int n0 = (i & 1) * 8 + 2 * tg;
                float b0 = __ldg(&d1b[n0]), b1 = __ldg(&d1b[n0 + 1]);
                acc[i][0] = b0; acc[i][1] = b1; acc[i][2] = b0; acc[i][3] = b1;
            }
            uint4 F = __ldg((const uint4*)&g_e1f[lane * 4]);
#pragma unroll
            for (int mt = 0; mt < 2; mt++) {
                const float* ap = s_xc + tg * CSX + (wg + mt * 8) * 20 + q;
                uint A[4];
                A[0] = tf32_rna(ap[0]);
                A[1] = tf32_rna(ap[8]);
                A[2] = tf32_rna(ap[4 * CSX]);
                A[3] = tf32_rna(ap[4 * CSX + 8]);
                mma8(acc[mt * 2 + 0], A, F.x, F.y);
                mma8(acc[mt * 2 + 1], A, F.z, F.w);
            }
#pragma unroll
            for (int i = 0; i < 4; i++) {
                int mt = i >> 1, nt = i & 1;
                int n0 = nt * 8 + 2 * tg;
                int pair = nt * 4 + tg;
                int t = wg + mt * 8;
                float s0 = __ldg(&g_sc[104 + n0]), h0 = __ldg(&g_sh[104 + n0]);
                float s1 = __ldg(&g_sc[105 + n0]), h1 = __ldg(&g_sh[105 + n0]);
                float v0 = fmaf(s0, fmaxf(acc[i][0], 0.f), h0);
                float v1 = fmaf(s1, fmaxf(acc[i][1], 0.f), h1);
                float v2 = fmaf(s0, fmaxf(acc[i][2], 0.f), h0);
                float v3 = fmaf(s1, fmaxf(acc[i][3], 0.f), h1);
                halo_u[pair * 360 + (t + 1) * 20 + q]     = packh2(v0, v1);
                halo_u[pair * 360 + (t + 1) * 20 + q + 8] = packh2(v2, v3);
            }
        }
        __syncthreads();

        // d2: 3x3 16->16 via fp16 mma (9 ksteps)
        {
            float acc[4][4];
#pragma unroll
            for (int i = 0; i < 4; i++) {
                int c2 = (i & 1) * 8 + tg * 2;
                float b0 = __ldg(&d2b[c2]), b1 = __ldg(&d2b[c2 + 1]);
                acc[i][0] = b0; acc[i][1] = b1; acc[i][2] = b0; acc[i][3] = b1;
            }
            const uint* hp0 = halo_u + tg * 360 + wg * 20 + q - 1;
            const uint4* bh = (const uint4*)g_qh16 + lane;
#pragma unroll 1
            for (int tap = 0; tap < 9; tap++) {
                int dyq = (tap * 11) >> 5;
                const uint* hp = hp0 + tap + 17 * dyq;
                uint A0[4] = {hp[0],   hp[8],   hp[1440], hp[1448]};
                uint A1[4] = {hp[160], hp[168], hp[1600], hp[1608]};
                uint4 B = __ldg(bh);
                bh += 32;
                mma16(acc[0], A0, B.x, B.y);
                mma16(acc[1], A0, B.z, B.w);
                mma16(acc[2], A1, B.x, B.y);
                mma16(acc[3], A1, B.z, B.w);
            }
            __syncthreads();   // halo reads done; s_bu may overwrite it
#pragma unroll
            for (int i = 0; i < 4; i++) {
                int mt = i >> 1, nt = i & 1;
                int c2 = nt * 8 + tg * 2;
                int pair = nt * 4 + tg;
                float s0 = __ldg(&g_sc[120 + c2]), h0 = __ldg(&g_sh[120 + c2]);
                float s1 = __ldg(&g_sc[121 + c2]), h1 = __ldg(&g_sh[121 + c2]);
                float v0 = fmaf(s0, fmaxf(acc[i][0], 0.f), h0);
                float v1 = fmaf(s1, fmaxf(acc[i][1], 0.f), h1);
                float v2 = fmaf(s0, fmaxf(acc[i][2], 0.f), h0);
                float v3 = fmaf(s1, fmaxf(acc[i][3], 0.f), h1);
                uint* o = s_bu + pair * SBS + (wg + mt * 8) * 16 + q;
                o[0] = packh2(v0, v1);
                o[8] = packh2(v2, v3);
            }
        }
        __syncthreads();

        // d3: 1x1 16->8 via fp16 mma (1 kstep)
        {
            float acc[2][4];
            {
                int n0 = 2 * tg;
                float b0 = __ldg(&d3b[n0]), b1 = __ldg(&d3b[n0 + 1]);
                acc[0][0] = b0; acc[0][1] = b1; acc[0][2] = b0; acc[0][3] = b1;
                acc[1][0] = b0; acc[1][1] = b1; acc[1][2] = b0; acc[1][3] = b1;
            }
            uint2 F = __ldg((const uint2*)&g_e3h[lane * 2]);
#pragma unroll
            for (int mt = 0; mt < 2; mt++) {
                const uint* ap = s_bu + tg * SBS + (wg + mt * 8) * 16 + q;
                uint A[4] = {ap[0], ap[8], ap[4 * SBS], ap[4 * SBS + 8]};
                mma16(acc[mt], A, F.x, F.y);
            }
#pragma unroll
            for (int mt = 0; mt < 2; mt++) {
                int n0 = 2 * tg;
                int t = wg + mt * 8;
                float s0 = __ldg(&g_sc[136 + n0]), h0 = __ldg(&g_sh[136 + n0]);
                float s1 = __ldg(&g_sc[137 + n0]), h1 = __ldg(&g_sh[137 + n0]);
                float* o = s_f + n0 * SBS + t * 16 + q;
                o[0]       = fmaf(s0, fmaxf(acc[mt][0], 0.f), h0);
                o[SBS]     = fmaf(s1, fmaxf(acc[mt][1], 0.f), h1);
                o[8]       = fmaf(s0, fmaxf(acc[mt][2], 0.f), h0);
                o[SBS + 8] = fmaf(s1, fmaxf(acc[mt][3], 0.f), h1);
            }
        }
        __syncthreads();
    }

    const float* srcp = act ? s_f : s_xc;
    const int chs = act ? SBS : CSX;
    const int rs = act ? 16 : 20;
#pragma unroll
    for (int k = 0; k < 2; k++) {
        int o = tid + k * 256;
        int c = o >> 6, qq = o & 63;
        int qy = qq >> 3, qx = qq & 7;
        const float* sp = &srcp[c * chs + (qy * 2) * rs + qx * 2];
        float mo = fmaxf(fmaxf(sp[0], sp[1]), fmaxf(sp[rs], sp[rs + 1]));
        g_x2p[((n * 8 + c) * 128 + by * 8 + qy) * 128 + (bx * 8 + qx)] = mo;
    }
}

// ---------------------------------------------------------------------------
__global__ void __launch_bounds__(256) fc_partial_kernel(const float* __restrict__ fc_w)
{
    const int b = blockIdx.x;
    const int n = b >> 5, s = b & 31;
    const int tid = threadIdx.x;
    const float4* f = (const float4*)(g_x2p + n * 131072 + s * 4096);
    const float4* w = (const float4*)(fc_w) + s * 1024;

    float part[10];
#pragma unroll
    for (int k = 0; k < 10; k++) part[k] = 0.0f;

#pragma unroll
    for (int j = tid; j < 1024; j += 256) {
        float4 fv = f[j];
#pragma unroll
        for (int k = 0; k < 10; k++) {
            float4 wv = __ldg(&w[k * 32768 + j]);
            part[k] += fv.x * wv.x + fv.y * wv.y + fv.z * wv.z + fv.w * wv.w;
        }
    }

    __shared__ float sred[10][256];
#pragma unroll
    for (int k = 0; k < 10; k++) sred[k][tid] = part[k];
    __syncthreads();
    for (int st = 128; st > 0; st >>= 1) {
        if (tid < st) {
#pragma unroll
            for (int k = 0; k < 10; k++) sred[k][tid] += sred[k][tid + st];
        }
        __syncthreads();
    }
    if (tid < 10) g_fcpart[(n * 32 + s) * 10 + tid] = sred[tid][0];
}

__global__ void fc_final_kernel(const float* __restrict__ fc_b, float* __restrict__ out)
{
    const int t = threadIdx.x;
    __shared__ float s_l[16][10];
    if (t < 160) {
        int n = t / 10, k = t - n * 10;
        float a = fc_b[k];
#pragma unroll
        for (int s = 0; s < 32; s++) a += g_fcpart[(n * 32 + s) * 10 + k];
        s_l[n][k] = a;
    }
    __syncthreads();
    if (t < 16) {
        float mx = -1e30f;
#pragma unroll
        for (int k = 0; k < 10; k++) mx = fmaxf(mx, s_l[t][k]);
        float e[10], se = 0.f;
#pragma unroll
        for (int k = 0; k < 10; k++) { e[k] = expf(s_l[t][k] - mx); se += e[k]; }
        float inv = 1.0f / se;
#pragma unroll
        for (int k = 0; k < 10; k++) out[t * 10 + k] = e[k] * inv;
    }
}

// ---------------------------------------------------------------------------
extern "C" void kernel_launch(void* const* d_in, const int* in_sizes, int n_in,
                              void* d_out, int out_size)
{
    const float* x      = (const float*)d_in[0];
    const float* mask   = (const float*)d_in[1];
    const float* s1_cw  = (const float*)d_in[2];
    const float* s1_cb  = (const float*)d_in[3];
    const float* s1_bn0 = (const float*)d_in[4];
    const float* s1_d1w = (const float*)d_in[5];
    const float* s1_d1b = (const float*)d_in[6];
    const float* s1_bn1 = (const float*)d_in[7];
    const float* s1_d2w = (const float*)d_in[8];
    const float* s1_d2b = (const float*)d_in[9];
    const float* s1_bn2 = (const float*)d_in[10];
    const float* s1_d3w = (const float*)d_in[11];
    const float* s1_d3b = (const float*)d_in[12];
    const float* s1_bn3 = (const float*)d_in[13];
    const float* s2_cw  = (const float*)d_in[14];
    const float* s2_cb  = (const float*)d_in[15];
    const float* s2_bn0 = (const float*)d_in[16];
    const float* s2_d1w = (const float*)d_in[17];
    const float* s2_d1b = (const float*)d_in[18];
    const float* s2_bn1 = (const float*)d_in[19];
    const float* s2_d2w = (const float*)d_in[20];
    const float* s2_d2b = (const float*)d_in[21];
    const float* s2_bn2 = (const float*)d_in[22];
    const float* s2_d3w = (const float*)d_in[23];
    const float* s2_d3b = (const float*)d_in[24];
    const float* s2_bn3 = (const float*)d_in[25];
    const float* fc_w   = (const float*)d_in[26];
    const float* fc_b   = (const float*)d_in[27];

    prep_kernel<<<1, 256>>>(s1_d2w, s2_d2w, s1_d1w, s1_d3w, s2_d1w, s2_d3w,
                            s1_bn0, s1_bn1, s1_bn2, s1_bn3,
                            s2_bn0, s2_bn1, s2_bn2, s2_bn3);

    stage1_all_kernel<<<16 * 32 * 32, 256>>>(x, mask, s1_cw, s1_cb);

    const int smem1 = 8452 * sizeof(float);    // 33.8 KB
    cudaFuncSetAttribute(stage1_active_kernel, cudaFuncAttributeMaxDynamicSharedMemorySize, smem1);
    stage1_active_kernel<<<16 * 32 * 32, 256, smem1>>>(
        x, s1_cw, s1_cb, s1_d1b, s1_d2b, s1_d3b);

    const int smem2 = 5508 * sizeof(float);    // 22 KB
    cudaFuncSetAttribute(stage2_kernel, cudaFuncAttributeMaxDynamicSharedMemorySize, smem2);
    stage2_kernel<<<16 * 16 * 16, 256, smem2>>>(
        s2_cw, s2_cb, s2_d1b, s2_d2b, s2_d3b);

    fc_partial_kernel<<<512, 256>>>(fc_w);
    fc_final_kernel<<<1, 256>>>(fc_b, (float*)d_out);
}